// round 2
// baseline (speedup 1.0000x reference)
#include <cuda_runtime.h>
#include <cuda_bf16.h>
#include <math.h>

#define BATCH 2
#define L_SEQ 4096
#define D_MODEL 1024
#define DIP 4384          // D_IN_PROJ
#define DSSM 2048
#define CONVD 2304        // CONV_DIM
#define NH 32
#define HD 64
#define DS 128
#define NC 16
#define CHUNK 256
#define MROWS (BATCH * L_SEQ)   // 8192

// ---------------- scratch (device globals; no allocation) ----------------
__device__ float g_zx[(size_t)MROWS * DIP];        // in_proj output
__device__ float g_xbc[(size_t)MROWS * CONVD];     // conv+silu output
__device__ float g_y[(size_t)MROWS * DSSM];        // ssm output y
__device__ float g_yn[(size_t)MROWS * DSSM];       // gated+normed y
__device__ float g_states[(size_t)BATCH * NC * NH * HD * DS];
__device__ float g_prev[(size_t)BATCH * NC * NH * HD * DS];
__device__ float g_cs[(size_t)BATCH * NC * NH * CHUNK];

// ---------------- GEMM: C[M,N] = A[M,K] * B[N,K]^T  (fp32) ----------------
// 128x128 block, BK=8, 256 threads, 8x8 per thread. M % 128 == 0, K % 8 == 0.
__global__ void gemm_nt(const float* __restrict__ A, const float* __restrict__ Bm,
                        float* __restrict__ C, int M, int N, int K) {
    __shared__ float sA[8][128];
    __shared__ float sB[8][128];
    const int tid = threadIdx.x;
    const int tx = tid & 15;
    const int ty = tid >> 4;
    const int rowBase = blockIdx.y * 128;
    const int colBase = blockIdx.x * 128;

    float acc[8][8];
#pragma unroll
    for (int i = 0; i < 8; i++)
#pragma unroll
        for (int j = 0; j < 8; j++) acc[i][j] = 0.f;

    const int lr = tid >> 1;          // 0..127
    const int lk = (tid & 1) * 4;     // 0 or 4

    for (int k0 = 0; k0 < K; k0 += 8) {
        {
            float4 av = *(const float4*)&A[(size_t)(rowBase + lr) * K + k0 + lk];
            sA[lk + 0][lr] = av.x; sA[lk + 1][lr] = av.y;
            sA[lk + 2][lr] = av.z; sA[lk + 3][lr] = av.w;
        }
        {
            int cn = colBase + lr;
            float4 bv = make_float4(0.f, 0.f, 0.f, 0.f);
            if (cn < N) bv = *(const float4*)&Bm[(size_t)cn * K + k0 + lk];
            sB[lk + 0][lr] = bv.x; sB[lk + 1][lr] = bv.y;
            sB[lk + 2][lr] = bv.z; sB[lk + 3][lr] = bv.w;
        }
        __syncthreads();
#pragma unroll
        for (int kk = 0; kk < 8; kk++) {
            float4 a0 = *(const float4*)&sA[kk][ty * 8];
            float4 a1 = *(const float4*)&sA[kk][ty * 8 + 4];
            float4 b0 = *(const float4*)&sB[kk][tx * 8];
            float4 b1 = *(const float4*)&sB[kk][tx * 8 + 4];
            float a[8] = {a0.x, a0.y, a0.z, a0.w, a1.x, a1.y, a1.z, a1.w};
            float b[8] = {b0.x, b0.y, b0.z, b0.w, b1.x, b1.y, b1.z, b1.w};
#pragma unroll
            for (int i = 0; i < 8; i++)
#pragma unroll
                for (int j = 0; j < 8; j++) acc[i][j] = fmaf(a[i], b[j], acc[i][j]);
        }
        __syncthreads();
    }
#pragma unroll
    for (int i = 0; i < 8; i++) {
        int r = rowBase + ty * 8 + i;
#pragma unroll
        for (int j = 0; j < 8; j++) {
            int cn = colBase + tx * 8 + j;
            if (cn < N) C[(size_t)r * N + cn] = acc[i][j];
        }
    }
}

__device__ __forceinline__ float fast_sigmoid(float x) {
    return 1.f / (1.f + __expf(-x));
}

// ---------------- conv1d (causal, depthwise, width 4) + SiLU ----------------
__global__ void conv_silu_kernel(const float* __restrict__ zx,
                                 const float* __restrict__ conv_w,
                                 const float* __restrict__ conv_b,
                                 float* __restrict__ xbc) {
    size_t idx = (size_t)blockIdx.x * 256 + threadIdx.x;
    const size_t total = (size_t)MROWS * CONVD;
    if (idx >= total) return;
    int cc = (int)(idx % CONVD);
    size_t bt = idx / CONVD;            // b*L + t
    int t = (int)(bt % L_SEQ);
    float acc = conv_b[cc];
#pragma unroll
    for (int k = 0; k < 4; k++) {
        int tt = t - 3 + k;
        if (tt >= 0)
            acc = fmaf(zx[(bt - t + tt) * DIP + 2048 + cc], conv_w[cc * 4 + k], acc);
    }
    xbc[idx] = acc * fast_sigmoid(acc);
}

// ---------------- SSM per-chunk: Y_diag + states ----------------
// grid (NC, NH, BATCH), 256 threads, dynamic smem.
#define SM3_FLOATS (512 + 8 + 2 * 64 * 129 + 2 * 64 * 65)
__global__ void ssm_chunk_kernel(const float* __restrict__ zx,
                                 const float* __restrict__ xbc,
                                 const float* __restrict__ dt_bias,
                                 const float* __restrict__ A_log,
                                 const float* __restrict__ Dvec,
                                 float* __restrict__ y,
                                 float* __restrict__ states,
                                 float* __restrict__ cs_out) {
    extern __shared__ float sm[];
    float* s_dt = sm;                 // 256
    float* s_cs = sm + 256;           // 256
    float* s_wsum = sm + 512;         // 8 (per-warp sums)
    float* sCt = sm + 520;            // 64*129
    float* sBs = sCt + 64 * 129;      // 64*129
    float* sXd = sBs + 64 * 129;      // 64*65
    float* sG  = sXd + 64 * 65;       // 64*65

    const int c = blockIdx.x, h = blockIdx.y, b = blockIdx.z;
    const int tid = threadIdx.x;
    const int tx = tid & 15, ty = tid >> 4;
    const int lane = tid & 31, wid = tid >> 5;
    const float Ah = -__expf(A_log[h]);

    // phase 0: dt = softplus(dt_raw + bias); dA; parallel inclusive scan
    float dA_val;
    {
        float draw = zx[((size_t)(b * L_SEQ) + c * CHUNK + tid) * DIP + 4352 + h] + dt_bias[h];
        float dt = (draw > 20.f) ? draw : log1pf(__expf(draw));
        s_dt[tid] = dt;
        dA_val = dt * Ah;
    }
    // warp inclusive scan
    float v = dA_val;
#pragma unroll
    for (int off = 1; off < 32; off <<= 1) {
        float n = __shfl_up_sync(0xffffffffu, v, off);
        if (lane >= off) v += n;
    }
    if (lane == 31) s_wsum[wid] = v;
    __syncthreads();
    if (tid < 8) {
        float w = s_wsum[tid];
#pragma unroll
        for (int off = 1; off < 8; off <<= 1) {
            float n = __shfl_up_sync(0xffu, w, off);
            if (tid >= off) w += n;
        }
        s_wsum[tid] = w;
    }
    __syncthreads();
    float csv = v + (wid > 0 ? s_wsum[wid - 1] : 0.f);
    s_cs[tid] = csv;
    __syncthreads();
    const float csL = s_cs[CHUNK - 1];
    cs_out[(((size_t)b * NC + c) * NH + h) * CHUNK + tid] = csv;

    const float* xrow = xbc + ((size_t)(b * L_SEQ) + c * CHUNK) * CONVD;

    // phase 1: Y_diag per 64-row t-tile
    for (int T = 0; T < 4; T++) {
        for (int l = tid; l < 64 * 128; l += 256) {
            int i = l >> 7, n = l & 127;
            sCt[i * 129 + n] = xrow[(size_t)(T * 64 + i) * CONVD + 2176 + n];
        }
        float acc[4][4];
#pragma unroll
        for (int i = 0; i < 4; i++)
#pragma unroll
            for (int j = 0; j < 4; j++) acc[i][j] = 0.f;

        for (int S = 0; S <= T; S++) {
            __syncthreads();
            for (int l = tid; l < 64 * 128; l += 256) {
                int j = l >> 7, n = l & 127;
                sBs[j * 129 + n] = xrow[(size_t)(S * 64 + j) * CONVD + 2048 + n];
            }
            for (int l = tid; l < 64 * 64; l += 256) {
                int j = l >> 6, p = l & 63;
                sXd[j * 65 + p] = xrow[(size_t)(S * 64 + j) * CONVD + h * 64 + p] * s_dt[S * 64 + j];
            }
            __syncthreads();
            // G = C * B^T (64x64 tile), k = 128
            float g[4][4];
#pragma unroll
            for (int i = 0; i < 4; i++)
#pragma unroll
                for (int j = 0; j < 4; j++) g[i][j] = 0.f;
            for (int n = 0; n < 128; n++) {
                float a0 = sCt[(ty * 4 + 0) * 129 + n];
                float a1 = sCt[(ty * 4 + 1) * 129 + n];
                float a2 = sCt[(ty * 4 + 2) * 129 + n];
                float a3 = sCt[(ty * 4 + 3) * 129 + n];
                float b0 = sBs[(tx * 4 + 0) * 129 + n];
                float b1 = sBs[(tx * 4 + 1) * 129 + n];
                float b2 = sBs[(tx * 4 + 2) * 129 + n];
                float b3 = sBs[(tx * 4 + 3) * 129 + n];
                g[0][0] = fmaf(a0, b0, g[0][0]); g[0][1] = fmaf(a0, b1, g[0][1]);
                g[0][2] = fmaf(a0, b2, g[0][2]); g[0][3] = fmaf(a0, b3, g[0][3]);
                g[1][0] = fmaf(a1, b0, g[1][0]); g[1][1] = fmaf(a1, b1, g[1][1]);
                g[1][2] = fmaf(a1, b2, g[1][2]); g[1][3] = fmaf(a1, b3, g[1][3]);
                g[2][0] = fmaf(a2, b0, g[2][0]); g[2][1] = fmaf(a2, b1, g[2][1]);
                g[2][2] = fmaf(a2, b2, g[2][2]); g[2][3] = fmaf(a2, b3, g[2][3]);
                g[3][0] = fmaf(a3, b0, g[3][0]); g[3][1] = fmaf(a3, b1, g[3][1]);
                g[3][2] = fmaf(a3, b2, g[3][2]); g[3][3] = fmaf(a3, b3, g[3][3]);
            }
#pragma unroll
            for (int i = 0; i < 4; i++)
#pragma unroll
                for (int j = 0; j < 4; j++) {
                    int tg = T * 64 + ty * 4 + i;
                    int sg = S * 64 + tx * 4 + j;
                    sG[(ty * 4 + i) * 65 + tx * 4 + j] =
                        (tg >= sg) ? g[i][j] * __expf(s_cs[tg] - s_cs[sg]) : 0.f;
                }
            __syncthreads();
            // acc += G_tile * x_dt_tile   (64x64 x 64)
            for (int kk = 0; kk < 64; kk++) {
                float a0 = sG[(ty * 4 + 0) * 65 + kk];
                float a1 = sG[(ty * 4 + 1) * 65 + kk];
                float a2 = sG[(ty * 4 + 2) * 65 + kk];
                float a3 = sG[(ty * 4 + 3) * 65 + kk];
                float b0 = sXd[kk * 65 + tx * 4 + 0];
                float b1 = sXd[kk * 65 + tx * 4 + 1];
                float b2 = sXd[kk * 65 + tx * 4 + 2];
                float b3 = sXd[kk * 65 + tx * 4 + 3];
                acc[0][0] = fmaf(a0, b0, acc[0][0]); acc[0][1] = fmaf(a0, b1, acc[0][1]);
                acc[0][2] = fmaf(a0, b2, acc[0][2]); acc[0][3] = fmaf(a0, b3, acc[0][3]);
                acc[1][0] = fmaf(a1, b0, acc[1][0]); acc[1][1] = fmaf(a1, b1, acc[1][1]);
                acc[1][2] = fmaf(a1, b2, acc[1][2]); acc[1][3] = fmaf(a1, b3, acc[1][3]);
                acc[2][0] = fmaf(a2, b0, acc[2][0]); acc[2][1] = fmaf(a2, b1, acc[2][1]);
                acc[2][2] = fmaf(a2, b2, acc[2][2]); acc[2][3] = fmaf(a2, b3, acc[2][3]);
                acc[3][0] = fmaf(a3, b0, acc[3][0]); acc[3][1] = fmaf(a3, b1, acc[3][1]);
                acc[3][2] = fmaf(a3, b2, acc[3][2]); acc[3][3] = fmaf(a3, b3, acc[3][3]);
            }
        }
        // write Y_diag + D*x
        float Dh = Dvec[h];
#pragma unroll
        for (int i = 0; i < 4; i++) {
            int trow = T * 64 + ty * 4 + i;
            size_t gro = ((size_t)(b * L_SEQ) + c * CHUNK + trow) * DSSM + h * 64;
#pragma unroll
            for (int j = 0; j < 4; j++) {
                int p = tx * 4 + j;
                float xv = xrow[(size_t)trow * CONVD + h * 64 + p];
                y[gro + p] = fmaf(Dh, xv, acc[i][j]);
            }
        }
    }

    // phase 2: per-chunk state S[p=64][n=128]
    float st[4][8];
#pragma unroll
    for (int i = 0; i < 4; i++)
#pragma unroll
        for (int j = 0; j < 8; j++) st[i][j] = 0.f;

    for (int T = 0; T < 4; T++) {
        __syncthreads();
        for (int l = tid; l < 64 * 128; l += 256) {
            int j = l >> 7, n = l & 127;
            sBs[j * 129 + n] = xrow[(size_t)(T * 64 + j) * CONVD + 2048 + n];
        }
        for (int l = tid; l < 64 * 64; l += 256) {
            int j = l >> 6, p = l & 63;
            int t = T * 64 + j;
            sXd[j * 65 + p] = xrow[(size_t)t * CONVD + h * 64 + p] * s_dt[t] * __expf(csL - s_cs[t]);
        }
        __syncthreads();
        for (int kk = 0; kk < 64; kk++) {
            float a[4];
#pragma unroll
            for (int i = 0; i < 4; i++) a[i] = sXd[kk * 65 + ty * 4 + i];
            float bb[8];
#pragma unroll
            for (int j = 0; j < 8; j++) bb[j] = sBs[kk * 129 + tx * 8 + j];
#pragma unroll
            for (int i = 0; i < 4; i++)
#pragma unroll
                for (int j = 0; j < 8; j++) st[i][j] = fmaf(a[i], bb[j], st[i][j]);
        }
    }
    size_t sbase = (((size_t)b * NC + c) * NH + h) * (size_t)(HD * DS);
#pragma unroll
    for (int i = 0; i < 4; i++)
#pragma unroll
        for (int j = 0; j < 8; j++)
            states[sbase + (size_t)(ty * 4 + i) * DS + tx * 8 + j] = st[i][j];
}

// ---------------- inter-chunk recurrence ----------------
__global__ void chunk_scan_kernel(const float* __restrict__ states,
                                  const float* __restrict__ cs,
                                  float* __restrict__ prev) {
    const int h = blockIdx.x, b = blockIdx.y;
    const int tid = threadIdx.x;
    float P[32];
#pragma unroll
    for (int k = 0; k < 32; k++) P[k] = 0.f;
    for (int c = 0; c < NC; c++) {
        size_t base = ((size_t)b * NC + c) * NH + h;
        float sc = __expf(cs[base * CHUNK + CHUNK - 1]);
        size_t off = base * (size_t)(HD * DS);
#pragma unroll
        for (int k = 0; k < 32; k++) {
            int e = tid + k * 256;
            prev[off + e] = P[k];
            P[k] = fmaf(P[k], sc, states[off + e]);
        }
    }
}

// ---------------- Y_off = (C .* exp(cs)) @ prev^T, added into y ----------------
#define SM5_FLOATS (2 * 64 * 129 + 256)
__global__ void yoff_kernel(const float* __restrict__ xbc,
                            const float* __restrict__ prev,
                            const float* __restrict__ cs,
                            float* __restrict__ y) {
    extern __shared__ float sm[];
    float* sP = sm;                   // 64*129  (p-major: prev[p][n])
    float* sCt = sP + 64 * 129;       // 64*129
    float* sE = sCt + 64 * 129;       // 256

    const int c = blockIdx.x, h = blockIdx.y, b = blockIdx.z;
    const int tid = threadIdx.x;
    const int tx = tid & 15, ty = tid >> 4;

    size_t base = ((size_t)b * NC + c) * NH + h;
    sE[tid] = __expf(cs[base * CHUNK + tid]);
    size_t poff = base * (size_t)(HD * DS);
    for (int l = tid; l < 64 * 128; l += 256) {
        int p = l >> 7, n = l & 127;
        sP[p * 129 + n] = prev[poff + (size_t)p * DS + n];
    }
    const float* xrow = xbc + ((size_t)(b * L_SEQ) + c * CHUNK) * CONVD;

    for (int T = 0; T < 4; T++) {
        __syncthreads();
        for (int l = tid; l < 64 * 128; l += 256) {
            int i = l >> 7, n = l & 127;
            sCt[i * 129 + n] = xrow[(size_t)(T * 64 + i) * CONVD + 2176 + n];
        }
        __syncthreads();
        float acc[4][4];
#pragma unroll
        for (int i = 0; i < 4; i++)
#pragma unroll
            for (int j = 0; j < 4; j++) acc[i][j] = 0.f;
        for (int n = 0; n < 128; n++) {
            float a0 = sCt[(ty * 4 + 0) * 129 + n];
            float a1 = sCt[(ty * 4 + 1) * 129 + n];
            float a2 = sCt[(ty * 4 + 2) * 129 + n];
            float a3 = sCt[(ty * 4 + 3) * 129 + n];
            float b0 = sP[(tx * 4 + 0) * 129 + n];
            float b1 = sP[(tx * 4 + 1) * 129 + n];
            float b2 = sP[(tx * 4 + 2) * 129 + n];
            float b3 = sP[(tx * 4 + 3) * 129 + n];
            acc[0][0] = fmaf(a0, b0, acc[0][0]); acc[0][1] = fmaf(a0, b1, acc[0][1]);
            acc[0][2] = fmaf(a0, b2, acc[0][2]); acc[0][3] = fmaf(a0, b3, acc[0][3]);
            acc[1][0] = fmaf(a1, b0, acc[1][0]); acc[1][1] = fmaf(a1, b1, acc[1][1]);
            acc[1][2] = fmaf(a1, b2, acc[1][2]); acc[1][3] = fmaf(a1, b3, acc[1][3]);
            acc[2][0] = fmaf(a2, b0, acc[2][0]); acc[2][1] = fmaf(a2, b1, acc[2][1]);
            acc[2][2] = fmaf(a2, b2, acc[2][2]); acc[2][3] = fmaf(a2, b3, acc[2][3]);
            acc[3][0] = fmaf(a3, b0, acc[3][0]); acc[3][1] = fmaf(a3, b1, acc[3][1]);
            acc[3][2] = fmaf(a3, b2, acc[3][2]); acc[3][3] = fmaf(a3, b3, acc[3][3]);
        }
#pragma unroll
        for (int i = 0; i < 4; i++) {
            int trow = T * 64 + ty * 4 + i;
            size_t go = ((size_t)(b * L_SEQ) + c * CHUNK + trow) * DSSM + h * 64 + tx * 4;
            float e = sE[trow];
#pragma unroll
            for (int j = 0; j < 4; j++) y[go + j] += acc[i][j] * e;
        }
    }
}

// ---------------- gate (y * silu(z)) + RMSNorm ----------------
__global__ void gate_norm_kernel(const float* __restrict__ zx,
                                 const float* __restrict__ y,
                                 const float* __restrict__ norm_w,
                                 float* __restrict__ yn) {
    const int row = blockIdx.x;
    const int tid = threadIdx.x;
    const float* yrow = y + (size_t)row * DSSM;
    const float* zrow = zx + (size_t)row * DIP;
    float v[8];
    float ss = 0.f;
#pragma unroll
    for (int k = 0; k < 8; k++) {
        int e = tid + k * 256;
        float z = zrow[e];
        float vv = yrow[e] * (z * fast_sigmoid(z));
        v[k] = vv;
        ss = fmaf(vv, vv, ss);
    }
    __shared__ float red[256];
    red[tid] = ss;
    __syncthreads();
    for (int s = 128; s > 0; s >>= 1) {
        if (tid < s) red[tid] += red[tid + s];
        __syncthreads();
    }
    float r = rsqrtf(red[0] / (float)DSSM + 1e-5f);
#pragma unroll
    for (int k = 0; k < 8; k++) {
        int e = tid + k * 256;
        yn[(size_t)row * DSSM + e] = v[k] * r * norm_w[e];
    }
}

// ---------------- host launch ----------------
extern "C" void kernel_launch(void* const* d_in, const int* in_sizes, int n_in,
                              void* d_out, int out_size) {
    const float* u       = (const float*)d_in[0];
    const float* W_in    = (const float*)d_in[1];
    const float* conv_w  = (const float*)d_in[2];
    const float* conv_b  = (const float*)d_in[3];
    const float* dt_bias = (const float*)d_in[4];
    const float* A_log   = (const float*)d_in[5];
    const float* Dv      = (const float*)d_in[6];
    const float* norm_w  = (const float*)d_in[7];
    const float* W_out   = (const float*)d_in[8];
    float* out = (float*)d_out;

    void *p_zx, *p_xbc, *p_y, *p_yn, *p_states, *p_prev, *p_cs;
    cudaGetSymbolAddress(&p_zx, g_zx);
    cudaGetSymbolAddress(&p_xbc, g_xbc);
    cudaGetSymbolAddress(&p_y, g_y);
    cudaGetSymbolAddress(&p_yn, g_yn);
    cudaGetSymbolAddress(&p_states, g_states);
    cudaGetSymbolAddress(&p_prev, g_prev);
    cudaGetSymbolAddress(&p_cs, g_cs);
    float* zx = (float*)p_zx;
    float* xbc = (float*)p_xbc;
    float* y = (float*)p_y;
    float* yn = (float*)p_yn;
    float* states = (float*)p_states;
    float* prev = (float*)p_prev;
    float* cs = (float*)p_cs;

    cudaFuncSetAttribute(ssm_chunk_kernel, cudaFuncAttributeMaxDynamicSharedMemorySize,
                         SM3_FLOATS * sizeof(float));
    cudaFuncSetAttribute(yoff_kernel, cudaFuncAttributeMaxDynamicSharedMemorySize,
                         SM5_FLOATS * sizeof(float));

    // 1. in_proj: zxbcdt = u @ W_in^T   (8192 x 4384 x 1024)
    gemm_nt<<<dim3((DIP + 127) / 128, MROWS / 128), 256>>>(u, W_in, zx, MROWS, DIP, D_MODEL);

    // 2. conv1d + silu
    {
        size_t total = (size_t)MROWS * CONVD;
        conv_silu_kernel<<<(unsigned)((total + 255) / 256), 256>>>(zx, conv_w, conv_b, xbc);
    }

    // 3. per-chunk SSM (Y_diag + states + cumsums)
    ssm_chunk_kernel<<<dim3(NC, NH, BATCH), 256, SM3_FLOATS * sizeof(float)>>>(
        zx, xbc, dt_bias, A_log, Dv, y, states, cs);

    // 4. inter-chunk recurrence -> prev states
    chunk_scan_kernel<<<dim3(NH, BATCH), 256>>>(states, cs, prev);

    // 5. Y_off added into y
    yoff_kernel<<<dim3(NC, NH, BATCH), 256, SM5_FLOATS * sizeof(float)>>>(xbc, prev, cs, y);

    // 6. gate + RMSNorm
    gate_norm_kernel<<<MROWS, 256>>>(zx, y, norm_w, yn);

    // 7. out_proj: out = yn @ W_out^T  (8192 x 1024 x 2048)
    gemm_nt<<<dim3(D_MODEL / 128, MROWS / 128), 256>>>(yn, W_out, out, MROWS, D_MODEL, DSSM);
}

// round 3
// speedup vs baseline: 1.6217x; 1.6217x over previous
#include <cuda_runtime.h>
#include <cuda_bf16.h>
#include <math.h>
#include <stdint.h>

#define BATCH 2
#define L_SEQ 4096
#define D_MODEL 1024
#define DIP 4384          // D_IN_PROJ
#define DSSM 2048
#define CONVD 2304        // CONV_DIM
#define NH 32
#define HD 64
#define DS 128
#define NC 16
#define CHUNK 256
#define MROWS (BATCH * L_SEQ)   // 8192

// ---------------- scratch (device globals; no allocation) ----------------
__device__ float g_zx[(size_t)MROWS * DIP];        // in_proj output
__device__ float g_xbc[(size_t)MROWS * CONVD];     // conv+silu output
__device__ float g_y[(size_t)MROWS * DSSM];        // ssm output y
__device__ float g_yn[(size_t)MROWS * DSSM];       // gated+normed y
__device__ float g_states[(size_t)BATCH * NC * NH * HD * DS];
__device__ float g_prev[(size_t)BATCH * NC * NH * HD * DS];
__device__ float g_cs[(size_t)BATCH * NC * NH * CHUNK];

// bf16 hi/lo split buffers for tensor-core GEMMs
__device__ __nv_bfloat16 g_uh[(size_t)MROWS * D_MODEL];
__device__ __nv_bfloat16 g_ul[(size_t)MROWS * D_MODEL];
__device__ __nv_bfloat16 g_wih[(size_t)DIP * D_MODEL];
__device__ __nv_bfloat16 g_wil[(size_t)DIP * D_MODEL];
__device__ __nv_bfloat16 g_ynh[(size_t)MROWS * DSSM];
__device__ __nv_bfloat16 g_ynl[(size_t)MROWS * DSSM];
__device__ __nv_bfloat16 g_woh[(size_t)D_MODEL * DSSM];
__device__ __nv_bfloat16 g_wol[(size_t)D_MODEL * DSSM];

// ---------------- fp32 -> bf16 hi/lo split ----------------
struct alignas(8) bf16x4 { __nv_bfloat16 a, b, c, d; };

__global__ void split_bf16_kernel(const float* __restrict__ x,
                                  __nv_bfloat16* __restrict__ hi,
                                  __nv_bfloat16* __restrict__ lo, int n4) {
    int i = blockIdx.x * 256 + threadIdx.x;
    if (i >= n4) return;
    float4 v = ((const float4*)x)[i];
    __nv_bfloat16 h0 = __float2bfloat16(v.x);
    __nv_bfloat16 h1 = __float2bfloat16(v.y);
    __nv_bfloat16 h2 = __float2bfloat16(v.z);
    __nv_bfloat16 h3 = __float2bfloat16(v.w);
    bf16x4 hv = {h0, h1, h2, h3};
    bf16x4 lv = {__float2bfloat16(v.x - __bfloat162float(h0)),
                 __float2bfloat16(v.y - __bfloat162float(h1)),
                 __float2bfloat16(v.z - __bfloat162float(h2)),
                 __float2bfloat16(v.w - __bfloat162float(h3))};
    ((bf16x4*)hi)[i] = hv;
    ((bf16x4*)lo)[i] = lv;
}

// ---------------- tensor-core GEMM: C[M,N] = A[M,K] * B[N,K]^T ----------------
// bf16 hi/lo split, 3 mma passes (Ah*Bh + Ah*Bl + Al*Bh), fp32 accum.
// 128x128 block, 8 warps (64x32 warp tile), k-step 16, double buffered.
#define GK 16
#define GPAD 24           // padded k width in smem (stride 48B, conflict-free frags)
#define GEMM_SMEM (2 * 2 * 128 * GPAD * 2 * 2)  // A + B: 49152 bytes

__device__ __forceinline__ void mma16816(float* d, const uint32_t* a, const uint32_t* b) {
    asm volatile(
        "mma.sync.aligned.m16n8k16.row.col.f32.bf16.bf16.f32 "
        "{%0,%1,%2,%3}, {%4,%5,%6,%7}, {%8,%9}, {%0,%1,%2,%3};"
        : "+f"(d[0]), "+f"(d[1]), "+f"(d[2]), "+f"(d[3])
        : "r"(a[0]), "r"(a[1]), "r"(a[2]), "r"(a[3]), "r"(b[0]), "r"(b[1]));
}

__global__ __launch_bounds__(256, 2) void gemm_nt_bf16x3(
    const __nv_bfloat16* __restrict__ Ah, const __nv_bfloat16* __restrict__ Al,
    const __nv_bfloat16* __restrict__ Bh, const __nv_bfloat16* __restrict__ Bl,
    float* __restrict__ C, int M, int N, int K) {
    extern __shared__ __nv_bfloat16 smb[];
    // layout: sA[stage][hl][row 128][GPAD], then sB likewise
    __nv_bfloat16* sA = smb;
    __nv_bfloat16* sB = smb + 2 * 2 * 128 * GPAD;

    const int tid = threadIdx.x;
    const int wid = tid >> 5, lane = tid & 31;
    const int wm = wid >> 2, wn = wid & 3;      // warp tile: rows wm*64, cols wn*32
    const int grp = lane >> 2, q2 = (lane & 3) * 2;
    const int rowBase = blockIdx.y * 128;
    const int colBase = blockIdx.x * 128;

    const int lrow = tid >> 1;            // 0..127
    const int lkh = (tid & 1) * 8;        // 0 or 8

    float acc[4][4][4];                    // [mt][nt][4]
#pragma unroll
    for (int i = 0; i < 4; i++)
#pragma unroll
        for (int j = 0; j < 4; j++)
#pragma unroll
            for (int r = 0; r < 4; r++) acc[i][j][r] = 0.f;

    const int nk = K / GK;

#define SAIDX(st, hl, r, k) (((((st) * 2 + (hl)) * 128 + (r)) * GPAD) + (k))

    // stage load macro
    auto load_stage = [&](int st, int k0) {
        *(float4*)&sA[SAIDX(st, 0, lrow, lkh)] =
            *(const float4*)&Ah[(size_t)(rowBase + lrow) * K + k0 + lkh];
        *(float4*)&sA[SAIDX(st, 1, lrow, lkh)] =
            *(const float4*)&Al[(size_t)(rowBase + lrow) * K + k0 + lkh];
        int cn = colBase + lrow;
        float4 z = make_float4(0.f, 0.f, 0.f, 0.f);
        float4 bh = z, bl = z;
        if (cn < N) {
            bh = *(const float4*)&Bh[(size_t)cn * K + k0 + lkh];
            bl = *(const float4*)&Bl[(size_t)cn * K + k0 + lkh];
        }
        *(float4*)&sB[SAIDX(st, 0, lrow, lkh)] = bh;
        *(float4*)&sB[SAIDX(st, 1, lrow, lkh)] = bl;
    };

    load_stage(0, 0);
    __syncthreads();

    for (int ks = 0; ks < nk; ks++) {
        int st = ks & 1;
        if (ks + 1 < nk) load_stage(st ^ 1, (ks + 1) * GK);

        // B fragments for 4 n-tiles (hi & lo)
        uint32_t bh[4][2], bl[4][2];
#pragma unroll
        for (int nt = 0; nt < 4; nt++) {
            int c0 = wn * 32 + nt * 8 + grp;
            bh[nt][0] = *(const uint32_t*)&sB[SAIDX(st, 0, c0, q2)];
            bh[nt][1] = *(const uint32_t*)&sB[SAIDX(st, 0, c0, q2 + 8)];
            bl[nt][0] = *(const uint32_t*)&sB[SAIDX(st, 1, c0, q2)];
            bl[nt][1] = *(const uint32_t*)&sB[SAIDX(st, 1, c0, q2 + 8)];
        }
#pragma unroll
        for (int mt = 0; mt < 4; mt++) {
            int r0 = wm * 64 + mt * 16 + grp;
            uint32_t ah[4], al[4];
            ah[0] = *(const uint32_t*)&sA[SAIDX(st, 0, r0, q2)];
            ah[1] = *(const uint32_t*)&sA[SAIDX(st, 0, r0 + 8, q2)];
            ah[2] = *(const uint32_t*)&sA[SAIDX(st, 0, r0, q2 + 8)];
            ah[3] = *(const uint32_t*)&sA[SAIDX(st, 0, r0 + 8, q2 + 8)];
            al[0] = *(const uint32_t*)&sA[SAIDX(st, 1, r0, q2)];
            al[1] = *(const uint32_t*)&sA[SAIDX(st, 1, r0 + 8, q2)];
            al[2] = *(const uint32_t*)&sA[SAIDX(st, 1, r0, q2 + 8)];
            al[3] = *(const uint32_t*)&sA[SAIDX(st, 1, r0 + 8, q2 + 8)];
#pragma unroll
            for (int nt = 0; nt < 4; nt++) {
                mma16816(acc[mt][nt], ah, bh[nt]);
                mma16816(acc[mt][nt], ah, bl[nt]);
                mma16816(acc[mt][nt], al, bh[nt]);
            }
        }
        __syncthreads();
    }

    // store C
#pragma unroll
    for (int mt = 0; mt < 4; mt++) {
#pragma unroll
        for (int nt = 0; nt < 4; nt++) {
            int colTile = colBase + wn * 32 + nt * 8;
            if (colTile >= N) continue;
            int r0 = rowBase + wm * 64 + mt * 16 + grp;
            int c0 = colTile + q2;
            *(float2*)&C[(size_t)r0 * N + c0] = make_float2(acc[mt][nt][0], acc[mt][nt][1]);
            *(float2*)&C[(size_t)(r0 + 8) * N + c0] = make_float2(acc[mt][nt][2], acc[mt][nt][3]);
        }
    }
#undef SAIDX
}

__device__ __forceinline__ float fast_sigmoid(float x) {
    return 1.f / (1.f + __expf(-x));
}

// ---------------- conv1d (causal, depthwise, width 4) + SiLU ----------------
__global__ void conv_silu_kernel(const float* __restrict__ zx,
                                 const float* __restrict__ conv_w,
                                 const float* __restrict__ conv_b,
                                 float* __restrict__ xbc) {
    size_t idx = (size_t)blockIdx.x * 256 + threadIdx.x;
    const size_t total = (size_t)MROWS * CONVD;
    if (idx >= total) return;
    int cc = (int)(idx % CONVD);
    size_t bt = idx / CONVD;            // b*L + t
    int t = (int)(bt % L_SEQ);
    float acc = conv_b[cc];
#pragma unroll
    for (int k = 0; k < 4; k++) {
        int tt = t - 3 + k;
        if (tt >= 0)
            acc = fmaf(zx[(bt - t + tt) * DIP + 2048 + cc], conv_w[cc * 4 + k], acc);
    }
    xbc[idx] = acc * fast_sigmoid(acc);
}

// ---------------- SSM per-chunk: Y_diag + states ----------------
#define SM3_FLOATS (512 + 8 + 2 * 64 * 129 + 2 * 64 * 65)
__global__ void ssm_chunk_kernel(const float* __restrict__ zx,
                                 const float* __restrict__ xbc,
                                 const float* __restrict__ dt_bias,
                                 const float* __restrict__ A_log,
                                 const float* __restrict__ Dvec,
                                 float* __restrict__ y,
                                 float* __restrict__ states,
                                 float* __restrict__ cs_out) {
    extern __shared__ float sm[];
    float* s_dt = sm;                 // 256
    float* s_cs = sm + 256;           // 256
    float* s_wsum = sm + 512;         // 8
    float* sCt = sm + 520;            // 64*129
    float* sBs = sCt + 64 * 129;      // 64*129
    float* sXd = sBs + 64 * 129;      // 64*65
    float* sG  = sXd + 64 * 65;       // 64*65

    const int c = blockIdx.x, h = blockIdx.y, b = blockIdx.z;
    const int tid = threadIdx.x;
    const int tx = tid & 15, ty = tid >> 4;
    const int lane = tid & 31, wid = tid >> 5;
    const float Ah = -__expf(A_log[h]);

    float dA_val;
    {
        float draw = zx[((size_t)(b * L_SEQ) + c * CHUNK + tid) * DIP + 4352 + h] + dt_bias[h];
        float dt = (draw > 20.f) ? draw : log1pf(__expf(draw));
        s_dt[tid] = dt;
        dA_val = dt * Ah;
    }
    float v = dA_val;
#pragma unroll
    for (int off = 1; off < 32; off <<= 1) {
        float n = __shfl_up_sync(0xffffffffu, v, off);
        if (lane >= off) v += n;
    }
    if (lane == 31) s_wsum[wid] = v;
    __syncthreads();
    if (tid < 8) {
        float w = s_wsum[tid];
#pragma unroll
        for (int off = 1; off < 8; off <<= 1) {
            float n = __shfl_up_sync(0xffu, w, off);
            if (tid >= off) w += n;
        }
        s_wsum[tid] = w;
    }
    __syncthreads();
    float csv = v + (wid > 0 ? s_wsum[wid - 1] : 0.f);
    s_cs[tid] = csv;
    __syncthreads();
    const float csL = s_cs[CHUNK - 1];
    cs_out[(((size_t)b * NC + c) * NH + h) * CHUNK + tid] = csv;

    const float* xrow = xbc + ((size_t)(b * L_SEQ) + c * CHUNK) * CONVD;

    for (int T = 0; T < 4; T++) {
        for (int l = tid; l < 64 * 128; l += 256) {
            int i = l >> 7, n = l & 127;
            sCt[i * 129 + n] = xrow[(size_t)(T * 64 + i) * CONVD + 2176 + n];
        }
        float acc[4][4];
#pragma unroll
        for (int i = 0; i < 4; i++)
#pragma unroll
            for (int j = 0; j < 4; j++) acc[i][j] = 0.f;

        for (int S = 0; S <= T; S++) {
            __syncthreads();
            for (int l = tid; l < 64 * 128; l += 256) {
                int j = l >> 7, n = l & 127;
                sBs[j * 129 + n] = xrow[(size_t)(S * 64 + j) * CONVD + 2048 + n];
            }
            for (int l = tid; l < 64 * 64; l += 256) {
                int j = l >> 6, p = l & 63;
                sXd[j * 65 + p] = xrow[(size_t)(S * 64 + j) * CONVD + h * 64 + p] * s_dt[S * 64 + j];
            }
            __syncthreads();
            float g[4][4];
#pragma unroll
            for (int i = 0; i < 4; i++)
#pragma unroll
                for (int j = 0; j < 4; j++) g[i][j] = 0.f;
            for (int n = 0; n < 128; n++) {
                float a0 = sCt[(ty * 4 + 0) * 129 + n];
                float a1 = sCt[(ty * 4 + 1) * 129 + n];
                float a2 = sCt[(ty * 4 + 2) * 129 + n];
                float a3 = sCt[(ty * 4 + 3) * 129 + n];
                float b0 = sBs[(tx * 4 + 0) * 129 + n];
                float b1 = sBs[(tx * 4 + 1) * 129 + n];
                float b2 = sBs[(tx * 4 + 2) * 129 + n];
                float b3 = sBs[(tx * 4 + 3) * 129 + n];
                g[0][0] = fmaf(a0, b0, g[0][0]); g[0][1] = fmaf(a0, b1, g[0][1]);
                g[0][2] = fmaf(a0, b2, g[0][2]); g[0][3] = fmaf(a0, b3, g[0][3]);
                g[1][0] = fmaf(a1, b0, g[1][0]); g[1][1] = fmaf(a1, b1, g[1][1]);
                g[1][2] = fmaf(a1, b2, g[1][2]); g[1][3] = fmaf(a1, b3, g[1][3]);
                g[2][0] = fmaf(a2, b0, g[2][0]); g[2][1] = fmaf(a2, b1, g[2][1]);
                g[2][2] = fmaf(a2, b2, g[2][2]); g[2][3] = fmaf(a2, b3, g[2][3]);
                g[3][0] = fmaf(a3, b0, g[3][0]); g[3][1] = fmaf(a3, b1, g[3][1]);
                g[3][2] = fmaf(a3, b2, g[3][2]); g[3][3] = fmaf(a3, b3, g[3][3]);
            }
#pragma unroll
            for (int i = 0; i < 4; i++)
#pragma unroll
                for (int j = 0; j < 4; j++) {
                    int tg = T * 64 + ty * 4 + i;
                    int sg = S * 64 + tx * 4 + j;
                    sG[(ty * 4 + i) * 65 + tx * 4 + j] =
                        (tg >= sg) ? g[i][j] * __expf(s_cs[tg] - s_cs[sg]) : 0.f;
                }
            __syncthreads();
            for (int kk = 0; kk < 64; kk++) {
                float a0 = sG[(ty * 4 + 0) * 65 + kk];
                float a1 = sG[(ty * 4 + 1) * 65 + kk];
                float a2 = sG[(ty * 4 + 2) * 65 + kk];
                float a3 = sG[(ty * 4 + 3) * 65 + kk];
                float b0 = sXd[kk * 65 + tx * 4 + 0];
                float b1 = sXd[kk * 65 + tx * 4 + 1];
                float b2 = sXd[kk * 65 + tx * 4 + 2];
                float b3 = sXd[kk * 65 + tx * 4 + 3];
                acc[0][0] = fmaf(a0, b0, acc[0][0]); acc[0][1] = fmaf(a0, b1, acc[0][1]);
                acc[0][2] = fmaf(a0, b2, acc[0][2]); acc[0][3] = fmaf(a0, b3, acc[0][3]);
                acc[1][0] = fmaf(a1, b0, acc[1][0]); acc[1][1] = fmaf(a1, b1, acc[1][1]);
                acc[1][2] = fmaf(a1, b2, acc[1][2]); acc[1][3] = fmaf(a1, b3, acc[1][3]);
                acc[2][0] = fmaf(a2, b0, acc[2][0]); acc[2][1] = fmaf(a2, b1, acc[2][1]);
                acc[2][2] = fmaf(a2, b2, acc[2][2]); acc[2][3] = fmaf(a2, b3, acc[2][3]);
                acc[3][0] = fmaf(a3, b0, acc[3][0]); acc[3][1] = fmaf(a3, b1, acc[3][1]);
                acc[3][2] = fmaf(a3, b2, acc[3][2]); acc[3][3] = fmaf(a3, b3, acc[3][3]);
            }
        }
        float Dh = Dvec[h];
#pragma unroll
        for (int i = 0; i < 4; i++) {
            int trow = T * 64 + ty * 4 + i;
            size_t gro = ((size_t)(b * L_SEQ) + c * CHUNK + trow) * DSSM + h * 64;
#pragma unroll
            for (int j = 0; j < 4; j++) {
                int p = tx * 4 + j;
                float xv = xrow[(size_t)trow * CONVD + h * 64 + p];
                y[gro + p] = fmaf(Dh, xv, acc[i][j]);
            }
        }
    }

    // per-chunk state S[p=64][n=128]
    float st[4][8];
#pragma unroll
    for (int i = 0; i < 4; i++)
#pragma unroll
        for (int j = 0; j < 8; j++) st[i][j] = 0.f;

    for (int T = 0; T < 4; T++) {
        __syncthreads();
        for (int l = tid; l < 64 * 128; l += 256) {
            int j = l >> 7, n = l & 127;
            sBs[j * 129 + n] = xrow[(size_t)(T * 64 + j) * CONVD + 2048 + n];
        }
        for (int l = tid; l < 64 * 64; l += 256) {
            int j = l >> 6, p = l & 63;
            int t = T * 64 + j;
            sXd[j * 65 + p] = xrow[(size_t)t * CONVD + h * 64 + p] * s_dt[t] * __expf(csL - s_cs[t]);
        }
        __syncthreads();
        for (int kk = 0; kk < 64; kk++) {
            float a[4];
#pragma unroll
            for (int i = 0; i < 4; i++) a[i] = sXd[kk * 65 + ty * 4 + i];
            float bb[8];
#pragma unroll
            for (int j = 0; j < 8; j++) bb[j] = sBs[kk * 129 + tx * 8 + j];
#pragma unroll
            for (int i = 0; i < 4; i++)
#pragma unroll
                for (int j = 0; j < 8; j++) st[i][j] = fmaf(a[i], bb[j], st[i][j]);
        }
    }
    size_t sbase = (((size_t)b * NC + c) * NH + h) * (size_t)(HD * DS);
#pragma unroll
    for (int i = 0; i < 4; i++)
#pragma unroll
        for (int j = 0; j < 8; j++)
            states[sbase + (size_t)(ty * 4 + i) * DS + tx * 8 + j] = st[i][j];
}

// ---------------- inter-chunk recurrence (high-occupancy version) ----------------
__global__ void chunk_scan_kernel2(const float* __restrict__ states,
                                   const float* __restrict__ cs,
                                   float* __restrict__ prev) {
    const int seg = blockIdx.x, h = blockIdx.y, b = blockIdx.z;
    const int e = seg * 256 + threadIdx.x;
    float P = 0.f;
    for (int c = 0; c < NC; c++) {
        size_t base = ((size_t)b * NC + c) * NH + h;
        float sc = __expf(cs[base * CHUNK + CHUNK - 1]);
        size_t off = base * (size_t)(HD * DS) + e;
        prev[off] = P;
        P = fmaf(P, sc, states[off]);
    }
}

// ---------------- Y_off = (C .* exp(cs)) @ prev^T, added into y ----------------
#define SM5_FLOATS (2 * 64 * 129 + 256)
__global__ void yoff_kernel(const float* __restrict__ xbc,
                            const float* __restrict__ prev,
                            const float* __restrict__ cs,
                            float* __restrict__ y) {
    extern __shared__ float sm[];
    float* sP = sm;                   // 64*129
    float* sCt = sP + 64 * 129;       // 64*129
    float* sE = sCt + 64 * 129;       // 256

    const int c = blockIdx.x, h = blockIdx.y, b = blockIdx.z;
    const int tid = threadIdx.x;
    const int tx = tid & 15, ty = tid >> 4;

    size_t base = ((size_t)b * NC + c) * NH + h;
    sE[tid] = __expf(cs[base * CHUNK + tid]);
    size_t poff = base * (size_t)(HD * DS);
    for (int l = tid; l < 64 * 128; l += 256) {
        int p = l >> 7, n = l & 127;
        sP[p * 129 + n] = prev[poff + (size_t)p * DS + n];
    }
    const float* xrow = xbc + ((size_t)(b * L_SEQ) + c * CHUNK) * CONVD;

    for (int T = 0; T < 4; T++) {
        __syncthreads();
        for (int l = tid; l < 64 * 128; l += 256) {
            int i = l >> 7, n = l & 127;
            sCt[i * 129 + n] = xrow[(size_t)(T * 64 + i) * CONVD + 2176 + n];
        }
        __syncthreads();
        float acc[4][4];
#pragma unroll
        for (int i = 0; i < 4; i++)
#pragma unroll
            for (int j = 0; j < 4; j++) acc[i][j] = 0.f;
        for (int n = 0; n < 128; n++) {
            float a0 = sCt[(ty * 4 + 0) * 129 + n];
            float a1 = sCt[(ty * 4 + 1) * 129 + n];
            float a2 = sCt[(ty * 4 + 2) * 129 + n];
            float a3 = sCt[(ty * 4 + 3) * 129 + n];
            float b0 = sP[(tx * 4 + 0) * 129 + n];
            float b1 = sP[(tx * 4 + 1) * 129 + n];
            float b2 = sP[(tx * 4 + 2) * 129 + n];
            float b3 = sP[(tx * 4 + 3) * 129 + n];
            acc[0][0] = fmaf(a0, b0, acc[0][0]); acc[0][1] = fmaf(a0, b1, acc[0][1]);
            acc[0][2] = fmaf(a0, b2, acc[0][2]); acc[0][3] = fmaf(a0, b3, acc[0][3]);
            acc[1][0] = fmaf(a1, b0, acc[1][0]); acc[1][1] = fmaf(a1, b1, acc[1][1]);
            acc[1][2] = fmaf(a1, b2, acc[1][2]); acc[1][3] = fmaf(a1, b3, acc[1][3]);
            acc[2][0] = fmaf(a2, b0, acc[2][0]); acc[2][1] = fmaf(a2, b1, acc[2][1]);
            acc[2][2] = fmaf(a2, b2, acc[2][2]); acc[2][3] = fmaf(a2, b3, acc[2][3]);
            acc[3][0] = fmaf(a3, b0, acc[3][0]); acc[3][1] = fmaf(a3, b1, acc[3][1]);
            acc[3][2] = fmaf(a3, b2, acc[3][2]); acc[3][3] = fmaf(a3, b3, acc[3][3]);
        }
#pragma unroll
        for (int i = 0; i < 4; i++) {
            int trow = T * 64 + ty * 4 + i;
            size_t go = ((size_t)(b * L_SEQ) + c * CHUNK + trow) * DSSM + h * 64 + tx * 4;
            float e = sE[trow];
#pragma unroll
            for (int j = 0; j < 4; j++) y[go + j] += acc[i][j] * e;
        }
    }
}

// ---------------- gate (y * silu(z)) + RMSNorm ----------------
__global__ void gate_norm_kernel(const float* __restrict__ zx,
                                 const float* __restrict__ y,
                                 const float* __restrict__ norm_w,
                                 float* __restrict__ yn) {
    const int row = blockIdx.x;
    const int tid = threadIdx.x;
    const float* yrow = y + (size_t)row * DSSM;
    const float* zrow = zx + (size_t)row * DIP;
    float v[8];
    float ss = 0.f;
#pragma unroll
    for (int k = 0; k < 8; k++) {
        int e = tid + k * 256;
        float z = zrow[e];
        float vv = yrow[e] * (z * fast_sigmoid(z));
        v[k] = vv;
        ss = fmaf(vv, vv, ss);
    }
    __shared__ float red[256];
    red[tid] = ss;
    __syncthreads();
    for (int s = 128; s > 0; s >>= 1) {
        if (tid < s) red[tid] += red[tid + s];
        __syncthreads();
    }
    float r = rsqrtf(red[0] / (float)DSSM + 1e-5f);
#pragma unroll
    for (int k = 0; k < 8; k++) {
        int e = tid + k * 256;
        yn[(size_t)row * DSSM + e] = v[k] * r * norm_w[e];
    }
}

// ---------------- host launch ----------------
extern "C" void kernel_launch(void* const* d_in, const int* in_sizes, int n_in,
                              void* d_out, int out_size) {
    const float* u       = (const float*)d_in[0];
    const float* W_in    = (const float*)d_in[1];
    const float* conv_w  = (const float*)d_in[2];
    const float* conv_b  = (const float*)d_in[3];
    const float* dt_bias = (const float*)d_in[4];
    const float* A_log   = (const float*)d_in[5];
    const float* Dv      = (const float*)d_in[6];
    const float* norm_w  = (const float*)d_in[7];
    const float* W_out   = (const float*)d_in[8];
    float* out = (float*)d_out;

    void *p_zx, *p_xbc, *p_y, *p_yn, *p_states, *p_prev, *p_cs;
    void *p_uh, *p_ul, *p_wih, *p_wil, *p_ynh, *p_ynl, *p_woh, *p_wol;
    cudaGetSymbolAddress(&p_zx, g_zx);
    cudaGetSymbolAddress(&p_xbc, g_xbc);
    cudaGetSymbolAddress(&p_y, g_y);
    cudaGetSymbolAddress(&p_yn, g_yn);
    cudaGetSymbolAddress(&p_states, g_states);
    cudaGetSymbolAddress(&p_prev, g_prev);
    cudaGetSymbolAddress(&p_cs, g_cs);
    cudaGetSymbolAddress(&p_uh, g_uh);
    cudaGetSymbolAddress(&p_ul, g_ul);
    cudaGetSymbolAddress(&p_wih, g_wih);
    cudaGetSymbolAddress(&p_wil, g_wil);
    cudaGetSymbolAddress(&p_ynh, g_ynh);
    cudaGetSymbolAddress(&p_ynl, g_ynl);
    cudaGetSymbolAddress(&p_woh, g_woh);
    cudaGetSymbolAddress(&p_wol, g_wol);
    float* zx = (float*)p_zx;
    float* xbc = (float*)p_xbc;
    float* y = (float*)p_y;
    float* yn = (float*)p_yn;
    float* states = (float*)p_states;
    float* prev = (float*)p_prev;
    float* cs = (float*)p_cs;
    __nv_bfloat16* uh = (__nv_bfloat16*)p_uh;
    __nv_bfloat16* ul = (__nv_bfloat16*)p_ul;
    __nv_bfloat16* wih = (__nv_bfloat16*)p_wih;
    __nv_bfloat16* wil = (__nv_bfloat16*)p_wil;
    __nv_bfloat16* ynh = (__nv_bfloat16*)p_ynh;
    __nv_bfloat16* ynl = (__nv_bfloat16*)p_ynl;
    __nv_bfloat16* woh = (__nv_bfloat16*)p_woh;
    __nv_bfloat16* wol = (__nv_bfloat16*)p_wol;

    cudaFuncSetAttribute(ssm_chunk_kernel, cudaFuncAttributeMaxDynamicSharedMemorySize,
                         SM3_FLOATS * sizeof(float));
    cudaFuncSetAttribute(yoff_kernel, cudaFuncAttributeMaxDynamicSharedMemorySize,
                         SM5_FLOATS * sizeof(float));
    cudaFuncSetAttribute(gemm_nt_bf16x3, cudaFuncAttributeMaxDynamicSharedMemorySize,
                         GEMM_SMEM);

    // 0. split inputs to bf16 hi/lo
    {
        int n4 = MROWS * D_MODEL / 4;
        split_bf16_kernel<<<(n4 + 255) / 256, 256>>>(u, uh, ul, n4);
        n4 = DIP * D_MODEL / 4;
        split_bf16_kernel<<<(n4 + 255) / 256, 256>>>(W_in, wih, wil, n4);
        n4 = D_MODEL * DSSM / 4;
        split_bf16_kernel<<<(n4 + 255) / 256, 256>>>(W_out, woh, wol, n4);
    }

    // 1. in_proj: zxbcdt = u @ W_in^T   (8192 x 4384 x 1024) via tensor cores
    gemm_nt_bf16x3<<<dim3((DIP + 127) / 128, MROWS / 128), 256, GEMM_SMEM>>>(
        uh, ul, wih, wil, zx, MROWS, DIP, D_MODEL);

    // 2. conv1d + silu
    {
        size_t total = (size_t)MROWS * CONVD;
        conv_silu_kernel<<<(unsigned)((total + 255) / 256), 256>>>(zx, conv_w, conv_b, xbc);
    }

    // 3. per-chunk SSM
    ssm_chunk_kernel<<<dim3(NC, NH, BATCH), 256, SM3_FLOATS * sizeof(float)>>>(
        zx, xbc, dt_bias, A_log, Dv, y, states, cs);

    // 4. inter-chunk recurrence
    chunk_scan_kernel2<<<dim3(32, NH, BATCH), 256>>>(states, cs, prev);

    // 5. Y_off
    yoff_kernel<<<dim3(NC, NH, BATCH), 256, SM5_FLOATS * sizeof(float)>>>(xbc, prev, cs, y);

    // 6. gate + RMSNorm
    gate_norm_kernel<<<MROWS, 256>>>(zx, y, norm_w, yn);

    // 7. split yn, out_proj via tensor cores
    {
        int n4 = MROWS * DSSM / 4;
        split_bf16_kernel<<<(n4 + 255) / 256, 256>>>(yn, ynh, ynl, n4);
    }
    gemm_nt_bf16x3<<<dim3(D_MODEL / 128, MROWS / 128), 256, GEMM_SMEM>>>(
        ynh, ynl, woh, wol, out, MROWS, D_MODEL, DSSM);
}

// round 4
// speedup vs baseline: 1.9868x; 1.2251x over previous
#include <cuda_runtime.h>
#include <cuda_bf16.h>
#include <math.h>
#include <stdint.h>

#define BATCH 2
#define L_SEQ 4096
#define D_MODEL 1024
#define DIP 4384          // D_IN_PROJ
#define DSSM 2048
#define CONVD 2304        // CONV_DIM
#define NH 32
#define HD 64
#define DS 128
#define NC64 64           // chunks of 64 per batch
#define TCH 64            // tile length
#define MROWS (BATCH * L_SEQ)   // 8192

// ---------------- scratch (device globals; no allocation) ----------------
__device__ float g_zx[(size_t)MROWS * DIP];
__device__ float g_xbc[(size_t)MROWS * CONVD];
__device__ float g_y[(size_t)MROWS * DSSM];
__device__ float g_yn[(size_t)MROWS * DSSM];
__device__ float g_states[(size_t)BATCH * NC64 * NH * HD * DS];
__device__ float g_prev[(size_t)BATCH * NC64 * NH * HD * DS];
__device__ float g_cs[(size_t)BATCH * NC64 * NH * TCH];

// bf16 hi/lo split buffers for projection GEMMs
__device__ __nv_bfloat16 g_uh[(size_t)MROWS * D_MODEL];
__device__ __nv_bfloat16 g_ul[(size_t)MROWS * D_MODEL];
__device__ __nv_bfloat16 g_wih[(size_t)DIP * D_MODEL];
__device__ __nv_bfloat16 g_wil[(size_t)DIP * D_MODEL];
__device__ __nv_bfloat16 g_ynh[(size_t)MROWS * DSSM];
__device__ __nv_bfloat16 g_ynl[(size_t)MROWS * DSSM];
__device__ __nv_bfloat16 g_woh[(size_t)D_MODEL * DSSM];
__device__ __nv_bfloat16 g_wol[(size_t)D_MODEL * DSSM];

// ---------------- helpers ----------------
struct alignas(8) bf16x4 { __nv_bfloat16 a, b, c, d; };

__device__ __forceinline__ float fast_sigmoid(float x) {
    return 1.f / (1.f + __expf(-x));
}

__device__ __forceinline__ void mma16816(float* d, const uint32_t* a, const uint32_t* b) {
    asm volatile(
        "mma.sync.aligned.m16n8k16.row.col.f32.bf16.bf16.f32 "
        "{%0,%1,%2,%3}, {%4,%5,%6,%7}, {%8,%9}, {%0,%1,%2,%3};"
        : "+f"(d[0]), "+f"(d[1]), "+f"(d[2]), "+f"(d[3])
        : "r"(a[0]), "r"(a[1]), "r"(a[2]), "r"(a[3]), "r"(b[0]), "r"(b[1]));
}

__device__ __forceinline__ void bfsplit(float v, __nv_bfloat16& h, __nv_bfloat16& l) {
    h = __float2bfloat16(v);
    l = __float2bfloat16(v - __bfloat162float(h));
}

// ---------------- fp32 -> bf16 hi/lo split ----------------
__global__ void split_bf16_kernel(const float* __restrict__ x,
                                  __nv_bfloat16* __restrict__ hi,
                                  __nv_bfloat16* __restrict__ lo, int n4) {
    int i = blockIdx.x * 256 + threadIdx.x;
    if (i >= n4) return;
    float4 v = ((const float4*)x)[i];
    __nv_bfloat16 h0, h1, h2, h3, l0, l1, l2, l3;
    bfsplit(v.x, h0, l0); bfsplit(v.y, h1, l1);
    bfsplit(v.z, h2, l2); bfsplit(v.w, h3, l3);
    bf16x4 hv = {h0, h1, h2, h3};
    bf16x4 lv = {l0, l1, l2, l3};
    ((bf16x4*)hi)[i] = hv;
    ((bf16x4*)lo)[i] = lv;
}

// ---------------- tensor-core GEMM: C[M,N] = A[M,K] * B[N,K]^T (hi/lo x3) ----------------
#define GK 16
#define GPAD 24
#define GEMM_SMEM (2 * 2 * 128 * GPAD * 2 * 2)  // 49152 bytes

__global__ __launch_bounds__(256, 2) void gemm_nt_bf16x3(
    const __nv_bfloat16* __restrict__ Ah, const __nv_bfloat16* __restrict__ Al,
    const __nv_bfloat16* __restrict__ Bh, const __nv_bfloat16* __restrict__ Bl,
    float* __restrict__ C, int M, int N, int K) {
    extern __shared__ __nv_bfloat16 smb[];
    __nv_bfloat16* sA = smb;
    __nv_bfloat16* sB = smb + 2 * 2 * 128 * GPAD;

    const int tid = threadIdx.x;
    const int wid = tid >> 5, lane = tid & 31;
    const int wm = wid >> 2, wn = wid & 3;
    const int grp = lane >> 2, q2 = (lane & 3) * 2;
    const int rowBase = blockIdx.y * 128;
    const int colBase = blockIdx.x * 128;
    const int lrow = tid >> 1;
    const int lkh = (tid & 1) * 8;

    float acc[4][4][4];
#pragma unroll
    for (int i = 0; i < 4; i++)
#pragma unroll
        for (int j = 0; j < 4; j++)
#pragma unroll
            for (int r = 0; r < 4; r++) acc[i][j][r] = 0.f;

    const int nk = K / GK;
#define SAIDX(st, hl, r, k) (((((st) * 2 + (hl)) * 128 + (r)) * GPAD) + (k))
    auto load_stage = [&](int st, int k0) {
        *(float4*)&sA[SAIDX(st, 0, lrow, lkh)] =
            *(const float4*)&Ah[(size_t)(rowBase + lrow) * K + k0 + lkh];
        *(float4*)&sA[SAIDX(st, 1, lrow, lkh)] =
            *(const float4*)&Al[(size_t)(rowBase + lrow) * K + k0 + lkh];
        int cn = colBase + lrow;
        float4 z = make_float4(0.f, 0.f, 0.f, 0.f);
        float4 bh = z, bl = z;
        if (cn < N) {
            bh = *(const float4*)&Bh[(size_t)cn * K + k0 + lkh];
            bl = *(const float4*)&Bl[(size_t)cn * K + k0 + lkh];
        }
        *(float4*)&sB[SAIDX(st, 0, lrow, lkh)] = bh;
        *(float4*)&sB[SAIDX(st, 1, lrow, lkh)] = bl;
    };

    load_stage(0, 0);
    __syncthreads();

    for (int ks = 0; ks < nk; ks++) {
        int st = ks & 1;
        if (ks + 1 < nk) load_stage(st ^ 1, (ks + 1) * GK);
        uint32_t bh[4][2], bl[4][2];
#pragma unroll
        for (int nt = 0; nt < 4; nt++) {
            int c0 = wn * 32 + nt * 8 + grp;
            bh[nt][0] = *(const uint32_t*)&sB[SAIDX(st, 0, c0, q2)];
            bh[nt][1] = *(const uint32_t*)&sB[SAIDX(st, 0, c0, q2 + 8)];
            bl[nt][0] = *(const uint32_t*)&sB[SAIDX(st, 1, c0, q2)];
            bl[nt][1] = *(const uint32_t*)&sB[SAIDX(st, 1, c0, q2 + 8)];
        }
#pragma unroll
        for (int mt = 0; mt < 4; mt++) {
            int r0 = wm * 64 + mt * 16 + grp;
            uint32_t ah[4], al[4];
            ah[0] = *(const uint32_t*)&sA[SAIDX(st, 0, r0, q2)];
            ah[1] = *(const uint32_t*)&sA[SAIDX(st, 0, r0 + 8, q2)];
            ah[2] = *(const uint32_t*)&sA[SAIDX(st, 0, r0, q2 + 8)];
            ah[3] = *(const uint32_t*)&sA[SAIDX(st, 0, r0 + 8, q2 + 8)];
            al[0] = *(const uint32_t*)&sA[SAIDX(st, 1, r0, q2)];
            al[1] = *(const uint32_t*)&sA[SAIDX(st, 1, r0 + 8, q2)];
            al[2] = *(const uint32_t*)&sA[SAIDX(st, 1, r0, q2 + 8)];
            al[3] = *(const uint32_t*)&sA[SAIDX(st, 1, r0 + 8, q2 + 8)];
#pragma unroll
            for (int nt = 0; nt < 4; nt++) {
                mma16816(acc[mt][nt], ah, bh[nt]);
                mma16816(acc[mt][nt], ah, bl[nt]);
                mma16816(acc[mt][nt], al, bh[nt]);
            }
        }
        __syncthreads();
    }
#pragma unroll
    for (int mt = 0; mt < 4; mt++) {
#pragma unroll
        for (int nt = 0; nt < 4; nt++) {
            int colTile = colBase + wn * 32 + nt * 8;
            if (colTile >= N) continue;
            int r0 = rowBase + wm * 64 + mt * 16 + grp;
            int c0 = colTile + q2;
            *(float2*)&C[(size_t)r0 * N + c0] = make_float2(acc[mt][nt][0], acc[mt][nt][1]);
            *(float2*)&C[(size_t)(r0 + 8) * N + c0] = make_float2(acc[mt][nt][2], acc[mt][nt][3]);
        }
    }
#undef SAIDX
}

// ---------------- conv1d (causal, depthwise, width 4) + SiLU ----------------
__global__ void conv_silu_kernel(const float* __restrict__ zx,
                                 const float* __restrict__ conv_w,
                                 const float* __restrict__ conv_b,
                                 float* __restrict__ xbc) {
    size_t idx = (size_t)blockIdx.x * 256 + threadIdx.x;
    const size_t total = (size_t)MROWS * CONVD;
    if (idx >= total) return;
    int cc = (int)(idx % CONVD);
    size_t bt = idx / CONVD;
    int t = (int)(bt % L_SEQ);
    float acc = conv_b[cc];
#pragma unroll
    for (int k = 0; k < 4; k++) {
        int tt = t - 3 + k;
        if (tt >= 0)
            acc = fmaf(zx[(bt - t + tt) * DIP + 2048 + cc], conv_w[cc * 4 + k], acc);
    }
    xbc[idx] = acc * fast_sigmoid(acc);
}

// ---------------- K1: intra-chunk SSM on tensor cores ----------------
// grid (NC64, BATCH), 256 threads. B,C shared across heads (ngroups=1).
#define SB_S 136   // (s|t, n) tiles stride (128+8)
#define ST_S 66    // (*, s) tiles stride (64+2)
#define SM_K1_BYTES ((4 * 64 * SB_S + 2 * 128 * ST_S + 6 * 64 * ST_S) * 2 + \
                     (64 * ST_S + 2 * 32 * 64 + 64) * 4)

__global__ __launch_bounds__(256, 1) void ssm_intra_kernel(
    const float* __restrict__ zx, const float* __restrict__ xbc,
    const float* __restrict__ dt_bias, const float* __restrict__ A_log,
    const float* __restrict__ Dvec,
    float* __restrict__ y, float* __restrict__ states, float* __restrict__ cs_out) {
    extern __shared__ char smraw[];
    __nv_bfloat16* sBh = (__nv_bfloat16*)smraw;       // 64 x SB_S  (s, n)
    __nv_bfloat16* sBl = sBh + 64 * SB_S;
    __nv_bfloat16* sCh = sBl + 64 * SB_S;             // 64 x SB_S  (t, n)
    __nv_bfloat16* sCl = sCh + 64 * SB_S;
    __nv_bfloat16* sBTh = sCl + 64 * SB_S;            // 128 x ST_S (n, s)
    __nv_bfloat16* sBTl = sBTh + 128 * ST_S;
    __nv_bfloat16* sGh = sBTl + 128 * ST_S;           // 64 x ST_S  (t, s)
    __nv_bfloat16* sGl = sGh + 64 * ST_S;
    __nv_bfloat16* sXh = sGl + 64 * ST_S;             // 64 x ST_S  (p, s)  x*dt
    __nv_bfloat16* sXl = sXh + 64 * ST_S;
    __nv_bfloat16* sXdh = sXl + 64 * ST_S;            // 64 x ST_S  (p, s)  x*dt*decay
    __nv_bfloat16* sXdl = sXdh + 64 * ST_S;
    float* sG = (float*)(sXdl + 64 * ST_S);           // 64 x ST_S fp32
    float* s_dt = sG + 64 * ST_S;                     // 32 x 64
    float* s_cs = s_dt + 32 * 64;                     // 32 x 64
    float* sEd = s_cs + 32 * 64;                      // 64

    const int c = blockIdx.x, b = blockIdx.y;
    const int tid = threadIdx.x;
    const int wid = tid >> 5, lane = tid & 31;
    const int wm = wid >> 2, wn = wid & 3;
    const int grp = lane >> 2, q2 = (lane & 3) * 2;
    const int row0 = b * L_SEQ + c * TCH;
    const float* xrow = xbc + (size_t)row0 * CONVD;

    // ---- dt / cumsum per head (warp w handles heads 4w..4w+3) ----
    for (int hh = 0; hh < 4; hh++) {
        int h = wid * 4 + hh;
        float Ah = -__expf(A_log[h]);
        float bias = dt_bias[h];
        float d0 = zx[(size_t)(row0 + lane) * DIP + 4352 + h] + bias;
        float d1 = zx[(size_t)(row0 + 32 + lane) * DIP + 4352 + h] + bias;
        float dt0 = (d0 > 20.f) ? d0 : log1pf(__expf(d0));
        float dt1 = (d1 > 20.f) ? d1 : log1pf(__expf(d1));
        s_dt[h * 64 + lane] = dt0;
        s_dt[h * 64 + 32 + lane] = dt1;
        float v0 = dt0 * Ah, v1 = dt1 * Ah;
#pragma unroll
        for (int off = 1; off < 32; off <<= 1) {
            float n0 = __shfl_up_sync(0xffffffffu, v0, off);
            float n1 = __shfl_up_sync(0xffffffffu, v1, off);
            if (lane >= off) { v0 += n0; v1 += n1; }
        }
        v1 += __shfl_sync(0xffffffffu, v0, 31);
        s_cs[h * 64 + lane] = v0;
        s_cs[h * 64 + 32 + lane] = v1;
        size_t cbase = (((size_t)b * NC64 + c) * NH + h) * TCH;
        cs_out[cbase + lane] = v0;
        cs_out[cbase + 32 + lane] = v1;
    }

    // ---- load B, C; split; also transposed B ----
    for (int idx = tid; idx < 64 * 128; idx += 256) {
        int s = idx >> 7, n = idx & 127;
        float bv = xrow[(size_t)s * CONVD + 2048 + n];
        float cv = xrow[(size_t)s * CONVD + 2176 + n];
        __nv_bfloat16 bh, bl, ch, cl;
        bfsplit(bv, bh, bl);
        bfsplit(cv, ch, cl);
        sBh[s * SB_S + n] = bh; sBl[s * SB_S + n] = bl;
        sCh[s * SB_S + n] = ch; sCl[s * SB_S + n] = cl;
        sBTh[n * ST_S + s] = bh; sBTl[n * ST_S + s] = bl;
    }
    __syncthreads();

    // ---- G = C * B^T (64 x 64 x 128), shared across heads ----
    {
        float g[2][2][4];
#pragma unroll
        for (int i = 0; i < 2; i++)
#pragma unroll
            for (int j = 0; j < 2; j++)
#pragma unroll
                for (int r = 0; r < 4; r++) g[i][j][r] = 0.f;
        for (int kb = 0; kb < 128; kb += 16) {
            uint32_t bh[2][2], bl[2][2];
#pragma unroll
            for (int nt = 0; nt < 2; nt++) {
                int c0 = wn * 16 + nt * 8 + grp;
                bh[nt][0] = *(const uint32_t*)&sBh[c0 * SB_S + kb + q2];
                bh[nt][1] = *(const uint32_t*)&sBh[c0 * SB_S + kb + q2 + 8];
                bl[nt][0] = *(const uint32_t*)&sBl[c0 * SB_S + kb + q2];
                bl[nt][1] = *(const uint32_t*)&sBl[c0 * SB_S + kb + q2 + 8];
            }
#pragma unroll
            for (int mt = 0; mt < 2; mt++) {
                int r0 = wm * 32 + mt * 16 + grp;
                uint32_t ah[4], al[4];
                ah[0] = *(const uint32_t*)&sCh[r0 * SB_S + kb + q2];
                ah[1] = *(const uint32_t*)&sCh[(r0 + 8) * SB_S + kb + q2];
                ah[2] = *(const uint32_t*)&sCh[r0 * SB_S + kb + q2 + 8];
                ah[3] = *(const uint32_t*)&sCh[(r0 + 8) * SB_S + kb + q2 + 8];
                al[0] = *(const uint32_t*)&sCl[r0 * SB_S + kb + q2];
                al[1] = *(const uint32_t*)&sCl[(r0 + 8) * SB_S + kb + q2];
                al[2] = *(const uint32_t*)&sCl[r0 * SB_S + kb + q2 + 8];
                al[3] = *(const uint32_t*)&sCl[(r0 + 8) * SB_S + kb + q2 + 8];
#pragma unroll
                for (int nt = 0; nt < 2; nt++) {
                    mma16816(g[mt][nt], ah, bh[nt]);
                    mma16816(g[mt][nt], ah, bl[nt]);
                    mma16816(g[mt][nt], al, bh[nt]);
                }
            }
        }
#pragma unroll
        for (int mt = 0; mt < 2; mt++)
#pragma unroll
            for (int nt = 0; nt < 2; nt++) {
                int t = wm * 32 + mt * 16 + grp;
                int s = wn * 16 + nt * 8 + q2;
                *(float2*)&sG[t * ST_S + s] = make_float2(g[mt][nt][0], g[mt][nt][1]);
                *(float2*)&sG[(t + 8) * ST_S + s] = make_float2(g[mt][nt][2], g[mt][nt][3]);
            }
    }

    // ---- per head ----
    for (int h = 0; h < NH; h++) {
        __syncthreads();   // G ready / prev head mma reads done
        const float* csh = s_cs + h * 64;
        const float* dth = s_dt + h * 64;
        const float csL = csh[63];
        if (tid < 64) sEd[tid] = __expf(csL - csh[tid]);
        // decay+mask G, split to bf16
        for (int idx = tid; idx < 64 * 64; idx += 256) {
            int t = idx >> 6, s = idx & 63;
            float val = 0.f;
            if (t >= s) val = sG[t * ST_S + s] * __expf(csh[t] - csh[s]);
            __nv_bfloat16 hch, hcl;
            bfsplit(val, hch, hcl);
            sGh[t * ST_S + s] = hch;
            sGl[t * ST_S + s] = hcl;
        }
        __syncthreads();   // sEd + G~ ready
        // x tilde (transposed): sX[p][s] = x[s][p]*dt[s];  sXd adds *exp(csL-cs[s])
        for (int idx = tid; idx < 64 * 64; idx += 256) {
            int s = idx >> 6, p = idx & 63;
            float xv = xrow[(size_t)s * CONVD + h * 64 + p];
            float xt = xv * dth[s];
            __nv_bfloat16 xh, xl, xdh, xdl;
            bfsplit(xt, xh, xl);
            bfsplit(xt * sEd[s], xdh, xdl);
            sXh[p * ST_S + s] = xh;  sXl[p * ST_S + s] = xl;
            sXdh[p * ST_S + s] = xdh; sXdl[p * ST_S + s] = xdl;
        }
        __syncthreads();

        // Y_diag = G~ * x~  (M=64 t, N=64 p, K=64 s)
        {
            float yd[2][2][4];
#pragma unroll
            for (int i = 0; i < 2; i++)
#pragma unroll
                for (int j = 0; j < 2; j++)
#pragma unroll
                    for (int r = 0; r < 4; r++) yd[i][j][r] = 0.f;
            for (int kb = 0; kb < 64; kb += 16) {
                uint32_t bh[2][2], bl[2][2];
#pragma unroll
                for (int nt = 0; nt < 2; nt++) {
                    int c0 = wn * 16 + nt * 8 + grp;
                    bh[nt][0] = *(const uint32_t*)&sXh[c0 * ST_S + kb + q2];
                    bh[nt][1] = *(const uint32_t*)&sXh[c0 * ST_S + kb + q2 + 8];
                    bl[nt][0] = *(const uint32_t*)&sXl[c0 * ST_S + kb + q2];
                    bl[nt][1] = *(const uint32_t*)&sXl[c0 * ST_S + kb + q2 + 8];
                }
#pragma unroll
                for (int mt = 0; mt < 2; mt++) {
                    int r0 = wm * 32 + mt * 16 + grp;
                    uint32_t ah[4], al[4];
                    ah[0] = *(const uint32_t*)&sGh[r0 * ST_S + kb + q2];
                    ah[1] = *(const uint32_t*)&sGh[(r0 + 8) * ST_S + kb + q2];
                    ah[2] = *(const uint32_t*)&sGh[r0 * ST_S + kb + q2 + 8];
                    ah[3] = *(const uint32_t*)&sGh[(r0 + 8) * ST_S + kb + q2 + 8];
                    al[0] = *(const uint32_t*)&sGl[r0 * ST_S + kb + q2];
                    al[1] = *(const uint32_t*)&sGl[(r0 + 8) * ST_S + kb + q2];
                    al[2] = *(const uint32_t*)&sGl[r0 * ST_S + kb + q2 + 8];
                    al[3] = *(const uint32_t*)&sGl[(r0 + 8) * ST_S + kb + q2 + 8];
#pragma unroll
                    for (int nt = 0; nt < 2; nt++) {
                        mma16816(yd[mt][nt], ah, bh[nt]);
                        mma16816(yd[mt][nt], ah, bl[nt]);
                        mma16816(yd[mt][nt], al, bh[nt]);
                    }
                }
            }
            // write Y_diag + D*x
            float Dh = Dvec[h];
#pragma unroll
            for (int mt = 0; mt < 2; mt++)
#pragma unroll
                for (int nt = 0; nt < 2; nt++) {
                    int t0 = wm * 32 + mt * 16 + grp;
                    int p0 = wn * 16 + nt * 8 + q2;
#pragma unroll
                    for (int rr = 0; rr < 2; rr++) {
                        int t = t0 + rr * 8;
                        float2 xv = *(const float2*)&xrow[(size_t)t * CONVD + h * 64 + p0];
                        float2 o;
                        o.x = fmaf(Dh, xv.x, yd[mt][nt][rr * 2 + 0]);
                        o.y = fmaf(Dh, xv.y, yd[mt][nt][rr * 2 + 1]);
                        *(float2*)&g_y[(size_t)(row0 + t) * DSSM + h * 64 + p0] = o;
                    }
                }
        }

        // state = x~d^T * B  (M=64 p, N=128 n, K=64 s)
        {
            float st[2][4][4];
#pragma unroll
            for (int i = 0; i < 2; i++)
#pragma unroll
                for (int j = 0; j < 4; j++)
#pragma unroll
                    for (int r = 0; r < 4; r++) st[i][j][r] = 0.f;
            for (int kb = 0; kb < 64; kb += 16) {
                uint32_t bh[4][2], bl[4][2];
#pragma unroll
                for (int nt = 0; nt < 4; nt++) {
                    int c0 = wn * 32 + nt * 8 + grp;
                    bh[nt][0] = *(const uint32_t*)&sBTh[c0 * ST_S + kb + q2];
                    bh[nt][1] = *(const uint32_t*)&sBTh[c0 * ST_S + kb + q2 + 8];
                    bl[nt][0] = *(const uint32_t*)&sBTl[c0 * ST_S + kb + q2];
                    bl[nt][1] = *(const uint32_t*)&sBTl[c0 * ST_S + kb + q2 + 8];
                }
#pragma unroll
                for (int mt = 0; mt < 2; mt++) {
                    int r0 = wm * 32 + mt * 16 + grp;
                    uint32_t ah[4], al[4];
                    ah[0] = *(const uint32_t*)&sXdh[r0 * ST_S + kb + q2];
                    ah[1] = *(const uint32_t*)&sXdh[(r0 + 8) * ST_S + kb + q2];
                    ah[2] = *(const uint32_t*)&sXdh[r0 * ST_S + kb + q2 + 8];
                    ah[3] = *(const uint32_t*)&sXdh[(r0 + 8) * ST_S + kb + q2 + 8];
                    al[0] = *(const uint32_t*)&sXdl[r0 * ST_S + kb + q2];
                    al[1] = *(const uint32_t*)&sXdl[(r0 + 8) * ST_S + kb + q2];
                    al[2] = *(const uint32_t*)&sXdl[r0 * ST_S + kb + q2 + 8];
                    al[3] = *(const uint32_t*)&sXdl[(r0 + 8) * ST_S + kb + q2 + 8];
#pragma unroll
                    for (int nt = 0; nt < 4; nt++) {
                        mma16816(st[mt][nt], ah, bh[nt]);
                        mma16816(st[mt][nt], ah, bl[nt]);
                        mma16816(st[mt][nt], al, bh[nt]);
                    }
                }
            }
            size_t sbase = (((size_t)b * NC64 + c) * NH + h) * (size_t)(HD * DS);
#pragma unroll
            for (int mt = 0; mt < 2; mt++)
#pragma unroll
                for (int nt = 0; nt < 4; nt++) {
                    int p0 = wm * 32 + mt * 16 + grp;
                    int n0 = wn * 32 + nt * 8 + q2;
                    *(float2*)&states[sbase + (size_t)p0 * DS + n0] =
                        make_float2(st[mt][nt][0], st[mt][nt][1]);
                    *(float2*)&states[sbase + (size_t)(p0 + 8) * DS + n0] =
                        make_float2(st[mt][nt][2], st[mt][nt][3]);
                }
        }
    }
}

// ---------------- K2: inter-chunk recurrence over 64 chunks ----------------
__global__ void chunk_scan64(const float* __restrict__ states,
                             const float* __restrict__ cs,
                             float* __restrict__ prev) {
    const int seg = blockIdx.x, h = blockIdx.y, b = blockIdx.z;
    const int e = seg * 256 + threadIdx.x;   // 0..8191
    float P = 0.f;
    for (int c = 0; c < NC64; c++) {
        size_t base = ((size_t)b * NC64 + c) * NH + h;
        float sc = __expf(cs[base * TCH + TCH - 1]);
        size_t off = base * (size_t)(HD * DS) + e;
        prev[off] = P;
        P = fmaf(P, sc, states[off]);
    }
}

// ---------------- K3: Y += diag(exp(cs)) * C * prev^T on tensor cores ----------------
#define SM_K3_BYTES ((4 * 64 * SB_S) * 2 + 64 * 4)
__global__ __launch_bounds__(256, 1) void yoff64_kernel(
    const float* __restrict__ xbc, const float* __restrict__ prev,
    const float* __restrict__ cs, float* __restrict__ y) {
    extern __shared__ char smraw[];
    __nv_bfloat16* sCh = (__nv_bfloat16*)smraw;    // 64 x SB_S (t, n)
    __nv_bfloat16* sCl = sCh + 64 * SB_S;
    __nv_bfloat16* sPh = sCl + 64 * SB_S;          // 64 x SB_S (p, n)
    __nv_bfloat16* sPl = sPh + 64 * SB_S;
    float* sE = (float*)(sPl + 64 * SB_S);         // 64

    const int c = blockIdx.x, b = blockIdx.y;
    const int tid = threadIdx.x;
    const int wid = tid >> 5, lane = tid & 31;
    const int wm = wid >> 2, wn = wid & 3;
    const int grp = lane >> 2, q2 = (lane & 3) * 2;
    const int row0 = b * L_SEQ + c * TCH;
    const float* xrow = xbc + (size_t)row0 * CONVD;

    for (int idx = tid; idx < 64 * 128; idx += 256) {
        int t = idx >> 7, n = idx & 127;
        float cv = xrow[(size_t)t * CONVD + 2176 + n];
        __nv_bfloat16 ch, cl;
        bfsplit(cv, ch, cl);
        sCh[t * SB_S + n] = ch;
        sCl[t * SB_S + n] = cl;
    }

    for (int h = 0; h < NH; h++) {
        __syncthreads();   // prev head done
        if (tid < 64)
            sE[tid] = __expf(cs[(((size_t)b * NC64 + c) * NH + h) * TCH + tid]);
        size_t pbase = (((size_t)b * NC64 + c) * NH + h) * (size_t)(HD * DS);
        for (int idx = tid; idx < 64 * 128; idx += 256) {
            int p = idx >> 7, n = idx & 127;
            float pv = prev[pbase + (size_t)p * DS + n];
            __nv_bfloat16 ph, pl;
            bfsplit(pv, ph, pl);
            sPh[p * SB_S + n] = ph;
            sPl[p * SB_S + n] = pl;
        }
        __syncthreads();

        float acc[2][2][4];
#pragma unroll
        for (int i = 0; i < 2; i++)
#pragma unroll
            for (int j = 0; j < 2; j++)
#pragma unroll
                for (int r = 0; r < 4; r++) acc[i][j][r] = 0.f;
        for (int kb = 0; kb < 128; kb += 16) {
            uint32_t bh[2][2], bl[2][2];
#pragma unroll
            for (int nt = 0; nt < 2; nt++) {
                int c0 = wn * 16 + nt * 8 + grp;
                bh[nt][0] = *(const uint32_t*)&sPh[c0 * SB_S + kb + q2];
                bh[nt][1] = *(const uint32_t*)&sPh[c0 * SB_S + kb + q2 + 8];
                bl[nt][0] = *(const uint32_t*)&sPl[c0 * SB_S + kb + q2];
                bl[nt][1] = *(const uint32_t*)&sPl[c0 * SB_S + kb + q2 + 8];
            }
#pragma unroll
            for (int mt = 0; mt < 2; mt++) {
                int r0 = wm * 32 + mt * 16 + grp;
                uint32_t ah[4], al[4];
                ah[0] = *(const uint32_t*)&sCh[r0 * SB_S + kb + q2];
                ah[1] = *(const uint32_t*)&sCh[(r0 + 8) * SB_S + kb + q2];
                ah[2] = *(const uint32_t*)&sCh[r0 * SB_S + kb + q2 + 8];
                ah[3] = *(const uint32_t*)&sCh[(r0 + 8) * SB_S + kb + q2 + 8];
                al[0] = *(const uint32_t*)&sCl[r0 * SB_S + kb + q2];
                al[1] = *(const uint32_t*)&sCl[(r0 + 8) * SB_S + kb + q2];
                al[2] = *(const uint32_t*)&sCl[r0 * SB_S + kb + q2 + 8];
                al[3] = *(const uint32_t*)&sCl[(r0 + 8) * SB_S + kb + q2 + 8];
#pragma unroll
                for (int nt = 0; nt < 2; nt++) {
                    mma16816(acc[mt][nt], ah, bh[nt]);
                    mma16816(acc[mt][nt], ah, bl[nt]);
                    mma16816(acc[mt][nt], al, bh[nt]);
                }
            }
        }
#pragma unroll
        for (int mt = 0; mt < 2; mt++)
#pragma unroll
            for (int nt = 0; nt < 2; nt++) {
                int t0 = wm * 32 + mt * 16 + grp;
                int p0 = wn * 16 + nt * 8 + q2;
#pragma unroll
                for (int rr = 0; rr < 2; rr++) {
                    int t = t0 + rr * 8;
                    float e = sE[t];
                    size_t addr = (size_t)(row0 + t) * DSSM + h * 64 + p0;
                    float2 old = *(float2*)&y[addr];
                    old.x = fmaf(e, acc[mt][nt][rr * 2 + 0], old.x);
                    old.y = fmaf(e, acc[mt][nt][rr * 2 + 1], old.y);
                    *(float2*)&y[addr] = old;
                }
            }
    }
}

// ---------------- gate (y * silu(z)) + RMSNorm ----------------
__global__ void gate_norm_kernel(const float* __restrict__ zx,
                                 const float* __restrict__ y,
                                 const float* __restrict__ norm_w,
                                 float* __restrict__ yn) {
    const int row = blockIdx.x;
    const int tid = threadIdx.x;
    const float* yrow = y + (size_t)row * DSSM;
    const float* zrow = zx + (size_t)row * DIP;
    float v[8];
    float ss = 0.f;
#pragma unroll
    for (int k = 0; k < 8; k++) {
        int e = tid + k * 256;
        float z = zrow[e];
        float vv = yrow[e] * (z * fast_sigmoid(z));
        v[k] = vv;
        ss = fmaf(vv, vv, ss);
    }
    __shared__ float red[256];
    red[tid] = ss;
    __syncthreads();
    for (int s = 128; s > 0; s >>= 1) {
        if (tid < s) red[tid] += red[tid + s];
        __syncthreads();
    }
    float r = rsqrtf(red[0] / (float)DSSM + 1e-5f);
#pragma unroll
    for (int k = 0; k < 8; k++) {
        int e = tid + k * 256;
        yn[(size_t)row * DSSM + e] = v[k] * r * norm_w[e];
    }
}

// ---------------- host launch ----------------
extern "C" void kernel_launch(void* const* d_in, const int* in_sizes, int n_in,
                              void* d_out, int out_size) {
    const float* u       = (const float*)d_in[0];
    const float* W_in    = (const float*)d_in[1];
    const float* conv_w  = (const float*)d_in[2];
    const float* conv_b  = (const float*)d_in[3];
    const float* dt_bias = (const float*)d_in[4];
    const float* A_log   = (const float*)d_in[5];
    const float* Dv      = (const float*)d_in[6];
    const float* norm_w  = (const float*)d_in[7];
    const float* W_out   = (const float*)d_in[8];
    float* out = (float*)d_out;

    void *p_zx, *p_xbc, *p_y, *p_yn, *p_states, *p_prev, *p_cs;
    void *p_uh, *p_ul, *p_wih, *p_wil, *p_ynh, *p_ynl, *p_woh, *p_wol;
    cudaGetSymbolAddress(&p_zx, g_zx);
    cudaGetSymbolAddress(&p_xbc, g_xbc);
    cudaGetSymbolAddress(&p_y, g_y);
    cudaGetSymbolAddress(&p_yn, g_yn);
    cudaGetSymbolAddress(&p_states, g_states);
    cudaGetSymbolAddress(&p_prev, g_prev);
    cudaGetSymbolAddress(&p_cs, g_cs);
    cudaGetSymbolAddress(&p_uh, g_uh);
    cudaGetSymbolAddress(&p_ul, g_ul);
    cudaGetSymbolAddress(&p_wih, g_wih);
    cudaGetSymbolAddress(&p_wil, g_wil);
    cudaGetSymbolAddress(&p_ynh, g_ynh);
    cudaGetSymbolAddress(&p_ynl, g_ynl);
    cudaGetSymbolAddress(&p_woh, g_woh);
    cudaGetSymbolAddress(&p_wol, g_wol);
    float* zx = (float*)p_zx;
    float* xbc = (float*)p_xbc;
    float* y = (float*)p_y;
    float* yn = (float*)p_yn;
    float* states = (float*)p_states;
    float* prev = (float*)p_prev;
    float* cs = (float*)p_cs;
    __nv_bfloat16* uh = (__nv_bfloat16*)p_uh;
    __nv_bfloat16* ul = (__nv_bfloat16*)p_ul;
    __nv_bfloat16* wih = (__nv_bfloat16*)p_wih;
    __nv_bfloat16* wil = (__nv_bfloat16*)p_wil;
    __nv_bfloat16* ynh = (__nv_bfloat16*)p_ynh;
    __nv_bfloat16* ynl = (__nv_bfloat16*)p_ynl;
    __nv_bfloat16* woh = (__nv_bfloat16*)p_woh;
    __nv_bfloat16* wol = (__nv_bfloat16*)p_wol;

    cudaFuncSetAttribute(gemm_nt_bf16x3, cudaFuncAttributeMaxDynamicSharedMemorySize,
                         GEMM_SMEM);
    cudaFuncSetAttribute(ssm_intra_kernel, cudaFuncAttributeMaxDynamicSharedMemorySize,
                         SM_K1_BYTES);
    cudaFuncSetAttribute(yoff64_kernel, cudaFuncAttributeMaxDynamicSharedMemorySize,
                         SM_K3_BYTES);

    // 0. split inputs to bf16 hi/lo
    {
        int n4 = MROWS * D_MODEL / 4;
        split_bf16_kernel<<<(n4 + 255) / 256, 256>>>(u, uh, ul, n4);
        n4 = DIP * D_MODEL / 4;
        split_bf16_kernel<<<(n4 + 255) / 256, 256>>>(W_in, wih, wil, n4);
        n4 = D_MODEL * DSSM / 4;
        split_bf16_kernel<<<(n4 + 255) / 256, 256>>>(W_out, woh, wol, n4);
    }

    // 1. in_proj
    gemm_nt_bf16x3<<<dim3((DIP + 127) / 128, MROWS / 128), 256, GEMM_SMEM>>>(
        uh, ul, wih, wil, zx, MROWS, DIP, D_MODEL);

    // 2. conv1d + silu
    {
        size_t total = (size_t)MROWS * CONVD;
        conv_silu_kernel<<<(unsigned)((total + 255) / 256), 256>>>(zx, conv_w, conv_b, xbc);
    }

    // 3. intra-chunk SSM (tensor cores)
    ssm_intra_kernel<<<dim3(NC64, BATCH), 256, SM_K1_BYTES>>>(
        zx, xbc, dt_bias, A_log, Dv, y, states, cs);

    // 4. inter-chunk recurrence
    chunk_scan64<<<dim3(32, NH, BATCH), 256>>>(states, cs, prev);

    // 5. Y_off (tensor cores)
    yoff64_kernel<<<dim3(NC64, BATCH), 256, SM_K3_BYTES>>>(xbc, prev, cs, y);

    // 6. gate + RMSNorm
    gate_norm_kernel<<<MROWS, 256>>>(zx, y, norm_w, yn);

    // 7. out_proj
    {
        int n4 = MROWS * DSSM / 4;
        split_bf16_kernel<<<(n4 + 255) / 256, 256>>>(yn, ynh, ynl, n4);
    }
    gemm_nt_bf16x3<<<dim3(D_MODEL / 128, MROWS / 128), 256, GEMM_SMEM>>>(
        ynh, ynl, woh, wol, out, MROWS, D_MODEL, DSSM);
}

// round 5
// speedup vs baseline: 2.0176x; 1.0155x over previous
#include <cuda_runtime.h>
#include <cuda_bf16.h>
#include <math.h>
#include <stdint.h>

#define BATCH 2
#define L_SEQ 4096
#define D_MODEL 1024
#define DIP 4384          // D_IN_PROJ
#define DSSM 2048
#define CONVD 2304        // CONV_DIM
#define NH 32
#define HD 64
#define DS 128
#define NC64 64           // chunks of 64 per batch
#define TCH 64            // tile length
#define MROWS (BATCH * L_SEQ)   // 8192

// ---------------- scratch (device globals; no allocation) ----------------
__device__ float g_zx[(size_t)MROWS * DIP];
__device__ float g_xbc[(size_t)MROWS * CONVD];
__device__ float g_y[(size_t)MROWS * DSSM];
__device__ float g_yn[(size_t)MROWS * DSSM];
__device__ float g_states[(size_t)BATCH * NC64 * NH * HD * DS];
__device__ float g_prev[(size_t)BATCH * NC64 * NH * HD * DS];
__device__ float g_cs[(size_t)BATCH * NC64 * NH * TCH];

// bf16 hi/lo split buffers for projection GEMMs
__device__ __nv_bfloat16 g_uh[(size_t)MROWS * D_MODEL];
__device__ __nv_bfloat16 g_ul[(size_t)MROWS * D_MODEL];
__device__ __nv_bfloat16 g_wih[(size_t)DIP * D_MODEL];
__device__ __nv_bfloat16 g_wil[(size_t)DIP * D_MODEL];
__device__ __nv_bfloat16 g_ynh[(size_t)MROWS * DSSM];
__device__ __nv_bfloat16 g_ynl[(size_t)MROWS * DSSM];
__device__ __nv_bfloat16 g_woh[(size_t)D_MODEL * DSSM];
__device__ __nv_bfloat16 g_wol[(size_t)D_MODEL * DSSM];

// ---------------- helpers ----------------
struct alignas(8) bf16x4 { __nv_bfloat16 a, b, c, d; };

__device__ __forceinline__ float fast_sigmoid(float x) {
    return 1.f / (1.f + __expf(-x));
}

__device__ __forceinline__ void mma16816(float* d, const uint32_t* a, const uint32_t* b) {
    asm volatile(
        "mma.sync.aligned.m16n8k16.row.col.f32.bf16.bf16.f32 "
        "{%0,%1,%2,%3}, {%4,%5,%6,%7}, {%8,%9}, {%0,%1,%2,%3};"
        : "+f"(d[0]), "+f"(d[1]), "+f"(d[2]), "+f"(d[3])
        : "r"(a[0]), "r"(a[1]), "r"(a[2]), "r"(a[3]), "r"(b[0]), "r"(b[1]));
}

__device__ __forceinline__ void ldsm_x4(uint32_t& r0, uint32_t& r1, uint32_t& r2,
                                        uint32_t& r3, uint32_t addr) {
    asm volatile("ldmatrix.sync.aligned.m8n8.x4.shared.b16 {%0,%1,%2,%3}, [%4];"
                 : "=r"(r0), "=r"(r1), "=r"(r2), "=r"(r3) : "r"(addr));
}

__device__ __forceinline__ void bfsplit(float v, __nv_bfloat16& h, __nv_bfloat16& l) {
    h = __float2bfloat16(v);
    l = __float2bfloat16(v - __bfloat162float(h));
}

// ---------------- fp32 -> bf16 hi/lo split ----------------
__global__ void split_bf16_kernel(const float* __restrict__ x,
                                  __nv_bfloat16* __restrict__ hi,
                                  __nv_bfloat16* __restrict__ lo, int n4) {
    int i = blockIdx.x * 256 + threadIdx.x;
    if (i >= n4) return;
    float4 v = ((const float4*)x)[i];
    __nv_bfloat16 h0, h1, h2, h3, l0, l1, l2, l3;
    bfsplit(v.x, h0, l0); bfsplit(v.y, h1, l1);
    bfsplit(v.z, h2, l2); bfsplit(v.w, h3, l3);
    bf16x4 hv = {h0, h1, h2, h3};
    bf16x4 lv = {l0, l1, l2, l3};
    ((bf16x4*)hi)[i] = hv;
    ((bf16x4*)lo)[i] = lv;
}

// ---------------- tensor-core GEMM: C[M,N] = A[M,K] * B[N,K]^T (hi/lo x3) ----------------
// ldmatrix fragment loads; 128x128 block, 8 warps, k-step 16, double buffered.
#define GK 16
#define GPAD 24
#define GEMM_SMEM (2 * 2 * 128 * GPAD * 2 * 2)  // 49152 bytes

__global__ __launch_bounds__(256, 2) void gemm_nt_bf16x3(
    const __nv_bfloat16* __restrict__ Ah, const __nv_bfloat16* __restrict__ Al,
    const __nv_bfloat16* __restrict__ Bh, const __nv_bfloat16* __restrict__ Bl,
    float* __restrict__ C, int M, int N, int K) {
    extern __shared__ __nv_bfloat16 smb[];
    __nv_bfloat16* sA = smb;
    __nv_bfloat16* sB = smb + 2 * 2 * 128 * GPAD;

    const int tid = threadIdx.x;
    const int wid = tid >> 5, lane = tid & 31;
    const int wm = wid >> 2, wn = wid & 3;
    const int grp = lane >> 2, q2 = (lane & 3) * 2;
    const int rowBase = blockIdx.y * 128;
    const int colBase = blockIdx.x * 128;
    const int lrow = tid >> 1;
    const int lkh = (tid & 1) * 8;

    // ldmatrix per-lane source row/col inside a 16x16 tile
    const int lmRow = lane & 15;            // row 0..15
    const int lmK = (lane >> 4) << 3;       // 0 or 8

    const uint32_t sA_s = (uint32_t)__cvta_generic_to_shared(sA);
    const uint32_t sB_s = (uint32_t)__cvta_generic_to_shared(sB);

    float acc[4][4][4];
#pragma unroll
    for (int i = 0; i < 4; i++)
#pragma unroll
        for (int j = 0; j < 4; j++)
#pragma unroll
            for (int r = 0; r < 4; r++) acc[i][j][r] = 0.f;

    const int nk = K / GK;
#define SAIDX(st, hl, r, k) (((((st) * 2 + (hl)) * 128 + (r)) * GPAD) + (k))
    auto load_stage = [&](int st, int k0) {
        *(float4*)&sA[SAIDX(st, 0, lrow, lkh)] =
            *(const float4*)&Ah[(size_t)(rowBase + lrow) * K + k0 + lkh];
        *(float4*)&sA[SAIDX(st, 1, lrow, lkh)] =
            *(const float4*)&Al[(size_t)(rowBase + lrow) * K + k0 + lkh];
        int cn = colBase + lrow;
        float4 z = make_float4(0.f, 0.f, 0.f, 0.f);
        float4 bh = z, bl = z;
        if (cn < N) {
            bh = *(const float4*)&Bh[(size_t)cn * K + k0 + lkh];
            bl = *(const float4*)&Bl[(size_t)cn * K + k0 + lkh];
        }
        *(float4*)&sB[SAIDX(st, 0, lrow, lkh)] = bh;
        *(float4*)&sB[SAIDX(st, 1, lrow, lkh)] = bl;
    };

    load_stage(0, 0);
    __syncthreads();

    for (int ks = 0; ks < nk; ks++) {
        int st = ks & 1;
        if (ks + 1 < nk) load_stage(st ^ 1, (ks + 1) * GK);

        // ---- B fragments via ldmatrix: two x4 per hi/lo (16 n-cols each) ----
        uint32_t bh[4][2], bl[4][2];
        {
            uint32_t r0, r1, r2, r3;
            // hi, n-cols wn*32 .. +15
            ldsm_x4(r0, r1, r2, r3,
                    sB_s + SAIDX(st, 0, wn * 32 + lmRow, lmK) * 2);
            bh[0][0] = r0; bh[0][1] = r2; bh[1][0] = r1; bh[1][1] = r3;
            // hi, n-cols wn*32+16 .. +31
            ldsm_x4(r0, r1, r2, r3,
                    sB_s + SAIDX(st, 0, wn * 32 + 16 + lmRow, lmK) * 2);
            bh[2][0] = r0; bh[2][1] = r2; bh[3][0] = r1; bh[3][1] = r3;
            // lo
            ldsm_x4(r0, r1, r2, r3,
                    sB_s + SAIDX(st, 1, wn * 32 + lmRow, lmK) * 2);
            bl[0][0] = r0; bl[0][1] = r2; bl[1][0] = r1; bl[1][1] = r3;
            ldsm_x4(r0, r1, r2, r3,
                    sB_s + SAIDX(st, 1, wn * 32 + 16 + lmRow, lmK) * 2);
            bl[2][0] = r0; bl[2][1] = r2; bl[3][0] = r1; bl[3][1] = r3;
        }
#pragma unroll
        for (int mt = 0; mt < 4; mt++) {
            int r0row = wm * 64 + mt * 16;
            uint32_t ah[4], al[4];
            ldsm_x4(ah[0], ah[1], ah[2], ah[3],
                    sA_s + SAIDX(st, 0, r0row + lmRow, lmK) * 2);
            ldsm_x4(al[0], al[1], al[2], al[3],
                    sA_s + SAIDX(st, 1, r0row + lmRow, lmK) * 2);
#pragma unroll
            for (int nt = 0; nt < 4; nt++) {
                mma16816(acc[mt][nt], ah, bh[nt]);
                mma16816(acc[mt][nt], ah, bl[nt]);
                mma16816(acc[mt][nt], al, bh[nt]);
            }
        }
        __syncthreads();
    }
#pragma unroll
    for (int mt = 0; mt < 4; mt++) {
#pragma unroll
        for (int nt = 0; nt < 4; nt++) {
            int colTile = colBase + wn * 32 + nt * 8;
            if (colTile >= N) continue;
            int r0 = rowBase + wm * 64 + mt * 16 + grp;
            int c0 = colTile + q2;
            *(float2*)&C[(size_t)r0 * N + c0] = make_float2(acc[mt][nt][0], acc[mt][nt][1]);
            *(float2*)&C[(size_t)(r0 + 8) * N + c0] = make_float2(acc[mt][nt][2], acc[mt][nt][3]);
        }
    }
#undef SAIDX
}

// ---------------- conv1d (causal, depthwise, width 4) + SiLU ----------------
__global__ void conv_silu_kernel(const float* __restrict__ zx,
                                 const float* __restrict__ conv_w,
                                 const float* __restrict__ conv_b,
                                 float* __restrict__ xbc) {
    size_t idx = (size_t)blockIdx.x * 256 + threadIdx.x;
    const size_t total = (size_t)MROWS * CONVD;
    if (idx >= total) return;
    int cc = (int)(idx % CONVD);
    size_t bt = idx / CONVD;
    int t = (int)(bt % L_SEQ);
    float acc = conv_b[cc];
#pragma unroll
    for (int k = 0; k < 4; k++) {
        int tt = t - 3 + k;
        if (tt >= 0)
            acc = fmaf(zx[(bt - t + tt) * DIP + 2048 + cc], conv_w[cc * 4 + k], acc);
    }
    xbc[idx] = acc * fast_sigmoid(acc);
}

// ---------------- K1: intra-chunk SSM on tensor cores ----------------
#define SB_S 136
#define ST_S 66
#define SM_K1_BYTES ((4 * 64 * SB_S + 2 * 128 * ST_S + 6 * 64 * ST_S) * 2 + \
                     (64 * ST_S + 2 * 32 * 64 + 64) * 4)

__global__ __launch_bounds__(256, 1) void ssm_intra_kernel(
    const float* __restrict__ zx, const float* __restrict__ xbc,
    const float* __restrict__ dt_bias, const float* __restrict__ A_log,
    const float* __restrict__ Dvec,
    float* __restrict__ y, float* __restrict__ states, float* __restrict__ cs_out) {
    extern __shared__ char smraw[];
    __nv_bfloat16* sBh = (__nv_bfloat16*)smraw;
    __nv_bfloat16* sBl = sBh + 64 * SB_S;
    __nv_bfloat16* sCh = sBl + 64 * SB_S;
    __nv_bfloat16* sCl = sCh + 64 * SB_S;
    __nv_bfloat16* sBTh = sCl + 64 * SB_S;
    __nv_bfloat16* sBTl = sBTh + 128 * ST_S;
    __nv_bfloat16* sGh = sBTl + 128 * ST_S;
    __nv_bfloat16* sGl = sGh + 64 * ST_S;
    __nv_bfloat16* sXh = sGl + 64 * ST_S;
    __nv_bfloat16* sXl = sXh + 64 * ST_S;
    __nv_bfloat16* sXdh = sXl + 64 * ST_S;
    __nv_bfloat16* sXdl = sXdh + 64 * ST_S;
    float* sG = (float*)(sXdl + 64 * ST_S);
    float* s_dt = sG + 64 * ST_S;
    float* s_cs = s_dt + 32 * 64;
    float* sEd = s_cs + 32 * 64;

    const int c = blockIdx.x, b = blockIdx.y;
    const int tid = threadIdx.x;
    const int wid = tid >> 5, lane = tid & 31;
    const int wm = wid >> 2, wn = wid & 3;
    const int grp = lane >> 2, q2 = (lane & 3) * 2;
    const int row0 = b * L_SEQ + c * TCH;
    const float* xrow = xbc + (size_t)row0 * CONVD;

    for (int hh = 0; hh < 4; hh++) {
        int h = wid * 4 + hh;
        float Ah = -__expf(A_log[h]);
        float bias = dt_bias[h];
        float d0 = zx[(size_t)(row0 + lane) * DIP + 4352 + h] + bias;
        float d1 = zx[(size_t)(row0 + 32 + lane) * DIP + 4352 + h] + bias;
        float dt0 = (d0 > 20.f) ? d0 : log1pf(__expf(d0));
        float dt1 = (d1 > 20.f) ? d1 : log1pf(__expf(d1));
        s_dt[h * 64 + lane] = dt0;
        s_dt[h * 64 + 32 + lane] = dt1;
        float v0 = dt0 * Ah, v1 = dt1 * Ah;
#pragma unroll
        for (int off = 1; off < 32; off <<= 1) {
            float n0 = __shfl_up_sync(0xffffffffu, v0, off);
            float n1 = __shfl_up_sync(0xffffffffu, v1, off);
            if (lane >= off) { v0 += n0; v1 += n1; }
        }
        v1 += __shfl_sync(0xffffffffu, v0, 31);
        s_cs[h * 64 + lane] = v0;
        s_cs[h * 64 + 32 + lane] = v1;
        size_t cbase = (((size_t)b * NC64 + c) * NH + h) * TCH;
        cs_out[cbase + lane] = v0;
        cs_out[cbase + 32 + lane] = v1;
    }

    for (int idx = tid; idx < 64 * 128; idx += 256) {
        int s = idx >> 7, n = idx & 127;
        float bv = xrow[(size_t)s * CONVD + 2048 + n];
        float cv = xrow[(size_t)s * CONVD + 2176 + n];
        __nv_bfloat16 bh, bl, ch, cl;
        bfsplit(bv, bh, bl);
        bfsplit(cv, ch, cl);
        sBh[s * SB_S + n] = bh; sBl[s * SB_S + n] = bl;
        sCh[s * SB_S + n] = ch; sCl[s * SB_S + n] = cl;
        sBTh[n * ST_S + s] = bh; sBTl[n * ST_S + s] = bl;
    }
    __syncthreads();

    {
        float g[2][2][4];
#pragma unroll
        for (int i = 0; i < 2; i++)
#pragma unroll
            for (int j = 0; j < 2; j++)
#pragma unroll
                for (int r = 0; r < 4; r++) g[i][j][r] = 0.f;
        for (int kb = 0; kb < 128; kb += 16) {
            uint32_t bh[2][2], bl[2][2];
#pragma unroll
            for (int nt = 0; nt < 2; nt++) {
                int c0 = wn * 16 + nt * 8 + grp;
                bh[nt][0] = *(const uint32_t*)&sBh[c0 * SB_S + kb + q2];
                bh[nt][1] = *(const uint32_t*)&sBh[c0 * SB_S + kb + q2 + 8];
                bl[nt][0] = *(const uint32_t*)&sBl[c0 * SB_S + kb + q2];
                bl[nt][1] = *(const uint32_t*)&sBl[c0 * SB_S + kb + q2 + 8];
            }
#pragma unroll
            for (int mt = 0; mt < 2; mt++) {
                int r0 = wm * 32 + mt * 16 + grp;
                uint32_t ah[4], al[4];
                ah[0] = *(const uint32_t*)&sCh[r0 * SB_S + kb + q2];
                ah[1] = *(const uint32_t*)&sCh[(r0 + 8) * SB_S + kb + q2];
                ah[2] = *(const uint32_t*)&sCh[r0 * SB_S + kb + q2 + 8];
                ah[3] = *(const uint32_t*)&sCh[(r0 + 8) * SB_S + kb + q2 + 8];
                al[0] = *(const uint32_t*)&sCl[r0 * SB_S + kb + q2];
                al[1] = *(const uint32_t*)&sCl[(r0 + 8) * SB_S + kb + q2];
                al[2] = *(const uint32_t*)&sCl[r0 * SB_S + kb + q2 + 8];
                al[3] = *(const uint32_t*)&sCl[(r0 + 8) * SB_S + kb + q2 + 8];
#pragma unroll
                for (int nt = 0; nt < 2; nt++) {
                    mma16816(g[mt][nt], ah, bh[nt]);
                    mma16816(g[mt][nt], ah, bl[nt]);
                    mma16816(g[mt][nt], al, bh[nt]);
                }
            }
        }
#pragma unroll
        for (int mt = 0; mt < 2; mt++)
#pragma unroll
            for (int nt = 0; nt < 2; nt++) {
                int t = wm * 32 + mt * 16 + grp;
                int s = wn * 16 + nt * 8 + q2;
                *(float2*)&sG[t * ST_S + s] = make_float2(g[mt][nt][0], g[mt][nt][1]);
                *(float2*)&sG[(t + 8) * ST_S + s] = make_float2(g[mt][nt][2], g[mt][nt][3]);
            }
    }

    for (int h = 0; h < NH; h++) {
        __syncthreads();
        const float* csh = s_cs + h * 64;
        const float* dth = s_dt + h * 64;
        const float csL = csh[63];
        if (tid < 64) sEd[tid] = __expf(csL - csh[tid]);
        for (int idx = tid; idx < 64 * 64; idx += 256) {
            int t = idx >> 6, s = idx & 63;
            float val = 0.f;
            if (t >= s) val = sG[t * ST_S + s] * __expf(csh[t] - csh[s]);
            __nv_bfloat16 hch, hcl;
            bfsplit(val, hch, hcl);
            sGh[t * ST_S + s] = hch;
            sGl[t * ST_S + s] = hcl;
        }
        __syncthreads();
        for (int idx = tid; idx < 64 * 64; idx += 256) {
            int s = idx >> 6, p = idx & 63;
            float xv = xrow[(size_t)s * CONVD + h * 64 + p];
            float xt = xv * dth[s];
            __nv_bfloat16 xh, xl, xdh, xdl;
            bfsplit(xt, xh, xl);
            bfsplit(xt * sEd[s], xdh, xdl);
            sXh[p * ST_S + s] = xh;  sXl[p * ST_S + s] = xl;
            sXdh[p * ST_S + s] = xdh; sXdl[p * ST_S + s] = xdl;
        }
        __syncthreads();

        {
            float yd[2][2][4];
#pragma unroll
            for (int i = 0; i < 2; i++)
#pragma unroll
                for (int j = 0; j < 2; j++)
#pragma unroll
                    for (int r = 0; r < 4; r++) yd[i][j][r] = 0.f;
            for (int kb = 0; kb < 64; kb += 16) {
                uint32_t bh[2][2], bl[2][2];
#pragma unroll
                for (int nt = 0; nt < 2; nt++) {
                    int c0 = wn * 16 + nt * 8 + grp;
                    bh[nt][0] = *(const uint32_t*)&sXh[c0 * ST_S + kb + q2];
                    bh[nt][1] = *(const uint32_t*)&sXh[c0 * ST_S + kb + q2 + 8];
                    bl[nt][0] = *(const uint32_t*)&sXl[c0 * ST_S + kb + q2];
                    bl[nt][1] = *(const uint32_t*)&sXl[c0 * ST_S + kb + q2 + 8];
                }
#pragma unroll
                for (int mt = 0; mt < 2; mt++) {
                    int r0 = wm * 32 + mt * 16 + grp;
                    uint32_t ah[4], al[4];
                    ah[0] = *(const uint32_t*)&sGh[r0 * ST_S + kb + q2];
                    ah[1] = *(const uint32_t*)&sGh[(r0 + 8) * ST_S + kb + q2];
                    ah[2] = *(const uint32_t*)&sGh[r0 * ST_S + kb + q2 + 8];
                    ah[3] = *(const uint32_t*)&sGh[(r0 + 8) * ST_S + kb + q2 + 8];
                    al[0] = *(const uint32_t*)&sGl[r0 * ST_S + kb + q2];
                    al[1] = *(const uint32_t*)&sGl[(r0 + 8) * ST_S + kb + q2];
                    al[2] = *(const uint32_t*)&sGl[r0 * ST_S + kb + q2 + 8];
                    al[3] = *(const uint32_t*)&sGl[(r0 + 8) * ST_S + kb + q2 + 8];
#pragma unroll
                    for (int nt = 0; nt < 2; nt++) {
                        mma16816(yd[mt][nt], ah, bh[nt]);
                        mma16816(yd[mt][nt], ah, bl[nt]);
                        mma16816(yd[mt][nt], al, bh[nt]);
                    }
                }
            }
            float Dh = Dvec[h];
#pragma unroll
            for (int mt = 0; mt < 2; mt++)
#pragma unroll
                for (int nt = 0; nt < 2; nt++) {
                    int t0 = wm * 32 + mt * 16 + grp;
                    int p0 = wn * 16 + nt * 8 + q2;
#pragma unroll
                    for (int rr = 0; rr < 2; rr++) {
                        int t = t0 + rr * 8;
                        float2 xv = *(const float2*)&xrow[(size_t)t * CONVD + h * 64 + p0];
                        float2 o;
                        o.x = fmaf(Dh, xv.x, yd[mt][nt][rr * 2 + 0]);
                        o.y = fmaf(Dh, xv.y, yd[mt][nt][rr * 2 + 1]);
                        *(float2*)&g_y[(size_t)(row0 + t) * DSSM + h * 64 + p0] = o;
                    }
                }
        }

        {
            float st[2][4][4];
#pragma unroll
            for (int i = 0; i < 2; i++)
#pragma unroll
                for (int j = 0; j < 4; j++)
#pragma unroll
                    for (int r = 0; r < 4; r++) st[i][j][r] = 0.f;
            for (int kb = 0; kb < 64; kb += 16) {
                uint32_t bh[4][2], bl[4][2];
#pragma unroll
                for (int nt = 0; nt < 4; nt++) {
                    int c0 = wn * 32 + nt * 8 + grp;
                    bh[nt][0] = *(const uint32_t*)&sBTh[c0 * ST_S + kb + q2];
                    bh[nt][1] = *(const uint32_t*)&sBTh[c0 * ST_S + kb + q2 + 8];
                    bl[nt][0] = *(const uint32_t*)&sBTl[c0 * ST_S + kb + q2];
                    bl[nt][1] = *(const uint32_t*)&sBTl[c0 * ST_S + kb + q2 + 8];
                }
#pragma unroll
                for (int mt = 0; mt < 2; mt++) {
                    int r0 = wm * 32 + mt * 16 + grp;
                    uint32_t ah[4], al[4];
                    ah[0] = *(const uint32_t*)&sXdh[r0 * ST_S + kb + q2];
                    ah[1] = *(const uint32_t*)&sXdh[(r0 + 8) * ST_S + kb + q2];
                    ah[2] = *(const uint32_t*)&sXdh[r0 * ST_S + kb + q2 + 8];
                    ah[3] = *(const uint32_t*)&sXdh[(r0 + 8) * ST_S + kb + q2 + 8];
                    al[0] = *(const uint32_t*)&sXdl[r0 * ST_S + kb + q2];
                    al[1] = *(const uint32_t*)&sXdl[(r0 + 8) * ST_S + kb + q2];
                    al[2] = *(const uint32_t*)&sXdl[r0 * ST_S + kb + q2 + 8];
                    al[3] = *(const uint32_t*)&sXdl[(r0 + 8) * ST_S + kb + q2 + 8];
#pragma unroll
                    for (int nt = 0; nt < 4; nt++) {
                        mma16816(st[mt][nt], ah, bh[nt]);
                        mma16816(st[mt][nt], ah, bl[nt]);
                        mma16816(st[mt][nt], al, bh[nt]);
                    }
                }
            }
            size_t sbase = (((size_t)b * NC64 + c) * NH + h) * (size_t)(HD * DS);
#pragma unroll
            for (int mt = 0; mt < 2; mt++)
#pragma unroll
                for (int nt = 0; nt < 4; nt++) {
                    int p0 = wm * 32 + mt * 16 + grp;
                    int n0 = wn * 32 + nt * 8 + q2;
                    *(float2*)&states[sbase + (size_t)p0 * DS + n0] =
                        make_float2(st[mt][nt][0], st[mt][nt][1]);
                    *(float2*)&states[sbase + (size_t)(p0 + 8) * DS + n0] =
                        make_float2(st[mt][nt][2], st[mt][nt][3]);
                }
        }
    }
}

// ---------------- K2: inter-chunk recurrence over 64 chunks ----------------
__global__ void chunk_scan64(const float* __restrict__ states,
                             const float* __restrict__ cs,
                             float* __restrict__ prev) {
    const int seg = blockIdx.x, h = blockIdx.y, b = blockIdx.z;
    const int e = seg * 256 + threadIdx.x;
    float P = 0.f;
    for (int c = 0; c < NC64; c++) {
        size_t base = ((size_t)b * NC64 + c) * NH + h;
        float sc = __expf(cs[base * TCH + TCH - 1]);
        size_t off = base * (size_t)(HD * DS) + e;
        prev[off] = P;
        P = fmaf(P, sc, states[off]);
    }
}

// ---------------- K3: Y += diag(exp(cs)) * C * prev^T on tensor cores ----------------
#define SM_K3_BYTES ((4 * 64 * SB_S) * 2 + 64 * 4)
__global__ __launch_bounds__(256, 1) void yoff64_kernel(
    const float* __restrict__ xbc, const float* __restrict__ prev,
    const float* __restrict__ cs, float* __restrict__ y) {
    extern __shared__ char smraw[];
    __nv_bfloat16* sCh = (__nv_bfloat16*)smraw;
    __nv_bfloat16* sCl = sCh + 64 * SB_S;
    __nv_bfloat16* sPh = sCl + 64 * SB_S;
    __nv_bfloat16* sPl = sPh + 64 * SB_S;
    float* sE = (float*)(sPl + 64 * SB_S);

    const int c = blockIdx.x, b = blockIdx.y;
    const int tid = threadIdx.x;
    const int wid = tid >> 5, lane = tid & 31;
    const int wm = wid >> 2, wn = wid & 3;
    const int grp = lane >> 2, q2 = (lane & 3) * 2;
    const int row0 = b * L_SEQ + c * TCH;
    const float* xrow = xbc + (size_t)row0 * CONVD;

    for (int idx = tid; idx < 64 * 128; idx += 256) {
        int t = idx >> 7, n = idx & 127;
        float cv = xrow[(size_t)t * CONVD + 2176 + n];
        __nv_bfloat16 ch, cl;
        bfsplit(cv, ch, cl);
        sCh[t * SB_S + n] = ch;
        sCl[t * SB_S + n] = cl;
    }

    for (int h = 0; h < NH; h++) {
        __syncthreads();
        if (tid < 64)
            sE[tid] = __expf(cs[(((size_t)b * NC64 + c) * NH + h) * TCH + tid]);
        size_t pbase = (((size_t)b * NC64 + c) * NH + h) * (size_t)(HD * DS);
        for (int idx = tid; idx < 64 * 128; idx += 256) {
            int p = idx >> 7, n = idx & 127;
            float pv = prev[pbase + (size_t)p * DS + n];
            __nv_bfloat16 ph, pl;
            bfsplit(pv, ph, pl);
            sPh[p * SB_S + n] = ph;
            sPl[p * SB_S + n] = pl;
        }
        __syncthreads();

        float acc[2][2][4];
#pragma unroll
        for (int i = 0; i < 2; i++)
#pragma unroll
            for (int j = 0; j < 2; j++)
#pragma unroll
                for (int r = 0; r < 4; r++) acc[i][j][r] = 0.f;
        for (int kb = 0; kb < 128; kb += 16) {
            uint32_t bh[2][2], bl[2][2];
#pragma unroll
            for (int nt = 0; nt < 2; nt++) {
                int c0 = wn * 16 + nt * 8 + grp;
                bh[nt][0] = *(const uint32_t*)&sPh[c0 * SB_S + kb + q2];
                bh[nt][1] = *(const uint32_t*)&sPh[c0 * SB_S + kb + q2 + 8];
                bl[nt][0] = *(const uint32_t*)&sPl[c0 * SB_S + kb + q2];
                bl[nt][1] = *(const uint32_t*)&sPl[c0 * SB_S + kb + q2 + 8];
            }
#pragma unroll
            for (int mt = 0; mt < 2; mt++) {
                int r0 = wm * 32 + mt * 16 + grp;
                uint32_t ah[4], al[4];
                ah[0] = *(const uint32_t*)&sCh[r0 * SB_S + kb + q2];
                ah[1] = *(const uint32_t*)&sCh[(r0 + 8) * SB_S + kb + q2];
                ah[2] = *(const uint32_t*)&sCh[r0 * SB_S + kb + q2 + 8];
                ah[3] = *(const uint32_t*)&sCh[(r0 + 8) * SB_S + kb + q2 + 8];
                al[0] = *(const uint32_t*)&sCl[r0 * SB_S + kb + q2];
                al[1] = *(const uint32_t*)&sCl[(r0 + 8) * SB_S + kb + q2];
                al[2] = *(const uint32_t*)&sCl[r0 * SB_S + kb + q2 + 8];
                al[3] = *(const uint32_t*)&sCl[(r0 + 8) * SB_S + kb + q2 + 8];
#pragma unroll
                for (int nt = 0; nt < 2; nt++) {
                    mma16816(acc[mt][nt], ah, bh[nt]);
                    mma16816(acc[mt][nt], ah, bl[nt]);
                    mma16816(acc[mt][nt], al, bh[nt]);
                }
            }
        }
#pragma unroll
        for (int mt = 0; mt < 2; mt++)
#pragma unroll
            for (int nt = 0; nt < 2; nt++) {
                int t0 = wm * 32 + mt * 16 + grp;
                int p0 = wn * 16 + nt * 8 + q2;
#pragma unroll
                for (int rr = 0; rr < 2; rr++) {
                    int t = t0 + rr * 8;
                    float e = sE[t];
                    size_t addr = (size_t)(row0 + t) * DSSM + h * 64 + p0;
                    float2 old = *(float2*)&y[addr];
                    old.x = fmaf(e, acc[mt][nt][rr * 2 + 0], old.x);
                    old.y = fmaf(e, acc[mt][nt][rr * 2 + 1], old.y);
                    *(float2*)&y[addr] = old;
                }
            }
    }
}

// ---------------- gate (y * silu(z)) + RMSNorm ----------------
__global__ void gate_norm_kernel(const float* __restrict__ zx,
                                 const float* __restrict__ y,
                                 const float* __restrict__ norm_w,
                                 float* __restrict__ yn) {
    const int row = blockIdx.x;
    const int tid = threadIdx.x;
    const float* yrow = y + (size_t)row * DSSM;
    const float* zrow = zx + (size_t)row * DIP;
    float v[8];
    float ss = 0.f;
#pragma unroll
    for (int k = 0; k < 8; k++) {
        int e = tid + k * 256;
        float z = zrow[e];
        float vv = yrow[e] * (z * fast_sigmoid(z));
        v[k] = vv;
        ss = fmaf(vv, vv, ss);
    }
    __shared__ float red[256];
    red[tid] = ss;
    __syncthreads();
    for (int s = 128; s > 0; s >>= 1) {
        if (tid < s) red[tid] += red[tid + s];
        __syncthreads();
    }
    float r = rsqrtf(red[0] / (float)DSSM + 1e-5f);
#pragma unroll
    for (int k = 0; k < 8; k++) {
        int e = tid + k * 256;
        yn[(size_t)row * DSSM + e] = v[k] * r * norm_w[e];
    }
}

// ---------------- host launch ----------------
extern "C" void kernel_launch(void* const* d_in, const int* in_sizes, int n_in,
                              void* d_out, int out_size) {
    const float* u       = (const float*)d_in[0];
    const float* W_in    = (const float*)d_in[1];
    const float* conv_w  = (const float*)d_in[2];
    const float* conv_b  = (const float*)d_in[3];
    const float* dt_bias = (const float*)d_in[4];
    const float* A_log   = (const float*)d_in[5];
    const float* Dv      = (const float*)d_in[6];
    const float* norm_w  = (const float*)d_in[7];
    const float* W_out   = (const float*)d_in[8];
    float* out = (float*)d_out;

    void *p_zx, *p_xbc, *p_y, *p_yn, *p_states, *p_prev, *p_cs;
    void *p_uh, *p_ul, *p_wih, *p_wil, *p_ynh, *p_ynl, *p_woh, *p_wol;
    cudaGetSymbolAddress(&p_zx, g_zx);
    cudaGetSymbolAddress(&p_xbc, g_xbc);
    cudaGetSymbolAddress(&p_y, g_y);
    cudaGetSymbolAddress(&p_yn, g_yn);
    cudaGetSymbolAddress(&p_states, g_states);
    cudaGetSymbolAddress(&p_prev, g_prev);
    cudaGetSymbolAddress(&p_cs, g_cs);
    cudaGetSymbolAddress(&p_uh, g_uh);
    cudaGetSymbolAddress(&p_ul, g_ul);
    cudaGetSymbolAddress(&p_wih, g_wih);
    cudaGetSymbolAddress(&p_wil, g_wil);
    cudaGetSymbolAddress(&p_ynh, g_ynh);
    cudaGetSymbolAddress(&p_ynl, g_ynl);
    cudaGetSymbolAddress(&p_woh, g_woh);
    cudaGetSymbolAddress(&p_wol, g_wol);
    float* zx = (float*)p_zx;
    float* xbc = (float*)p_xbc;
    float* y = (float*)p_y;
    float* yn = (float*)p_yn;
    float* states = (float*)p_states;
    float* prev = (float*)p_prev;
    float* cs = (float*)p_cs;
    __nv_bfloat16* uh = (__nv_bfloat16*)p_uh;
    __nv_bfloat16* ul = (__nv_bfloat16*)p_ul;
    __nv_bfloat16* wih = (__nv_bfloat16*)p_wih;
    __nv_bfloat16* wil = (__nv_bfloat16*)p_wil;
    __nv_bfloat16* ynh = (__nv_bfloat16*)p_ynh;
    __nv_bfloat16* ynl = (__nv_bfloat16*)p_ynl;
    __nv_bfloat16* woh = (__nv_bfloat16*)p_woh;
    __nv_bfloat16* wol = (__nv_bfloat16*)p_wol;

    cudaFuncSetAttribute(gemm_nt_bf16x3, cudaFuncAttributeMaxDynamicSharedMemorySize,
                         GEMM_SMEM);
    cudaFuncSetAttribute(ssm_intra_kernel, cudaFuncAttributeMaxDynamicSharedMemorySize,
                         SM_K1_BYTES);
    cudaFuncSetAttribute(yoff64_kernel, cudaFuncAttributeMaxDynamicSharedMemorySize,
                         SM_K3_BYTES);

    // 0. split inputs to bf16 hi/lo
    {
        int n4 = MROWS * D_MODEL / 4;
        split_bf16_kernel<<<(n4 + 255) / 256, 256>>>(u, uh, ul, n4);
        n4 = DIP * D_MODEL / 4;
        split_bf16_kernel<<<(n4 + 255) / 256, 256>>>(W_in, wih, wil, n4);
        n4 = D_MODEL * DSSM / 4;
        split_bf16_kernel<<<(n4 + 255) / 256, 256>>>(W_out, woh, wol, n4);
    }

    // 1. in_proj
    gemm_nt_bf16x3<<<dim3((DIP + 127) / 128, MROWS / 128), 256, GEMM_SMEM>>>(
        uh, ul, wih, wil, zx, MROWS, DIP, D_MODEL);

    // 2. conv1d + silu
    {
        size_t total = (size_t)MROWS * CONVD;
        conv_silu_kernel<<<(unsigned)((total + 255) / 256), 256>>>(zx, conv_w, conv_b, xbc);
    }

    // 3. intra-chunk SSM (tensor cores)
    ssm_intra_kernel<<<dim3(NC64, BATCH), 256, SM_K1_BYTES>>>(
        zx, xbc, dt_bias, A_log, Dv, y, states, cs);

    // 4. inter-chunk recurrence
    chunk_scan64<<<dim3(32, NH, BATCH), 256>>>(states, cs, prev);

    // 5. Y_off (tensor cores)
    yoff64_kernel<<<dim3(NC64, BATCH), 256, SM_K3_BYTES>>>(xbc, prev, cs, y);

    // 6. gate + RMSNorm
    gate_norm_kernel<<<MROWS, 256>>>(zx, y, norm_w, yn);

    // 7. out_proj
    {
        int n4 = MROWS * DSSM / 4;
        split_bf16_kernel<<<(n4 + 255) / 256, 256>>>(yn, ynh, ynl, n4);
    }
    gemm_nt_bf16x3<<<dim3(D_MODEL / 128, MROWS / 128), 256, GEMM_SMEM>>>(
        ynh, ynl, woh, wol, out, MROWS, D_MODEL, DSSM);
}

// round 7
// speedup vs baseline: 2.0303x; 1.0063x over previous
#include <cuda_runtime.h>
#include <cuda_bf16.h>
#include <math.h>
#include <stdint.h>

#define BATCH 2
#define L_SEQ 4096
#define D_MODEL 1024
#define DIP 4384          // D_IN_PROJ
#define DSSM 2048
#define CONVD 2304        // CONV_DIM
#define NH 32
#define HD 64
#define DS 128
#define NC64 64           // chunks of 64 per batch
#define TCH 64
#define HPB 8             // heads per block in ssm_intra
#define MROWS (BATCH * L_SEQ)   // 8192

// ---------------- scratch (device globals; no allocation) ----------------
__device__ float g_zx[(size_t)MROWS * DIP];
__device__ float g_xbc[(size_t)MROWS * CONVD];
__device__ float g_y[(size_t)MROWS * DSSM];
__device__ float g_states[(size_t)BATCH * NC64 * NH * HD * DS];
__device__ float g_prev[(size_t)BATCH * NC64 * NH * HD * DS];
__device__ float g_cs[(size_t)BATCH * NC64 * NH * TCH];

__device__ __nv_bfloat16 g_uh[(size_t)MROWS * D_MODEL];
__device__ __nv_bfloat16 g_ul[(size_t)MROWS * D_MODEL];
__device__ __nv_bfloat16 g_wih[(size_t)DIP * D_MODEL];
__device__ __nv_bfloat16 g_wil[(size_t)DIP * D_MODEL];
__device__ __nv_bfloat16 g_ynh[(size_t)MROWS * DSSM];
__device__ __nv_bfloat16 g_ynl[(size_t)MROWS * DSSM];
__device__ __nv_bfloat16 g_woh[(size_t)D_MODEL * DSSM];
__device__ __nv_bfloat16 g_wol[(size_t)D_MODEL * DSSM];

// ---------------- helpers ----------------
struct alignas(8) bf16x4 { __nv_bfloat16 a, b, c, d; };

__device__ __forceinline__ float fast_sigmoid(float x) {
    return 1.f / (1.f + __expf(-x));
}

__device__ __forceinline__ void mma16816(float* d, const uint32_t* a, const uint32_t* b) {
    asm volatile(
        "mma.sync.aligned.m16n8k16.row.col.f32.bf16.bf16.f32 "
        "{%0,%1,%2,%3}, {%4,%5,%6,%7}, {%8,%9}, {%0,%1,%2,%3};"
        : "+f"(d[0]), "+f"(d[1]), "+f"(d[2]), "+f"(d[3])
        : "r"(a[0]), "r"(a[1]), "r"(a[2]), "r"(a[3]), "r"(b[0]), "r"(b[1]));
}

__device__ __forceinline__ void ldsm_x4(uint32_t& r0, uint32_t& r1, uint32_t& r2,
                                        uint32_t& r3, uint32_t addr) {
    asm volatile("ldmatrix.sync.aligned.m8n8.x4.shared.b16 {%0,%1,%2,%3}, [%4];"
                 : "=r"(r0), "=r"(r1), "=r"(r2), "=r"(r3) : "r"(addr));
}

__device__ __forceinline__ void bfsplit(float v, __nv_bfloat16& h, __nv_bfloat16& l) {
    h = __float2bfloat16(v);
    l = __float2bfloat16(v - __bfloat162float(h));
}

__device__ __forceinline__ void cpasync16(uint32_t dst, const void* src, int szvalid) {
    asm volatile("cp.async.cg.shared.global [%0], [%1], 16, %2;"
                 :: "r"(dst), "l"(src), "r"(szvalid) : "memory");
}
#define CPASYNC_COMMIT() asm volatile("cp.async.commit_group;" ::: "memory")
#define CPASYNC_WAIT(n)  asm volatile("cp.async.wait_group %0;" :: "n"(n) : "memory")

// ---------------- fp32 -> bf16 hi/lo split ----------------
__global__ void split_bf16_kernel(const float* __restrict__ x,
                                  __nv_bfloat16* __restrict__ hi,
                                  __nv_bfloat16* __restrict__ lo, int n4) {
    int i = blockIdx.x * 256 + threadIdx.x;
    if (i >= n4) return;
    float4 v = ((const float4*)x)[i];
    __nv_bfloat16 h0, h1, h2, h3, l0, l1, l2, l3;
    bfsplit(v.x, h0, l0); bfsplit(v.y, h1, l1);
    bfsplit(v.z, h2, l2); bfsplit(v.w, h3, l3);
    bf16x4 hv = {h0, h1, h2, h3};
    bf16x4 lv = {l0, l1, l2, l3};
    ((bf16x4*)hi)[i] = hv;
    ((bf16x4*)lo)[i] = lv;
}

// ---------------- tensor-core GEMM: C[M,N] = A[M,K] * B[N,K]^T (hi/lo x3) ----------------
// cp.async 3-stage staging + ldmatrix fragments. 128x128 block, 8 warps.
#define GK 16
#define GPAD 24
#define NSTAGE 3
#define GEMM_SMEM (NSTAGE * 2 * 128 * GPAD * 2 * 2)   // 73728 bytes

__global__ __launch_bounds__(256, 2) void gemm_nt_bf16x3(
    const __nv_bfloat16* __restrict__ Ah, const __nv_bfloat16* __restrict__ Al,
    const __nv_bfloat16* __restrict__ Bh, const __nv_bfloat16* __restrict__ Bl,
    float* __restrict__ C, int M, int N, int K) {
    extern __shared__ __nv_bfloat16 smb[];
    __nv_bfloat16* sA = smb;
    __nv_bfloat16* sB = smb + NSTAGE * 2 * 128 * GPAD;

    const int tid = threadIdx.x;
    const int wid = tid >> 5, lane = tid & 31;
    const int wm = wid >> 2, wn = wid & 3;
    const int grp = lane >> 2, q2 = (lane & 3) * 2;
    const int rowBase = blockIdx.y * 128;
    const int colBase = blockIdx.x * 128;
    const int lrow = tid >> 1;
    const int lkh = (tid & 1) * 8;

    const int lmRow = lane & 15;
    const int lmK = (lane >> 4) << 3;

    const uint32_t sA_s = (uint32_t)__cvta_generic_to_shared(sA);
    const uint32_t sB_s = (uint32_t)__cvta_generic_to_shared(sB);

    float acc[4][4][4];
#pragma unroll
    for (int i = 0; i < 4; i++)
#pragma unroll
        for (int j = 0; j < 4; j++)
#pragma unroll
            for (int r = 0; r < 4; r++) acc[i][j][r] = 0.f;

    const int nk = K / GK;
#define SAIDX(st, hl, r, k) (((((st) * 2 + (hl)) * 128 + (r)) * GPAD) + (k))

    // per-thread staging source pointers
    const __nv_bfloat16* pAh = Ah + (size_t)(rowBase + lrow) * K + lkh;
    const __nv_bfloat16* pAl = Al + (size_t)(rowBase + lrow) * K + lkh;
    int cn = colBase + lrow;
    int bok = (cn < N) ? 16 : 0;
    int cnc = (cn < N) ? cn : 0;
    const __nv_bfloat16* pBh = Bh + (size_t)cnc * K + lkh;
    const __nv_bfloat16* pBl = Bl + (size_t)cnc * K + lkh;

    auto load_stage = [&](int st, int kc) {
        int ko = kc * GK;
        cpasync16(sA_s + SAIDX(st, 0, lrow, lkh) * 2, pAh + ko, 16);
        cpasync16(sA_s + SAIDX(st, 1, lrow, lkh) * 2, pAl + ko, 16);
        cpasync16(sB_s + SAIDX(st, 0, lrow, lkh) * 2, pBh + ko, bok);
        cpasync16(sB_s + SAIDX(st, 1, lrow, lkh) * 2, pBl + ko, bok);
        CPASYNC_COMMIT();
    };

    load_stage(0, 0);
    if (nk > 1) load_stage(1, 1);

    for (int k = 0; k < nk; k++) {
        int st = k % NSTAGE;
        if (k + 2 < nk) {
            load_stage((k + 2) % NSTAGE, k + 2);
            CPASYNC_WAIT(2);
        } else if (k + 1 < nk) {
            CPASYNC_WAIT(1);
        } else {
            CPASYNC_WAIT(0);
        }
        __syncthreads();

        uint32_t bh[4][2], bl[4][2];
        {
            uint32_t r0, r1, r2, r3;
            ldsm_x4(r0, r1, r2, r3, sB_s + SAIDX(st, 0, wn * 32 + lmRow, lmK) * 2);
            bh[0][0] = r0; bh[0][1] = r2; bh[1][0] = r1; bh[1][1] = r3;
            ldsm_x4(r0, r1, r2, r3, sB_s + SAIDX(st, 0, wn * 32 + 16 + lmRow, lmK) * 2);
            bh[2][0] = r0; bh[2][1] = r2; bh[3][0] = r1; bh[3][1] = r3;
            ldsm_x4(r0, r1, r2, r3, sB_s + SAIDX(st, 1, wn * 32 + lmRow, lmK) * 2);
            bl[0][0] = r0; bl[0][1] = r2; bl[1][0] = r1; bl[1][1] = r3;
            ldsm_x4(r0, r1, r2, r3, sB_s + SAIDX(st, 1, wn * 32 + 16 + lmRow, lmK) * 2);
            bl[2][0] = r0; bl[2][1] = r2; bl[3][0] = r1; bl[3][1] = r3;
        }
#pragma unroll
        for (int mt = 0; mt < 4; mt++) {
            int r0row = wm * 64 + mt * 16;
            uint32_t ah[4], al[4];
            ldsm_x4(ah[0], ah[1], ah[2], ah[3], sA_s + SAIDX(st, 0, r0row + lmRow, lmK) * 2);
            ldsm_x4(al[0], al[1], al[2], al[3], sA_s + SAIDX(st, 1, r0row + lmRow, lmK) * 2);
#pragma unroll
            for (int nt = 0; nt < 4; nt++) {
                mma16816(acc[mt][nt], ah, bh[nt]);
                mma16816(acc[mt][nt], ah, bl[nt]);
                mma16816(acc[mt][nt], al, bh[nt]);
            }
        }
        __syncthreads();
    }
#pragma unroll
    for (int mt = 0; mt < 4; mt++) {
#pragma unroll
        for (int nt = 0; nt < 4; nt++) {
            int colTile = colBase + wn * 32 + nt * 8;
            if (colTile >= N) continue;
            int r0 = rowBase + wm * 64 + mt * 16 + grp;
            int c0 = colTile + q2;
            *(float2*)&C[(size_t)r0 * N + c0] = make_float2(acc[mt][nt][0], acc[mt][nt][1]);
            *(float2*)&C[(size_t)(r0 + 8) * N + c0] = make_float2(acc[mt][nt][2], acc[mt][nt][3]);
        }
    }
#undef SAIDX
}

// ---------------- conv1d (causal, depthwise, width 4) + SiLU : 4 t per thread ----------------
__global__ void conv_silu_kernel(const float* __restrict__ zx,
                                 const float* __restrict__ conv_w,
                                 const float* __restrict__ conv_b,
                                 float* __restrict__ xbc) {
    size_t idx = (size_t)blockIdx.x * 256 + threadIdx.x;
    const size_t total = (size_t)(MROWS / 4) * CONVD;
    if (idx >= total) return;
    int cc = (int)(idx % CONVD);
    size_t r4 = idx / CONVD;
    size_t bt0 = r4 * 4;
    int t0 = (int)(bt0 % L_SEQ);

    float w0 = conv_w[cc * 4 + 0], w1 = conv_w[cc * 4 + 1];
    float w2 = conv_w[cc * 4 + 2], w3 = conv_w[cc * 4 + 3];
    float bia = conv_b[cc];

    float v[7];
#pragma unroll
    for (int j = 0; j < 7; j++) {
        int tt = t0 - 3 + j;
        v[j] = (tt >= 0) ? zx[(bt0 - 3 + j) * DIP + 2048 + cc] : 0.f;
    }
#pragma unroll
    for (int i = 0; i < 4; i++) {
        float acc = bia;
        acc = fmaf(v[i + 0], w0, acc);
        acc = fmaf(v[i + 1], w1, acc);
        acc = fmaf(v[i + 2], w2, acc);
        acc = fmaf(v[i + 3], w3, acc);
        xbc[(bt0 + i) * CONVD + cc] = acc * fast_sigmoid(acc);
    }
}

// ---------------- K1: intra-chunk SSM on tensor cores (HMMA) ----------------
// grid (NC64, NH/HPB, BATCH), 256 threads; HPB heads per block.
#define SB_S 136
#define ST_S 66
#define SM_K1_BYTES ((4 * 64 * SB_S + 2 * 128 * ST_S + 6 * 64 * ST_S) * 2 + \
                     (64 * ST_S + 2 * HPB * 64 + 64) * 4)

__global__ __launch_bounds__(256, 1) void ssm_intra_kernel(
    const float* __restrict__ zx, const float* __restrict__ xbc,
    const float* __restrict__ dt_bias, const float* __restrict__ A_log,
    const float* __restrict__ Dvec,
    float* __restrict__ y, float* __restrict__ states, float* __restrict__ cs_out) {
    extern __shared__ char smraw[];
    __nv_bfloat16* sBh = (__nv_bfloat16*)smraw;
    __nv_bfloat16* sBl = sBh + 64 * SB_S;
    __nv_bfloat16* sCh = sBl + 64 * SB_S;
    __nv_bfloat16* sCl = sCh + 64 * SB_S;
    __nv_bfloat16* sBTh = sCl + 64 * SB_S;
    __nv_bfloat16* sBTl = sBTh + 128 * ST_S;
    __nv_bfloat16* sGh = sBTl + 128 * ST_S;
    __nv_bfloat16* sGl = sGh + 64 * ST_S;
    __nv_bfloat16* sXh = sGl + 64 * ST_S;
    __nv_bfloat16* sXl = sXh + 64 * ST_S;
    __nv_bfloat16* sXdh = sXl + 64 * ST_S;
    __nv_bfloat16* sXdl = sXdh + 64 * ST_S;
    float* sG = (float*)(sXdl + 64 * ST_S);
    float* s_dt = sG + 64 * ST_S;        // HPB x 64
    float* s_cs = s_dt + HPB * 64;       // HPB x 64
    float* sEd = s_cs + HPB * 64;        // 64

    const int c = blockIdx.x, hg = blockIdx.y, b = blockIdx.z;
    const int h0 = hg * HPB;
    const int tid = threadIdx.x;
    const int wid = tid >> 5, lane = tid & 31;
    const int wm = wid >> 2, wn = wid & 3;
    const int grp = lane >> 2, q2 = (lane & 3) * 2;
    const int row0 = b * L_SEQ + c * TCH;
    const float* xrow = xbc + (size_t)row0 * CONVD;

    // each warp: one head (HPB == 8 == #warps)
    {
        int h = h0 + wid;
        float Ah = -__expf(A_log[h]);
        float bias = dt_bias[h];
        float d0 = zx[(size_t)(row0 + lane) * DIP + 4352 + h] + bias;
        float d1 = zx[(size_t)(row0 + 32 + lane) * DIP + 4352 + h] + bias;
        float dt0 = (d0 > 20.f) ? d0 : log1pf(__expf(d0));
        float dt1 = (d1 > 20.f) ? d1 : log1pf(__expf(d1));
        s_dt[wid * 64 + lane] = dt0;
        s_dt[wid * 64 + 32 + lane] = dt1;
        float v0 = dt0 * Ah, v1 = dt1 * Ah;
#pragma unroll
        for (int off = 1; off < 32; off <<= 1) {
            float n0 = __shfl_up_sync(0xffffffffu, v0, off);
            float n1 = __shfl_up_sync(0xffffffffu, v1, off);
            if (lane >= off) { v0 += n0; v1 += n1; }
        }
        v1 += __shfl_sync(0xffffffffu, v0, 31);
        s_cs[wid * 64 + lane] = v0;
        s_cs[wid * 64 + 32 + lane] = v1;
        size_t cbase = (((size_t)b * NC64 + c) * NH + h) * TCH;
        cs_out[cbase + lane] = v0;
        cs_out[cbase + 32 + lane] = v1;
    }

    for (int idx = tid; idx < 64 * 128; idx += 256) {
        int s = idx >> 7, n = idx & 127;
        float bv = xrow[(size_t)s * CONVD + 2048 + n];
        float cv = xrow[(size_t)s * CONVD + 2176 + n];
        __nv_bfloat16 bh, bl, ch, cl;
        bfsplit(bv, bh, bl);
        bfsplit(cv, ch, cl);
        sBh[s * SB_S + n] = bh; sBl[s * SB_S + n] = bl;
        sCh[s * SB_S + n] = ch; sCl[s * SB_S + n] = cl;
        sBTh[n * ST_S + s] = bh; sBTl[n * ST_S + s] = bl;
    }
    __syncthreads();

    // G = C * B^T (shared across the HPB heads)
    {
        float g[2][2][4];
#pragma unroll
        for (int i = 0; i < 2; i++)
#pragma unroll
            for (int j = 0; j < 2; j++)
#pragma unroll
                for (int r = 0; r < 4; r++) g[i][j][r] = 0.f;
        for (int kb = 0; kb < 128; kb += 16) {
            uint32_t bh[2][2], bl[2][2];
#pragma unroll
            for (int nt = 0; nt < 2; nt++) {
                int c0 = wn * 16 + nt * 8 + grp;
                bh[nt][0] = *(const uint32_t*)&sBh[c0 * SB_S + kb + q2];
                bh[nt][1] = *(const uint32_t*)&sBh[c0 * SB_S + kb + q2 + 8];
                bl[nt][0] = *(const uint32_t*)&sBl[c0 * SB_S + kb + q2];
                bl[nt][1] = *(const uint32_t*)&sBl[c0 * SB_S + kb + q2 + 8];
            }
#pragma unroll
            for (int mt = 0; mt < 2; mt++) {
                int r0 = wm * 32 + mt * 16 + grp;
                uint32_t ah[4], al[4];
                ah[0] = *(const uint32_t*)&sCh[r0 * SB_S + kb + q2];
                ah[1] = *(const uint32_t*)&sCh[(r0 + 8) * SB_S + kb + q2];
                ah[2] = *(const uint32_t*)&sCh[r0 * SB_S + kb + q2 + 8];
                ah[3] = *(const uint32_t*)&sCh[(r0 + 8) * SB_S + kb + q2 + 8];
                al[0] = *(const uint32_t*)&sCl[r0 * SB_S + kb + q2];
                al[1] = *(const uint32_t*)&sCl[(r0 + 8) * SB_S + kb + q2];
                al[2] = *(const uint32_t*)&sCl[r0 * SB_S + kb + q2 + 8];
                al[3] = *(const uint32_t*)&sCl[(r0 + 8) * SB_S + kb + q2 + 8];
#pragma unroll
                for (int nt = 0; nt < 2; nt++) {
                    mma16816(g[mt][nt], ah, bh[nt]);
                    mma16816(g[mt][nt], ah, bl[nt]);
                    mma16816(g[mt][nt], al, bh[nt]);
                }
            }
        }
#pragma unroll
        for (int mt = 0; mt < 2; mt++)
#pragma unroll
            for (int nt = 0; nt < 2; nt++) {
                int t = wm * 32 + mt * 16 + grp;
                int s = wn * 16 + nt * 8 + q2;
                *(float2*)&sG[t * ST_S + s] = make_float2(g[mt][nt][0], g[mt][nt][1]);
                *(float2*)&sG[(t + 8) * ST_S + s] = make_float2(g[mt][nt][2], g[mt][nt][3]);
            }
    }

    for (int hl = 0; hl < HPB; hl++) {
        int h = h0 + hl;
        __syncthreads();
        const float* csh = s_cs + hl * 64;
        const float* dth = s_dt + hl * 64;
        const float csL = csh[63];
        if (tid < 64) sEd[tid] = __expf(csL - csh[tid]);
        for (int idx = tid; idx < 64 * 64; idx += 256) {
            int t = idx >> 6, s = idx & 63;
            float val = 0.f;
            if (t >= s) val = sG[t * ST_S + s] * __expf(csh[t] - csh[s]);
            __nv_bfloat16 hch, hcl;
            bfsplit(val, hch, hcl);
            sGh[t * ST_S + s] = hch;
            sGl[t * ST_S + s] = hcl;
        }
        __syncthreads();
        for (int idx = tid; idx < 64 * 64; idx += 256) {
            int s = idx >> 6, p = idx & 63;
            float xv = xrow[(size_t)s * CONVD + h * 64 + p];
            float xt = xv * dth[s];
            __nv_bfloat16 xh, xl, xdh, xdl;
            bfsplit(xt, xh, xl);
            bfsplit(xt * sEd[s], xdh, xdl);
            sXh[p * ST_S + s] = xh;  sXl[p * ST_S + s] = xl;
            sXdh[p * ST_S + s] = xdh; sXdl[p * ST_S + s] = xdl;
        }
        __syncthreads();

        // Y_diag = G~ * x~
        {
            float yd[2][2][4];
#pragma unroll
            for (int i = 0; i < 2; i++)
#pragma unroll
                for (int j = 0; j < 2; j++)
#pragma unroll
                    for (int r = 0; r < 4; r++) yd[i][j][r] = 0.f;
            for (int kb = 0; kb < 64; kb += 16) {
                uint32_t bh[2][2], bl[2][2];
#pragma unroll
                for (int nt = 0; nt < 2; nt++) {
                    int c0 = wn * 16 + nt * 8 + grp;
                    bh[nt][0] = *(const uint32_t*)&sXh[c0 * ST_S + kb + q2];
                    bh[nt][1] = *(const uint32_t*)&sXh[c0 * ST_S + kb + q2 + 8];
                    bl[nt][0] = *(const uint32_t*)&sXl[c0 * ST_S + kb + q2];
                    bl[nt][1] = *(const uint32_t*)&sXl[c0 * ST_S + kb + q2 + 8];
                }
#pragma unroll
                for (int mt = 0; mt < 2; mt++) {
                    int r0 = wm * 32 + mt * 16 + grp;
                    uint32_t ah[4], al[4];
                    ah[0] = *(const uint32_t*)&sGh[r0 * ST_S + kb + q2];
                    ah[1] = *(const uint32_t*)&sGh[(r0 + 8) * ST_S + kb + q2];
                    ah[2] = *(const uint32_t*)&sGh[r0 * ST_S + kb + q2 + 8];
                    ah[3] = *(const uint32_t*)&sGh[(r0 + 8) * ST_S + kb + q2 + 8];
                    al[0] = *(const uint32_t*)&sGl[r0 * ST_S + kb + q2];
                    al[1] = *(const uint32_t*)&sGl[(r0 + 8) * ST_S + kb + q2];
                    al[2] = *(const uint32_t*)&sGl[r0 * ST_S + kb + q2 + 8];
                    al[3] = *(const uint32_t*)&sGl[(r0 + 8) * ST_S + kb + q2 + 8];
#pragma unroll
                    for (int nt = 0; nt < 2; nt++) {
                        mma16816(yd[mt][nt], ah, bh[nt]);
                        mma16816(yd[mt][nt], ah, bl[nt]);
                        mma16816(yd[mt][nt], al, bh[nt]);
                    }
                }
            }
            float Dh = Dvec[h];
#pragma unroll
            for (int mt = 0; mt < 2; mt++)
#pragma unroll
                for (int nt = 0; nt < 2; nt++) {
                    int t0 = wm * 32 + mt * 16 + grp;
                    int p0 = wn * 16 + nt * 8 + q2;
#pragma unroll
                    for (int rr = 0; rr < 2; rr++) {
                        int t = t0 + rr * 8;
                        float2 xv = *(const float2*)&xrow[(size_t)t * CONVD + h * 64 + p0];
                        float2 o;
                        o.x = fmaf(Dh, xv.x, yd[mt][nt][rr * 2 + 0]);
                        o.y = fmaf(Dh, xv.y, yd[mt][nt][rr * 2 + 1]);
                        *(float2*)&g_y[(size_t)(row0 + t) * DSSM + h * 64 + p0] = o;
                    }
                }
        }

        // state = x~d^T * B
        {
            float st[2][4][4];
#pragma unroll
            for (int i = 0; i < 2; i++)
#pragma unroll
                for (int j = 0; j < 4; j++)
#pragma unroll
                    for (int r = 0; r < 4; r++) st[i][j][r] = 0.f;
            for (int kb = 0; kb < 64; kb += 16) {
                uint32_t bh[4][2], bl[4][2];
#pragma unroll
                for (int nt = 0; nt < 4; nt++) {
                    int c0 = wn * 32 + nt * 8 + grp;
                    bh[nt][0] = *(const uint32_t*)&sBTh[c0 * ST_S + kb + q2];
                    bh[nt][1] = *(const uint32_t*)&sBTh[c0 * ST_S + kb + q2 + 8];
                    bl[nt][0] = *(const uint32_t*)&sBTl[c0 * ST_S + kb + q2];
                    bl[nt][1] = *(const uint32_t*)&sBTl[c0 * ST_S + kb + q2 + 8];
                }
#pragma unroll
                for (int mt = 0; mt < 2; mt++) {
                    int r0 = wm * 32 + mt * 16 + grp;
                    uint32_t ah[4], al[4];
                    ah[0] = *(const uint32_t*)&sXdh[r0 * ST_S + kb + q2];
                    ah[1] = *(const uint32_t*)&sXdh[(r0 + 8) * ST_S + kb + q2];
                    ah[2] = *(const uint32_t*)&sXdh[r0 * ST_S + kb + q2 + 8];
                    ah[3] = *(const uint32_t*)&sXdh[(r0 + 8) * ST_S + kb + q2 + 8];
                    al[0] = *(const uint32_t*)&sXdl[r0 * ST_S + kb + q2];
                    al[1] = *(const uint32_t*)&sXdl[(r0 + 8) * ST_S + kb + q2];
                    al[2] = *(const uint32_t*)&sXdl[r0 * ST_S + kb + q2 + 8];
                    al[3] = *(const uint32_t*)&sXdl[(r0 + 8) * ST_S + kb + q2 + 8];
#pragma unroll
                    for (int nt = 0; nt < 4; nt++) {
                        mma16816(st[mt][nt], ah, bh[nt]);
                        mma16816(st[mt][nt], ah, bl[nt]);
                        mma16816(st[mt][nt], al, bh[nt]);
                    }
                }
            }
            size_t sbase = (((size_t)b * NC64 + c) * NH + h) * (size_t)(HD * DS);
#pragma unroll
            for (int mt = 0; mt < 2; mt++)
#pragma unroll
                for (int nt = 0; nt < 4; nt++) {
                    int p0 = wm * 32 + mt * 16 + grp;
                    int n0 = wn * 32 + nt * 8 + q2;
                    *(float2*)&states[sbase + (size_t)p0 * DS + n0] =
                        make_float2(st[mt][nt][0], st[mt][nt][1]);
                    *(float2*)&states[sbase + (size_t)(p0 + 8) * DS + n0] =
                        make_float2(st[mt][nt][2], st[mt][nt][3]);
                }
        }
    }
}

// ---------------- K2: inter-chunk recurrence over 64 chunks ----------------
__global__ void chunk_scan64(const float* __restrict__ states,
                             const float* __restrict__ cs,
                             float* __restrict__ prev) {
    const int seg = blockIdx.x, h = blockIdx.y, b = blockIdx.z;
    const int e = seg * 256 + threadIdx.x;
    float P = 0.f;
    for (int c = 0; c < NC64; c++) {
        size_t base = ((size_t)b * NC64 + c) * NH + h;
        float sc = __expf(cs[base * TCH + TCH - 1]);
        size_t off = base * (size_t)(HD * DS) + e;
        prev[off] = P;
        P = fmaf(P, sc, states[off]);
    }
}

// ---------------- K3: Y += diag(exp(cs)) * C * prev^T on tensor cores ----------------
#define SM_K3_BYTES ((4 * 64 * SB_S) * 2 + 64 * 4)
__global__ __launch_bounds__(256, 1) void yoff64_kernel(
    const float* __restrict__ xbc, const float* __restrict__ prev,
    const float* __restrict__ cs, float* __restrict__ y) {
    extern __shared__ char smraw[];
    __nv_bfloat16* sCh = (__nv_bfloat16*)smraw;
    __nv_bfloat16* sCl = sCh + 64 * SB_S;
    __nv_bfloat16* sPh = sCl + 64 * SB_S;
    __nv_bfloat16* sPl = sPh + 64 * SB_S;
    float* sE = (float*)(sPl + 64 * SB_S);

    const int c = blockIdx.x, b = blockIdx.y;
    const int tid = threadIdx.x;
    const int wid = tid >> 5, lane = tid & 31;
    const int wm = wid >> 2, wn = wid & 3;
    const int grp = lane >> 2, q2 = (lane & 3) * 2;
    const int row0 = b * L_SEQ + c * TCH;
    const float* xrow = xbc + (size_t)row0 * CONVD;

    for (int idx = tid; idx < 64 * 128; idx += 256) {
        int t = idx >> 7, n = idx & 127;
        float cv = xrow[(size_t)t * CONVD + 2176 + n];
        __nv_bfloat16 ch, cl;
        bfsplit(cv, ch, cl);
        sCh[t * SB_S + n] = ch;
        sCl[t * SB_S + n] = cl;
    }

    for (int h = 0; h < NH; h++) {
        __syncthreads();
        if (tid < 64)
            sE[tid] = __expf(cs[(((size_t)b * NC64 + c) * NH + h) * TCH + tid]);
        size_t pbase = (((size_t)b * NC64 + c) * NH + h) * (size_t)(HD * DS);
        for (int idx = tid; idx < 64 * 128; idx += 256) {
            int p = idx >> 7, n = idx & 127;
            float pv = prev[pbase + (size_t)p * DS + n];
            __nv_bfloat16 ph, pl;
            bfsplit(pv, ph, pl);
            sPh[p * SB_S + n] = ph;
            sPl[p * SB_S + n] = pl;
        }
        __syncthreads();

        float acc[2][2][4];
#pragma unroll
        for (int i = 0; i < 2; i++)
#pragma unroll
            for (int j = 0; j < 2; j++)
#pragma unroll
                for (int r = 0; r < 4; r++) acc[i][j][r] = 0.f;
        for (int kb = 0; kb < 128; kb += 16) {
            uint32_t bh[2][2], bl[2][2];
#pragma unroll
            for (int nt = 0; nt < 2; nt++) {
                int c0 = wn * 16 + nt * 8 + grp;
                bh[nt][0] = *(const uint32_t*)&sPh[c0 * SB_S + kb + q2];
                bh[nt][1] = *(const uint32_t*)&sPh[c0 * SB_S + kb + q2 + 8];
                bl[nt][0] = *(const uint32_t*)&sPl[c0 * SB_S + kb + q2];
                bl[nt][1] = *(const uint32_t*)&sPl[c0 * SB_S + kb + q2 + 8];
            }
#pragma unroll
            for (int mt = 0; mt < 2; mt++) {
                int r0 = wm * 32 + mt * 16 + grp;
                uint32_t ah[4], al[4];
                ah[0] = *(const uint32_t*)&sCh[r0 * SB_S + kb + q2];
                ah[1] = *(const uint32_t*)&sCh[(r0 + 8) * SB_S + kb + q2];
                ah[2] = *(const uint32_t*)&sCh[r0 * SB_S + kb + q2 + 8];
                ah[3] = *(const uint32_t*)&sCh[(r0 + 8) * SB_S + kb + q2 + 8];
                al[0] = *(const uint32_t*)&sCl[r0 * SB_S + kb + q2];
                al[1] = *(const uint32_t*)&sCl[(r0 + 8) * SB_S + kb + q2];
                al[2] = *(const uint32_t*)&sCl[r0 * SB_S + kb + q2 + 8];
                al[3] = *(const uint32_t*)&sCl[(r0 + 8) * SB_S + kb + q2 + 8];
#pragma unroll
                for (int nt = 0; nt < 2; nt++) {
                    mma16816(acc[mt][nt], ah, bh[nt]);
                    mma16816(acc[mt][nt], ah, bl[nt]);
                    mma16816(acc[mt][nt], al, bh[nt]);
                }
            }
        }
#pragma unroll
        for (int mt = 0; mt < 2; mt++)
#pragma unroll
            for (int nt = 0; nt < 2; nt++) {
                int t0 = wm * 32 + mt * 16 + grp;
                int p0 = wn * 16 + nt * 8 + q2;
#pragma unroll
                for (int rr = 0; rr < 2; rr++) {
                    int t = t0 + rr * 8;
                    float e = sE[t];
                    size_t addr = (size_t)(row0 + t) * DSSM + h * 64 + p0;
                    float2 old = *(float2*)&y[addr];
                    old.x = fmaf(e, acc[mt][nt][rr * 2 + 0], old.x);
                    old.y = fmaf(e, acc[mt][nt][rr * 2 + 1], old.y);
                    *(float2*)&y[addr] = old;
                }
            }
    }
}

// ---------------- gate (y * silu(z)) + RMSNorm, fused bf16 hi/lo split ----------------
__global__ void gate_norm_kernel(const float* __restrict__ zx,
                                 const float* __restrict__ y,
                                 const float* __restrict__ norm_w,
                                 __nv_bfloat16* __restrict__ ynh,
                                 __nv_bfloat16* __restrict__ ynl) {
    const int row = blockIdx.x;
    const int tid = threadIdx.x;
    const float* yrow = y + (size_t)row * DSSM;
    const float* zrow = zx + (size_t)row * DIP;
    float v[8];
    float ss = 0.f;
#pragma unroll
    for (int k = 0; k < 8; k++) {
        int e = tid + k * 256;
        float z = zrow[e];
        float vv = yrow[e] * (z * fast_sigmoid(z));
        v[k] = vv;
        ss = fmaf(vv, vv, ss);
    }
    __shared__ float red[256];
    red[tid] = ss;
    __syncthreads();
    for (int s = 128; s > 0; s >>= 1) {
        if (tid < s) red[tid] += red[tid + s];
        __syncthreads();
    }
    float r = rsqrtf(red[0] / (float)DSSM + 1e-5f);
#pragma unroll
    for (int k = 0; k < 8; k++) {
        int e = tid + k * 256;
        float o = v[k] * r * norm_w[e];
        __nv_bfloat16 oh, ol;
        bfsplit(o, oh, ol);
        ynh[(size_t)row * DSSM + e] = oh;
        ynl[(size_t)row * DSSM + e] = ol;
    }
}

// ---------------- host launch ----------------
extern "C" void kernel_launch(void* const* d_in, const int* in_sizes, int n_in,
                              void* d_out, int out_size) {
    const float* u       = (const float*)d_in[0];
    const float* W_in    = (const float*)d_in[1];
    const float* conv_w  = (const float*)d_in[2];
    const float* conv_b  = (const float*)d_in[3];
    const float* dt_bias = (const float*)d_in[4];
    const float* A_log   = (const float*)d_in[5];
    const float* Dv      = (const float*)d_in[6];
    const float* norm_w  = (const float*)d_in[7];
    const float* W_out   = (const float*)d_in[8];
    float* out = (float*)d_out;

    void *p_zx, *p_xbc, *p_y, *p_states, *p_prev, *p_cs;
    void *p_uh, *p_ul, *p_wih, *p_wil, *p_ynh, *p_ynl, *p_woh, *p_wol;
    cudaGetSymbolAddress(&p_zx, g_zx);
    cudaGetSymbolAddress(&p_xbc, g_xbc);
    cudaGetSymbolAddress(&p_y, g_y);
    cudaGetSymbolAddress(&p_states, g_states);
    cudaGetSymbolAddress(&p_prev, g_prev);
    cudaGetSymbolAddress(&p_cs, g_cs);
    cudaGetSymbolAddress(&p_uh, g_uh);
    cudaGetSymbolAddress(&p_ul, g_ul);
    cudaGetSymbolAddress(&p_wih, g_wih);
    cudaGetSymbolAddress(&p_wil, g_wil);
    cudaGetSymbolAddress(&p_ynh, g_ynh);
    cudaGetSymbolAddress(&p_ynl, g_ynl);
    cudaGetSymbolAddress(&p_woh, g_woh);
    cudaGetSymbolAddress(&p_wol, g_wol);
    float* zx = (float*)p_zx;
    float* xbc = (float*)p_xbc;
    float* y = (float*)p_y;
    float* states = (float*)p_states;
    float* prev = (float*)p_prev;
    float* cs = (float*)p_cs;
    __nv_bfloat16* uh = (__nv_bfloat16*)p_uh;
    __nv_bfloat16* ul = (__nv_bfloat16*)p_ul;
    __nv_bfloat16* wih = (__nv_bfloat16*)p_wih;
    __nv_bfloat16* wil = (__nv_bfloat16*)p_wil;
    __nv_bfloat16* ynh = (__nv_bfloat16*)p_ynh;
    __nv_bfloat16* ynl = (__nv_bfloat16*)p_ynl;
    __nv_bfloat16* woh = (__nv_bfloat16*)p_woh;
    __nv_bfloat16* wol = (__nv_bfloat16*)p_wol;

    cudaFuncSetAttribute(gemm_nt_bf16x3, cudaFuncAttributeMaxDynamicSharedMemorySize,
                         GEMM_SMEM);
    cudaFuncSetAttribute(ssm_intra_kernel, cudaFuncAttributeMaxDynamicSharedMemorySize,
                         SM_K1_BYTES);
    cudaFuncSetAttribute(yoff64_kernel, cudaFuncAttributeMaxDynamicSharedMemorySize,
                         SM_K3_BYTES);

    // 0. split inputs to bf16 hi/lo
    {
        int n4 = MROWS * D_MODEL / 4;
        split_bf16_kernel<<<(n4 + 255) / 256, 256>>>(u, uh, ul, n4);
        n4 = DIP * D_MODEL / 4;
        split_bf16_kernel<<<(n4 + 255) / 256, 256>>>(W_in, wih, wil, n4);
        n4 = D_MODEL * DSSM / 4;
        split_bf16_kernel<<<(n4 + 255) / 256, 256>>>(W_out, woh, wol, n4);
    }

    // 1. in_proj
    gemm_nt_bf16x3<<<dim3((DIP + 127) / 128, MROWS / 128), 256, GEMM_SMEM>>>(
        uh, ul, wih, wil, zx, MROWS, DIP, D_MODEL);

    // 2. conv1d + silu (4 t per thread)
    {
        size_t total4 = (size_t)(MROWS / 4) * CONVD;
        conv_silu_kernel<<<(unsigned)((total4 + 255) / 256), 256>>>(zx, conv_w, conv_b, xbc);
    }

    // 3. intra-chunk SSM
    ssm_intra_kernel<<<dim3(NC64, NH / HPB, BATCH), 256, SM_K1_BYTES>>>(
        zx, xbc, dt_bias, A_log, Dv, y, states, cs);

    // 4. inter-chunk recurrence
    chunk_scan64<<<dim3(32, NH, BATCH), 256>>>(states, cs, prev);

    // 5. Y_off
    yoff64_kernel<<<dim3(NC64, BATCH), 256, SM_K3_BYTES>>>(xbc, prev, cs, y);

    // 6. gate + RMSNorm + fused split
    gate_norm_kernel<<<MROWS, 256>>>(zx, y, norm_w, ynh, ynl);

    // 7. out_proj
    gemm_nt_bf16x3<<<dim3(D_MODEL / 128, MROWS / 128), 256, GEMM_SMEM>>>(
        ynh, ynl, woh, wol, out, MROWS, D_MODEL, DSSM);
}

// round 8
// speedup vs baseline: 2.1267x; 1.0475x over previous
#include <cuda_runtime.h>
#include <cuda_bf16.h>
#include <math.h>
#include <stdint.h>

#define BATCH 2
#define L_SEQ 4096
#define D_MODEL 1024
#define DIP 4384          // D_IN_PROJ
#define DSSM 2048
#define CONVD 2304        // CONV_DIM
#define NH 32
#define HD 64
#define DS 128
#define NC64 64           // chunks of 64 per batch
#define TCH 64
#define HPB 8             // heads per block in ssm_intra
#define MROWS (BATCH * L_SEQ)   // 8192

// ---------------- scratch (device globals; no allocation) ----------------
__device__ float g_zx[(size_t)MROWS * DIP];
__device__ float g_xbc[(size_t)MROWS * CONVD];
__device__ float g_y[(size_t)MROWS * DSSM];
__device__ float g_states[(size_t)BATCH * NC64 * NH * HD * DS];
__device__ float g_prev[(size_t)BATCH * NC64 * NH * HD * DS];
__device__ float g_cs[(size_t)BATCH * NC64 * NH * TCH];

__device__ __nv_bfloat16 g_uh[(size_t)MROWS * D_MODEL];
__device__ __nv_bfloat16 g_ul[(size_t)MROWS * D_MODEL];
__device__ __nv_bfloat16 g_wih[(size_t)DIP * D_MODEL];
__device__ __nv_bfloat16 g_wil[(size_t)DIP * D_MODEL];
__device__ __nv_bfloat16 g_ynh[(size_t)MROWS * DSSM];
__device__ __nv_bfloat16 g_ynl[(size_t)MROWS * DSSM];
__device__ __nv_bfloat16 g_woh[(size_t)D_MODEL * DSSM];
__device__ __nv_bfloat16 g_wol[(size_t)D_MODEL * DSSM];

// ---------------- helpers ----------------
struct alignas(8) bf16x4 { __nv_bfloat16 a, b, c, d; };

__device__ __forceinline__ float fast_sigmoid(float x) {
    return 1.f / (1.f + __expf(-x));
}

__device__ __forceinline__ void mma16816(float* d, const uint32_t* a, const uint32_t* b) {
    asm volatile(
        "mma.sync.aligned.m16n8k16.row.col.f32.bf16.bf16.f32 "
        "{%0,%1,%2,%3}, {%4,%5,%6,%7}, {%8,%9}, {%0,%1,%2,%3};"
        : "+f"(d[0]), "+f"(d[1]), "+f"(d[2]), "+f"(d[3])
        : "r"(a[0]), "r"(a[1]), "r"(a[2]), "r"(a[3]), "r"(b[0]), "r"(b[1]));
}

__device__ __forceinline__ void ldsm_x4(uint32_t& r0, uint32_t& r1, uint32_t& r2,
                                        uint32_t& r3, uint32_t addr) {
    asm volatile("ldmatrix.sync.aligned.m8n8.x4.shared.b16 {%0,%1,%2,%3}, [%4];"
                 : "=r"(r0), "=r"(r1), "=r"(r2), "=r"(r3) : "r"(addr));
}

__device__ __forceinline__ void bfsplit(float v, __nv_bfloat16& h, __nv_bfloat16& l) {
    h = __float2bfloat16(v);
    l = __float2bfloat16(v - __bfloat162float(h));
}

__device__ __forceinline__ void cpasync16(uint32_t dst, const void* src, int szvalid) {
    asm volatile("cp.async.cg.shared.global [%0], [%1], 16, %2;"
                 :: "r"(dst), "l"(src), "r"(szvalid) : "memory");
}
#define CPASYNC_COMMIT() asm volatile("cp.async.commit_group;" ::: "memory")
#define CPASYNC_WAIT(n)  asm volatile("cp.async.wait_group %0;" :: "n"(n) : "memory")

// ---------------- fp32 -> bf16 hi/lo split ----------------
__global__ void split_bf16_kernel(const float* __restrict__ x,
                                  __nv_bfloat16* __restrict__ hi,
                                  __nv_bfloat16* __restrict__ lo, int n4) {
    int i = blockIdx.x * 256 + threadIdx.x;
    if (i >= n4) return;
    float4 v = ((const float4*)x)[i];
    __nv_bfloat16 h0, h1, h2, h3, l0, l1, l2, l3;
    bfsplit(v.x, h0, l0); bfsplit(v.y, h1, l1);
    bfsplit(v.z, h2, l2); bfsplit(v.w, h3, l3);
    bf16x4 hv = {h0, h1, h2, h3};
    bf16x4 lv = {l0, l1, l2, l3};
    ((bf16x4*)hi)[i] = hv;
    ((bf16x4*)lo)[i] = lv;
}

// ---------------- tensor-core GEMM: C[M,N] = A[M,K] * B[N,K]^T (hi/lo x3) ----------------
// 4-stage cp.async ring, ONE barrier per k-step. 128x128 block, 8 warps.
#define GK 16
#define GPAD 24
#define NSTAGE 4
#define GEMM_SMEM (NSTAGE * 2 * 128 * GPAD * 2 * 2)   // 98304 bytes

__global__ __launch_bounds__(256, 2) void gemm_nt_bf16x3(
    const __nv_bfloat16* __restrict__ Ah, const __nv_bfloat16* __restrict__ Al,
    const __nv_bfloat16* __restrict__ Bh, const __nv_bfloat16* __restrict__ Bl,
    float* __restrict__ C, int M, int N, int K) {
    extern __shared__ __nv_bfloat16 smb[];
    __nv_bfloat16* sA = smb;
    __nv_bfloat16* sB = smb + NSTAGE * 2 * 128 * GPAD;

    const int tid = threadIdx.x;
    const int wid = tid >> 5, lane = tid & 31;
    const int wm = wid >> 2, wn = wid & 3;
    const int grp = lane >> 2, q2 = (lane & 3) * 2;
    const int rowBase = blockIdx.y * 128;
    const int colBase = blockIdx.x * 128;
    const int lrow = tid >> 1;
    const int lkh = (tid & 1) * 8;

    const int lmRow = lane & 15;
    const int lmK = (lane >> 4) << 3;

    const uint32_t sA_s = (uint32_t)__cvta_generic_to_shared(sA);
    const uint32_t sB_s = (uint32_t)__cvta_generic_to_shared(sB);

    float acc[4][4][4];
#pragma unroll
    for (int i = 0; i < 4; i++)
#pragma unroll
        for (int j = 0; j < 4; j++)
#pragma unroll
            for (int r = 0; r < 4; r++) acc[i][j][r] = 0.f;

    const int nk = K / GK;
#define SAIDX(st, hl, r, k) (((((st) * 2 + (hl)) * 128 + (r)) * GPAD) + (k))

    const __nv_bfloat16* pAh = Ah + (size_t)(rowBase + lrow) * K + lkh;
    const __nv_bfloat16* pAl = Al + (size_t)(rowBase + lrow) * K + lkh;
    int cn = colBase + lrow;
    int bok = (cn < N) ? 16 : 0;
    int cnc = (cn < N) ? cn : 0;
    const __nv_bfloat16* pBh = Bh + (size_t)cnc * K + lkh;
    const __nv_bfloat16* pBl = Bl + (size_t)cnc * K + lkh;

    auto load_stage = [&](int st, int kc) {
        int ko = kc * GK;
        cpasync16(sA_s + SAIDX(st, 0, lrow, lkh) * 2, pAh + ko, 16);
        cpasync16(sA_s + SAIDX(st, 1, lrow, lkh) * 2, pAl + ko, 16);
        cpasync16(sB_s + SAIDX(st, 0, lrow, lkh) * 2, pBh + ko, bok);
        cpasync16(sB_s + SAIDX(st, 1, lrow, lkh) * 2, pBl + ko, bok);
        CPASYNC_COMMIT();
    };

    load_stage(0, 0);
    if (nk > 1) load_stage(1, 1);

    for (int k = 0; k < nk; k++) {
        int st = k & (NSTAGE - 1);
        if (k + 2 < nk) {
            load_stage((k + 2) & (NSTAGE - 1), k + 2);
            CPASYNC_WAIT(2);
        } else if (k + 1 < nk) {
            CPASYNC_WAIT(1);
        } else {
            CPASYNC_WAIT(0);
        }
        __syncthreads();   // single barrier per k-step (4-stage ring makes WAR safe)

        uint32_t bh[4][2], bl[4][2];
        {
            uint32_t r0, r1, r2, r3;
            ldsm_x4(r0, r1, r2, r3, sB_s + SAIDX(st, 0, wn * 32 + lmRow, lmK) * 2);
            bh[0][0] = r0; bh[0][1] = r2; bh[1][0] = r1; bh[1][1] = r3;
            ldsm_x4(r0, r1, r2, r3, sB_s + SAIDX(st, 0, wn * 32 + 16 + lmRow, lmK) * 2);
            bh[2][0] = r0; bh[2][1] = r2; bh[3][0] = r1; bh[3][1] = r3;
            ldsm_x4(r0, r1, r2, r3, sB_s + SAIDX(st, 1, wn * 32 + lmRow, lmK) * 2);
            bl[0][0] = r0; bl[0][1] = r2; bl[1][0] = r1; bl[1][1] = r3;
            ldsm_x4(r0, r1, r2, r3, sB_s + SAIDX(st, 1, wn * 32 + 16 + lmRow, lmK) * 2);
            bl[2][0] = r0; bl[2][1] = r2; bl[3][0] = r1; bl[3][1] = r3;
        }
#pragma unroll
        for (int mt = 0; mt < 4; mt++) {
            int r0row = wm * 64 + mt * 16;
            uint32_t ah[4], al[4];
            ldsm_x4(ah[0], ah[1], ah[2], ah[3], sA_s + SAIDX(st, 0, r0row + lmRow, lmK) * 2);
            ldsm_x4(al[0], al[1], al[2], al[3], sA_s + SAIDX(st, 1, r0row + lmRow, lmK) * 2);
#pragma unroll
            for (int nt = 0; nt < 4; nt++) {
                mma16816(acc[mt][nt], ah, bh[nt]);
                mma16816(acc[mt][nt], ah, bl[nt]);
                mma16816(acc[mt][nt], al, bh[nt]);
            }
        }
        // no bottom barrier
    }
#pragma unroll
    for (int mt = 0; mt < 4; mt++) {
#pragma unroll
        for (int nt = 0; nt < 4; nt++) {
            int colTile = colBase + wn * 32 + nt * 8;
            if (colTile >= N) continue;
            int r0 = rowBase + wm * 64 + mt * 16 + grp;
            int c0 = colTile + q2;
            *(float2*)&C[(size_t)r0 * N + c0] = make_float2(acc[mt][nt][0], acc[mt][nt][1]);
            *(float2*)&C[(size_t)(r0 + 8) * N + c0] = make_float2(acc[mt][nt][2], acc[mt][nt][3]);
        }
    }
#undef SAIDX
}

// ---------------- conv1d (causal, depthwise, width 4) + SiLU : 4 t per thread ----------------
__global__ void conv_silu_kernel(const float* __restrict__ zx,
                                 const float* __restrict__ conv_w,
                                 const float* __restrict__ conv_b,
                                 float* __restrict__ xbc) {
    size_t idx = (size_t)blockIdx.x * 256 + threadIdx.x;
    const size_t total = (size_t)(MROWS / 4) * CONVD;
    if (idx >= total) return;
    int cc = (int)(idx % CONVD);
    size_t r4 = idx / CONVD;
    size_t bt0 = r4 * 4;
    int t0 = (int)(bt0 % L_SEQ);

    float w0 = conv_w[cc * 4 + 0], w1 = conv_w[cc * 4 + 1];
    float w2 = conv_w[cc * 4 + 2], w3 = conv_w[cc * 4 + 3];
    float bia = conv_b[cc];

    float v[7];
#pragma unroll
    for (int j = 0; j < 7; j++) {
        int tt = t0 - 3 + j;
        v[j] = (tt >= 0) ? zx[(bt0 - 3 + j) * DIP + 2048 + cc] : 0.f;
    }
#pragma unroll
    for (int i = 0; i < 4; i++) {
        float acc = bia;
        acc = fmaf(v[i + 0], w0, acc);
        acc = fmaf(v[i + 1], w1, acc);
        acc = fmaf(v[i + 2], w2, acc);
        acc = fmaf(v[i + 3], w3, acc);
        xbc[(bt0 + i) * CONVD + cc] = acc * fast_sigmoid(acc);
    }
}

// ---------------- K1: intra-chunk SSM on tensor cores (HMMA) ----------------
#define SB_S 136
#define ST_S 66
#define SM_K1_BYTES ((4 * 64 * SB_S + 2 * 128 * ST_S + 6 * 64 * ST_S) * 2 + \
                     (64 * ST_S + 2 * HPB * 64 + 64) * 4)

__global__ __launch_bounds__(256, 1) void ssm_intra_kernel(
    const float* __restrict__ zx, const float* __restrict__ xbc,
    const float* __restrict__ dt_bias, const float* __restrict__ A_log,
    const float* __restrict__ Dvec,
    float* __restrict__ y, float* __restrict__ states, float* __restrict__ cs_out) {
    extern __shared__ char smraw[];
    __nv_bfloat16* sBh = (__nv_bfloat16*)smraw;
    __nv_bfloat16* sBl = sBh + 64 * SB_S;
    __nv_bfloat16* sCh = sBl + 64 * SB_S;
    __nv_bfloat16* sCl = sCh + 64 * SB_S;
    __nv_bfloat16* sBTh = sCl + 64 * SB_S;
    __nv_bfloat16* sBTl = sBTh + 128 * ST_S;
    __nv_bfloat16* sGh = sBTl + 128 * ST_S;
    __nv_bfloat16* sGl = sGh + 64 * ST_S;
    __nv_bfloat16* sXh = sGl + 64 * ST_S;
    __nv_bfloat16* sXl = sXh + 64 * ST_S;
    __nv_bfloat16* sXdh = sXl + 64 * ST_S;
    __nv_bfloat16* sXdl = sXdh + 64 * ST_S;
    float* sG = (float*)(sXdl + 64 * ST_S);
    float* s_dt = sG + 64 * ST_S;
    float* s_cs = s_dt + HPB * 64;
    float* sEd = s_cs + HPB * 64;

    const int c = blockIdx.x, hg = blockIdx.y, b = blockIdx.z;
    const int h0 = hg * HPB;
    const int tid = threadIdx.x;
    const int wid = tid >> 5, lane = tid & 31;
    const int wm = wid >> 2, wn = wid & 3;
    const int grp = lane >> 2, q2 = (lane & 3) * 2;
    const int row0 = b * L_SEQ + c * TCH;
    const float* xrow = xbc + (size_t)row0 * CONVD;

    {
        int h = h0 + wid;
        float Ah = -__expf(A_log[h]);
        float bias = dt_bias[h];
        float d0 = zx[(size_t)(row0 + lane) * DIP + 4352 + h] + bias;
        float d1 = zx[(size_t)(row0 + 32 + lane) * DIP + 4352 + h] + bias;
        float dt0 = (d0 > 20.f) ? d0 : log1pf(__expf(d0));
        float dt1 = (d1 > 20.f) ? d1 : log1pf(__expf(d1));
        s_dt[wid * 64 + lane] = dt0;
        s_dt[wid * 64 + 32 + lane] = dt1;
        float v0 = dt0 * Ah, v1 = dt1 * Ah;
#pragma unroll
        for (int off = 1; off < 32; off <<= 1) {
            float n0 = __shfl_up_sync(0xffffffffu, v0, off);
            float n1 = __shfl_up_sync(0xffffffffu, v1, off);
            if (lane >= off) { v0 += n0; v1 += n1; }
        }
        v1 += __shfl_sync(0xffffffffu, v0, 31);
        s_cs[wid * 64 + lane] = v0;
        s_cs[wid * 64 + 32 + lane] = v1;
        size_t cbase = (((size_t)b * NC64 + c) * NH + h) * TCH;
        cs_out[cbase + lane] = v0;
        cs_out[cbase + 32 + lane] = v1;
    }

    for (int idx = tid; idx < 64 * 128; idx += 256) {
        int s = idx >> 7, n = idx & 127;
        float bv = xrow[(size_t)s * CONVD + 2048 + n];
        float cv = xrow[(size_t)s * CONVD + 2176 + n];
        __nv_bfloat16 bh, bl, ch, cl;
        bfsplit(bv, bh, bl);
        bfsplit(cv, ch, cl);
        sBh[s * SB_S + n] = bh; sBl[s * SB_S + n] = bl;
        sCh[s * SB_S + n] = ch; sCl[s * SB_S + n] = cl;
        sBTh[n * ST_S + s] = bh; sBTl[n * ST_S + s] = bl;
    }
    __syncthreads();

    {
        float g[2][2][4];
#pragma unroll
        for (int i = 0; i < 2; i++)
#pragma unroll
            for (int j = 0; j < 2; j++)
#pragma unroll
                for (int r = 0; r < 4; r++) g[i][j][r] = 0.f;
        for (int kb = 0; kb < 128; kb += 16) {
            uint32_t bh[2][2], bl[2][2];
#pragma unroll
            for (int nt = 0; nt < 2; nt++) {
                int c0 = wn * 16 + nt * 8 + grp;
                bh[nt][0] = *(const uint32_t*)&sBh[c0 * SB_S + kb + q2];
                bh[nt][1] = *(const uint32_t*)&sBh[c0 * SB_S + kb + q2 + 8];
                bl[nt][0] = *(const uint32_t*)&sBl[c0 * SB_S + kb + q2];
                bl[nt][1] = *(const uint32_t*)&sBl[c0 * SB_S + kb + q2 + 8];
            }
#pragma unroll
            for (int mt = 0; mt < 2; mt++) {
                int r0 = wm * 32 + mt * 16 + grp;
                uint32_t ah[4], al[4];
                ah[0] = *(const uint32_t*)&sCh[r0 * SB_S + kb + q2];
                ah[1] = *(const uint32_t*)&sCh[(r0 + 8) * SB_S + kb + q2];
                ah[2] = *(const uint32_t*)&sCh[r0 * SB_S + kb + q2 + 8];
                ah[3] = *(const uint32_t*)&sCh[(r0 + 8) * SB_S + kb + q2 + 8];
                al[0] = *(const uint32_t*)&sCl[r0 * SB_S + kb + q2];
                al[1] = *(const uint32_t*)&sCl[(r0 + 8) * SB_S + kb + q2];
                al[2] = *(const uint32_t*)&sCl[r0 * SB_S + kb + q2 + 8];
                al[3] = *(const uint32_t*)&sCl[(r0 + 8) * SB_S + kb + q2 + 8];
#pragma unroll
                for (int nt = 0; nt < 2; nt++) {
                    mma16816(g[mt][nt], ah, bh[nt]);
                    mma16816(g[mt][nt], ah, bl[nt]);
                    mma16816(g[mt][nt], al, bh[nt]);
                }
            }
        }
#pragma unroll
        for (int mt = 0; mt < 2; mt++)
#pragma unroll
            for (int nt = 0; nt < 2; nt++) {
                int t = wm * 32 + mt * 16 + grp;
                int s = wn * 16 + nt * 8 + q2;
                *(float2*)&sG[t * ST_S + s] = make_float2(g[mt][nt][0], g[mt][nt][1]);
                *(float2*)&sG[(t + 8) * ST_S + s] = make_float2(g[mt][nt][2], g[mt][nt][3]);
            }
    }

    for (int hl = 0; hl < HPB; hl++) {
        int h = h0 + hl;
        __syncthreads();
        const float* csh = s_cs + hl * 64;
        const float* dth = s_dt + hl * 64;
        const float csL = csh[63];
        if (tid < 64) sEd[tid] = __expf(csL - csh[tid]);
        for (int idx = tid; idx < 64 * 64; idx += 256) {
            int t = idx >> 6, s = idx & 63;
            float val = 0.f;
            if (t >= s) val = sG[t * ST_S + s] * __expf(csh[t] - csh[s]);
            __nv_bfloat16 hch, hcl;
            bfsplit(val, hch, hcl);
            sGh[t * ST_S + s] = hch;
            sGl[t * ST_S + s] = hcl;
        }
        __syncthreads();
        for (int idx = tid; idx < 64 * 64; idx += 256) {
            int s = idx >> 6, p = idx & 63;
            float xv = xrow[(size_t)s * CONVD + h * 64 + p];
            float xt = xv * dth[s];
            __nv_bfloat16 xh, xl, xdh, xdl;
            bfsplit(xt, xh, xl);
            bfsplit(xt * sEd[s], xdh, xdl);
            sXh[p * ST_S + s] = xh;  sXl[p * ST_S + s] = xl;
            sXdh[p * ST_S + s] = xdh; sXdl[p * ST_S + s] = xdl;
        }
        __syncthreads();

        {
            float yd[2][2][4];
#pragma unroll
            for (int i = 0; i < 2; i++)
#pragma unroll
                for (int j = 0; j < 2; j++)
#pragma unroll
                    for (int r = 0; r < 4; r++) yd[i][j][r] = 0.f;
            for (int kb = 0; kb < 64; kb += 16) {
                uint32_t bh[2][2], bl[2][2];
#pragma unroll
                for (int nt = 0; nt < 2; nt++) {
                    int c0 = wn * 16 + nt * 8 + grp;
                    bh[nt][0] = *(const uint32_t*)&sXh[c0 * ST_S + kb + q2];
                    bh[nt][1] = *(const uint32_t*)&sXh[c0 * ST_S + kb + q2 + 8];
                    bl[nt][0] = *(const uint32_t*)&sXl[c0 * ST_S + kb + q2];
                    bl[nt][1] = *(const uint32_t*)&sXl[c0 * ST_S + kb + q2 + 8];
                }
#pragma unroll
                for (int mt = 0; mt < 2; mt++) {
                    int r0 = wm * 32 + mt * 16 + grp;
                    uint32_t ah[4], al[4];
                    ah[0] = *(const uint32_t*)&sGh[r0 * ST_S + kb + q2];
                    ah[1] = *(const uint32_t*)&sGh[(r0 + 8) * ST_S + kb + q2];
                    ah[2] = *(const uint32_t*)&sGh[r0 * ST_S + kb + q2 + 8];
                    ah[3] = *(const uint32_t*)&sGh[(r0 + 8) * ST_S + kb + q2 + 8];
                    al[0] = *(const uint32_t*)&sGl[r0 * ST_S + kb + q2];
                    al[1] = *(const uint32_t*)&sGl[(r0 + 8) * ST_S + kb + q2];
                    al[2] = *(const uint32_t*)&sGl[r0 * ST_S + kb + q2 + 8];
                    al[3] = *(const uint32_t*)&sGl[(r0 + 8) * ST_S + kb + q2 + 8];
#pragma unroll
                    for (int nt = 0; nt < 2; nt++) {
                        mma16816(yd[mt][nt], ah, bh[nt]);
                        mma16816(yd[mt][nt], ah, bl[nt]);
                        mma16816(yd[mt][nt], al, bh[nt]);
                    }
                }
            }
            float Dh = Dvec[h];
#pragma unroll
            for (int mt = 0; mt < 2; mt++)
#pragma unroll
                for (int nt = 0; nt < 2; nt++) {
                    int t0 = wm * 32 + mt * 16 + grp;
                    int p0 = wn * 16 + nt * 8 + q2;
#pragma unroll
                    for (int rr = 0; rr < 2; rr++) {
                        int t = t0 + rr * 8;
                        float2 xv = *(const float2*)&xrow[(size_t)t * CONVD + h * 64 + p0];
                        float2 o;
                        o.x = fmaf(Dh, xv.x, yd[mt][nt][rr * 2 + 0]);
                        o.y = fmaf(Dh, xv.y, yd[mt][nt][rr * 2 + 1]);
                        *(float2*)&g_y[(size_t)(row0 + t) * DSSM + h * 64 + p0] = o;
                    }
                }
        }

        {
            float st[2][4][4];
#pragma unroll
            for (int i = 0; i < 2; i++)
#pragma unroll
                for (int j = 0; j < 4; j++)
#pragma unroll
                    for (int r = 0; r < 4; r++) st[i][j][r] = 0.f;
            for (int kb = 0; kb < 64; kb += 16) {
                uint32_t bh[4][2], bl[4][2];
#pragma unroll
                for (int nt = 0; nt < 4; nt++) {
                    int c0 = wn * 32 + nt * 8 + grp;
                    bh[nt][0] = *(const uint32_t*)&sBTh[c0 * ST_S + kb + q2];
                    bh[nt][1] = *(const uint32_t*)&sBTh[c0 * ST_S + kb + q2 + 8];
                    bl[nt][0] = *(const uint32_t*)&sBTl[c0 * ST_S + kb + q2];
                    bl[nt][1] = *(const uint32_t*)&sBTl[c0 * ST_S + kb + q2 + 8];
                }
#pragma unroll
                for (int mt = 0; mt < 2; mt++) {
                    int r0 = wm * 32 + mt * 16 + grp;
                    uint32_t ah[4], al[4];
                    ah[0] = *(const uint32_t*)&sXdh[r0 * ST_S + kb + q2];
                    ah[1] = *(const uint32_t*)&sXdh[(r0 + 8) * ST_S + kb + q2];
                    ah[2] = *(const uint32_t*)&sXdh[r0 * ST_S + kb + q2 + 8];
                    ah[3] = *(const uint32_t*)&sXdh[(r0 + 8) * ST_S + kb + q2 + 8];
                    al[0] = *(const uint32_t*)&sXdl[r0 * ST_S + kb + q2];
                    al[1] = *(const uint32_t*)&sXdl[(r0 + 8) * ST_S + kb + q2];
                    al[2] = *(const uint32_t*)&sXdl[r0 * ST_S + kb + q2 + 8];
                    al[3] = *(const uint32_t*)&sXdl[(r0 + 8) * ST_S + kb + q2 + 8];
#pragma unroll
                    for (int nt = 0; nt < 4; nt++) {
                        mma16816(st[mt][nt], ah, bh[nt]);
                        mma16816(st[mt][nt], ah, bl[nt]);
                        mma16816(st[mt][nt], al, bh[nt]);
                    }
                }
            }
            size_t sbase = (((size_t)b * NC64 + c) * NH + h) * (size_t)(HD * DS);
#pragma unroll
            for (int mt = 0; mt < 2; mt++)
#pragma unroll
                for (int nt = 0; nt < 4; nt++) {
                    int p0 = wm * 32 + mt * 16 + grp;
                    int n0 = wn * 32 + nt * 8 + q2;
                    *(float2*)&states[sbase + (size_t)p0 * DS + n0] =
                        make_float2(st[mt][nt][0], st[mt][nt][1]);
                    *(float2*)&states[sbase + (size_t)(p0 + 8) * DS + n0] =
                        make_float2(st[mt][nt][2], st[mt][nt][3]);
                }
        }
    }
}

// ---------------- K2: inter-chunk recurrence over 64 chunks ----------------
__global__ void chunk_scan64(const float* __restrict__ states,
                             const float* __restrict__ cs,
                             float* __restrict__ prev) {
    const int seg = blockIdx.x, h = blockIdx.y, b = blockIdx.z;
    const int e = seg * 256 + threadIdx.x;
    float P = 0.f;
    for (int c = 0; c < NC64; c++) {
        size_t base = ((size_t)b * NC64 + c) * NH + h;
        float sc = __expf(cs[base * TCH + TCH - 1]);
        size_t off = base * (size_t)(HD * DS) + e;
        prev[off] = P;
        P = fmaf(P, sc, states[off]);
    }
}

// ---------------- K3: Y += diag(exp(cs)) * C * prev^T on tensor cores ----------------
#define SM_K3_BYTES ((4 * 64 * SB_S) * 2 + 64 * 4)
__global__ __launch_bounds__(256, 1) void yoff64_kernel(
    const float* __restrict__ xbc, const float* __restrict__ prev,
    const float* __restrict__ cs, float* __restrict__ y) {
    extern __shared__ char smraw[];
    __nv_bfloat16* sCh = (__nv_bfloat16*)smraw;
    __nv_bfloat16* sCl = sCh + 64 * SB_S;
    __nv_bfloat16* sPh = sCl + 64 * SB_S;
    __nv_bfloat16* sPl = sPh + 64 * SB_S;
    float* sE = (float*)(sPl + 64 * SB_S);

    const int c = blockIdx.x, b = blockIdx.y;
    const int tid = threadIdx.x;
    const int wid = tid >> 5, lane = tid & 31;
    const int wm = wid >> 2, wn = wid & 3;
    const int grp = lane >> 2, q2 = (lane & 3) * 2;
    const int row0 = b * L_SEQ + c * TCH;
    const float* xrow = xbc + (size_t)row0 * CONVD;

    for (int idx = tid; idx < 64 * 128; idx += 256) {
        int t = idx >> 7, n = idx & 127;
        float cv = xrow[(size_t)t * CONVD + 2176 + n];
        __nv_bfloat16 ch, cl;
        bfsplit(cv, ch, cl);
        sCh[t * SB_S + n] = ch;
        sCl[t * SB_S + n] = cl;
    }

    for (int h = 0; h < NH; h++) {
        __syncthreads();
        if (tid < 64)
            sE[tid] = __expf(cs[(((size_t)b * NC64 + c) * NH + h) * TCH + tid]);
        size_t pbase = (((size_t)b * NC64 + c) * NH + h) * (size_t)(HD * DS);
        for (int idx = tid; idx < 64 * 128; idx += 256) {
            int p = idx >> 7, n = idx & 127;
            float pv = prev[pbase + (size_t)p * DS + n];
            __nv_bfloat16 ph, pl;
            bfsplit(pv, ph, pl);
            sPh[p * SB_S + n] = ph;
            sPl[p * SB_S + n] = pl;
        }
        __syncthreads();

        float acc[2][2][4];
#pragma unroll
        for (int i = 0; i < 2; i++)
#pragma unroll
            for (int j = 0; j < 2; j++)
#pragma unroll
                for (int r = 0; r < 4; r++) acc[i][j][r] = 0.f;
        for (int kb = 0; kb < 128; kb += 16) {
            uint32_t bh[2][2], bl[2][2];
#pragma unroll
            for (int nt = 0; nt < 2; nt++) {
                int c0 = wn * 16 + nt * 8 + grp;
                bh[nt][0] = *(const uint32_t*)&sPh[c0 * SB_S + kb + q2];
                bh[nt][1] = *(const uint32_t*)&sPh[c0 * SB_S + kb + q2 + 8];
                bl[nt][0] = *(const uint32_t*)&sPl[c0 * SB_S + kb + q2];
                bl[nt][1] = *(const uint32_t*)&sPl[c0 * SB_S + kb + q2 + 8];
            }
#pragma unroll
            for (int mt = 0; mt < 2; mt++) {
                int r0 = wm * 32 + mt * 16 + grp;
                uint32_t ah[4], al[4];
                ah[0] = *(const uint32_t*)&sCh[r0 * SB_S + kb + q2];
                ah[1] = *(const uint32_t*)&sCh[(r0 + 8) * SB_S + kb + q2];
                ah[2] = *(const uint32_t*)&sCh[r0 * SB_S + kb + q2 + 8];
                ah[3] = *(const uint32_t*)&sCh[(r0 + 8) * SB_S + kb + q2 + 8];
                al[0] = *(const uint32_t*)&sCl[r0 * SB_S + kb + q2];
                al[1] = *(const uint32_t*)&sCl[(r0 + 8) * SB_S + kb + q2];
                al[2] = *(const uint32_t*)&sCl[r0 * SB_S + kb + q2 + 8];
                al[3] = *(const uint32_t*)&sCl[(r0 + 8) * SB_S + kb + q2 + 8];
#pragma unroll
                for (int nt = 0; nt < 2; nt++) {
                    mma16816(acc[mt][nt], ah, bh[nt]);
                    mma16816(acc[mt][nt], ah, bl[nt]);
                    mma16816(acc[mt][nt], al, bh[nt]);
                }
            }
        }
#pragma unroll
        for (int mt = 0; mt < 2; mt++)
#pragma unroll
            for (int nt = 0; nt < 2; nt++) {
                int t0 = wm * 32 + mt * 16 + grp;
                int p0 = wn * 16 + nt * 8 + q2;
#pragma unroll
                for (int rr = 0; rr < 2; rr++) {
                    int t = t0 + rr * 8;
                    float e = sE[t];
                    size_t addr = (size_t)(row0 + t) * DSSM + h * 64 + p0;
                    float2 old = *(float2*)&y[addr];
                    old.x = fmaf(e, acc[mt][nt][rr * 2 + 0], old.x);
                    old.y = fmaf(e, acc[mt][nt][rr * 2 + 1], old.y);
                    *(float2*)&y[addr] = old;
                }
            }
    }
}

// ---------------- gate (y * silu(z)) + RMSNorm, fused bf16 hi/lo split ----------------
__global__ void gate_norm_kernel(const float* __restrict__ zx,
                                 const float* __restrict__ y,
                                 const float* __restrict__ norm_w,
                                 __nv_bfloat16* __restrict__ ynh,
                                 __nv_bfloat16* __restrict__ ynl) {
    const int row = blockIdx.x;
    const int tid = threadIdx.x;
    const float* yrow = y + (size_t)row * DSSM;
    const float* zrow = zx + (size_t)row * DIP;
    float v[8];
    float ss = 0.f;
#pragma unroll
    for (int k = 0; k < 8; k++) {
        int e = tid + k * 256;
        float z = zrow[e];
        float vv = yrow[e] * (z * fast_sigmoid(z));
        v[k] = vv;
        ss = fmaf(vv, vv, ss);
    }
    __shared__ float red[256];
    red[tid] = ss;
    __syncthreads();
    for (int s = 128; s > 0; s >>= 1) {
        if (tid < s) red[tid] += red[tid + s];
        __syncthreads();
    }
    float r = rsqrtf(red[0] / (float)DSSM + 1e-5f);
#pragma unroll
    for (int k = 0; k < 8; k++) {
        int e = tid + k * 256;
        float o = v[k] * r * norm_w[e];
        __nv_bfloat16 oh, ol;
        bfsplit(o, oh, ol);
        ynh[(size_t)row * DSSM + e] = oh;
        ynl[(size_t)row * DSSM + e] = ol;
    }
}

// ---------------- host launch ----------------
extern "C" void kernel_launch(void* const* d_in, const int* in_sizes, int n_in,
                              void* d_out, int out_size) {
    const float* u       = (const float*)d_in[0];
    const float* W_in    = (const float*)d_in[1];
    const float* conv_w  = (const float*)d_in[2];
    const float* conv_b  = (const float*)d_in[3];
    const float* dt_bias = (const float*)d_in[4];
    const float* A_log   = (const float*)d_in[5];
    const float* Dv      = (const float*)d_in[6];
    const float* norm_w  = (const float*)d_in[7];
    const float* W_out   = (const float*)d_in[8];
    float* out = (float*)d_out;

    void *p_zx, *p_xbc, *p_y, *p_states, *p_prev, *p_cs;
    void *p_uh, *p_ul, *p_wih, *p_wil, *p_ynh, *p_ynl, *p_woh, *p_wol;
    cudaGetSymbolAddress(&p_zx, g_zx);
    cudaGetSymbolAddress(&p_xbc, g_xbc);
    cudaGetSymbolAddress(&p_y, g_y);
    cudaGetSymbolAddress(&p_states, g_states);
    cudaGetSymbolAddress(&p_prev, g_prev);
    cudaGetSymbolAddress(&p_cs, g_cs);
    cudaGetSymbolAddress(&p_uh, g_uh);
    cudaGetSymbolAddress(&p_ul, g_ul);
    cudaGetSymbolAddress(&p_wih, g_wih);
    cudaGetSymbolAddress(&p_wil, g_wil);
    cudaGetSymbolAddress(&p_ynh, g_ynh);
    cudaGetSymbolAddress(&p_ynl, g_ynl);
    cudaGetSymbolAddress(&p_woh, g_woh);
    cudaGetSymbolAddress(&p_wol, g_wol);
    float* zx = (float*)p_zx;
    float* xbc = (float*)p_xbc;
    float* y = (float*)p_y;
    float* states = (float*)p_states;
    float* prev = (float*)p_prev;
    float* cs = (float*)p_cs;
    __nv_bfloat16* uh = (__nv_bfloat16*)p_uh;
    __nv_bfloat16* ul = (__nv_bfloat16*)p_ul;
    __nv_bfloat16* wih = (__nv_bfloat16*)p_wih;
    __nv_bfloat16* wil = (__nv_bfloat16*)p_wil;
    __nv_bfloat16* ynh = (__nv_bfloat16*)p_ynh;
    __nv_bfloat16* ynl = (__nv_bfloat16*)p_ynl;
    __nv_bfloat16* woh = (__nv_bfloat16*)p_woh;
    __nv_bfloat16* wol = (__nv_bfloat16*)p_wol;

    cudaFuncSetAttribute(gemm_nt_bf16x3, cudaFuncAttributeMaxDynamicSharedMemorySize,
                         GEMM_SMEM);
    cudaFuncSetAttribute(ssm_intra_kernel, cudaFuncAttributeMaxDynamicSharedMemorySize,
                         SM_K1_BYTES);
    cudaFuncSetAttribute(yoff64_kernel, cudaFuncAttributeMaxDynamicSharedMemorySize,
                         SM_K3_BYTES);

    // 0. split inputs to bf16 hi/lo
    {
        int n4 = MROWS * D_MODEL / 4;
        split_bf16_kernel<<<(n4 + 255) / 256, 256>>>(u, uh, ul, n4);
        n4 = DIP * D_MODEL / 4;
        split_bf16_kernel<<<(n4 + 255) / 256, 256>>>(W_in, wih, wil, n4);
        n4 = D_MODEL * DSSM / 4;
        split_bf16_kernel<<<(n4 + 255) / 256, 256>>>(W_out, woh, wol, n4);
    }

    // 1. in_proj
    gemm_nt_bf16x3<<<dim3((DIP + 127) / 128, MROWS / 128), 256, GEMM_SMEM>>>(
        uh, ul, wih, wil, zx, MROWS, DIP, D_MODEL);

    // 2. conv1d + silu (4 t per thread)
    {
        size_t total4 = (size_t)(MROWS / 4) * CONVD;
        conv_silu_kernel<<<(unsigned)((total4 + 255) / 256), 256>>>(zx, conv_w, conv_b, xbc);
    }

    // 3. intra-chunk SSM
    ssm_intra_kernel<<<dim3(NC64, NH / HPB, BATCH), 256, SM_K1_BYTES>>>(
        zx, xbc, dt_bias, A_log, Dv, y, states, cs);

    // 4. inter-chunk recurrence
    chunk_scan64<<<dim3(32, NH, BATCH), 256>>>(states, cs, prev);

    // 5. Y_off
    yoff64_kernel<<<dim3(NC64, BATCH), 256, SM_K3_BYTES>>>(xbc, prev, cs, y);

    // 6. gate + RMSNorm + fused split
    gate_norm_kernel<<<MROWS, 256>>>(zx, y, norm_w, ynh, ynl);

    // 7. out_proj
    gemm_nt_bf16x3<<<dim3(D_MODEL / 128, MROWS / 128), 256, GEMM_SMEM>>>(
        ynh, ynl, woh, wol, out, MROWS, D_MODEL, DSSM);
}

// round 9
// speedup vs baseline: 2.5313x; 1.1903x over previous
#include <cuda_runtime.h>
#include <cuda_bf16.h>
#include <cuda_fp16.h>
#include <math.h>
#include <stdint.h>

#define BATCH 2
#define L_SEQ 4096
#define D_MODEL 1024
#define DIP 4384          // D_IN_PROJ
#define DSSM 2048
#define CONVD 2304        // CONV_DIM
#define NH 32
#define HD 64
#define DS 128
#define NC64 64           // chunks of 64 per batch
#define TCH 64
#define HPB 8             // heads per block in ssm_intra
#define MROWS (BATCH * L_SEQ)   // 8192

// ---------------- scratch (device globals; no allocation) ----------------
__device__ float g_zx[(size_t)MROWS * DIP];
__device__ float g_xbc[(size_t)MROWS * CONVD];
__device__ float g_y[(size_t)MROWS * DSSM];
__device__ float g_states[(size_t)BATCH * NC64 * NH * HD * DS];
__device__ float g_prev[(size_t)BATCH * NC64 * NH * HD * DS];
__device__ float g_cs[(size_t)BATCH * NC64 * NH * TCH];

// fp16 buffers for projection GEMMs (A hi/lo split, B single)
__device__ __half g_uh[(size_t)MROWS * D_MODEL];
__device__ __half g_ul[(size_t)MROWS * D_MODEL];
__device__ __half g_wih[(size_t)DIP * D_MODEL];
__device__ __half g_ynh[(size_t)MROWS * DSSM];
__device__ __half g_ynl[(size_t)MROWS * DSSM];
__device__ __half g_woh[(size_t)D_MODEL * DSSM];

// ---------------- helpers ----------------
struct alignas(8) half4 { __half a, b, c, d; };

__device__ __forceinline__ float fast_sigmoid(float x) {
    return 1.f / (1.f + __expf(-x));
}

// bf16 mma (SSM kernels)
__device__ __forceinline__ void mma16816(float* d, const uint32_t* a, const uint32_t* b) {
    asm volatile(
        "mma.sync.aligned.m16n8k16.row.col.f32.bf16.bf16.f32 "
        "{%0,%1,%2,%3}, {%4,%5,%6,%7}, {%8,%9}, {%0,%1,%2,%3};"
        : "+f"(d[0]), "+f"(d[1]), "+f"(d[2]), "+f"(d[3])
        : "r"(a[0]), "r"(a[1]), "r"(a[2]), "r"(a[3]), "r"(b[0]), "r"(b[1]));
}

// fp16 mma (projection GEMMs)
__device__ __forceinline__ void mma16816h(float* d, const uint32_t* a, const uint32_t* b) {
    asm volatile(
        "mma.sync.aligned.m16n8k16.row.col.f32.f16.f16.f32 "
        "{%0,%1,%2,%3}, {%4,%5,%6,%7}, {%8,%9}, {%0,%1,%2,%3};"
        : "+f"(d[0]), "+f"(d[1]), "+f"(d[2]), "+f"(d[3])
        : "r"(a[0]), "r"(a[1]), "r"(a[2]), "r"(a[3]), "r"(b[0]), "r"(b[1]));
}

__device__ __forceinline__ void ldsm_x4(uint32_t& r0, uint32_t& r1, uint32_t& r2,
                                        uint32_t& r3, uint32_t addr) {
    asm volatile("ldmatrix.sync.aligned.m8n8.x4.shared.b16 {%0,%1,%2,%3}, [%4];"
                 : "=r"(r0), "=r"(r1), "=r"(r2), "=r"(r3) : "r"(addr));
}

__device__ __forceinline__ void bfsplit(float v, __nv_bfloat16& h, __nv_bfloat16& l) {
    h = __float2bfloat16(v);
    l = __float2bfloat16(v - __bfloat162float(h));
}

__device__ __forceinline__ void hsplit(float v, __half& h, __half& l) {
    h = __float2half(v);
    l = __float2half(v - __half2float(h));
}

__device__ __forceinline__ void cpasync16(uint32_t dst, const void* src, int szvalid) {
    asm volatile("cp.async.cg.shared.global [%0], [%1], 16, %2;"
                 :: "r"(dst), "l"(src), "r"(szvalid) : "memory");
}
#define CPASYNC_COMMIT() asm volatile("cp.async.commit_group;" ::: "memory")
#define CPASYNC_WAIT(n)  asm volatile("cp.async.wait_group %0;" :: "n"(n) : "memory")

// ---------------- fp32 -> fp16 hi/lo split ----------------
__global__ void split_fp16_kernel(const float* __restrict__ x,
                                  __half* __restrict__ hi,
                                  __half* __restrict__ lo, int n4) {
    int i = blockIdx.x * 256 + threadIdx.x;
    if (i >= n4) return;
    float4 v = ((const float4*)x)[i];
    __half h0, h1, h2, h3, l0, l1, l2, l3;
    hsplit(v.x, h0, l0); hsplit(v.y, h1, l1);
    hsplit(v.z, h2, l2); hsplit(v.w, h3, l3);
    half4 hv = {h0, h1, h2, h3};
    half4 lv = {l0, l1, l2, l3};
    ((half4*)hi)[i] = hv;
    ((half4*)lo)[i] = lv;
}

// ---------------- fp32 -> fp16 single convert (weights) ----------------
__global__ void conv_fp16_kernel(const float* __restrict__ x,
                                 __half* __restrict__ o, int n4) {
    int i = blockIdx.x * 256 + threadIdx.x;
    if (i >= n4) return;
    float4 v = ((const float4*)x)[i];
    half4 hv = {__float2half(v.x), __float2half(v.y),
                __float2half(v.z), __float2half(v.w)};
    ((half4*)o)[i] = hv;
}

// ---------------- fp16 2-pass GEMM: C[M,N] = (Ah+Al)[M,K] * B[N,K]^T ----------------
// 4-stage cp.async ring, single barrier per k-step, ldmatrix fragments.
#define GK 16
#define GPAD 24
#define NSTAGE 4
#define GEMM_SMEM (NSTAGE * 3 * 128 * GPAD * 2)   // 73728 bytes (Ah,Al,B per stage)

__global__ __launch_bounds__(256, 2) void gemm_nt_fp16x2(
    const __half* __restrict__ Ah, const __half* __restrict__ Al,
    const __half* __restrict__ B,
    float* __restrict__ C, int M, int N, int K) {
    extern __shared__ __half smh[];
    __half* sA = smh;                                  // NSTAGE x 2 x 128 x GPAD
    __half* sB = smh + NSTAGE * 2 * 128 * GPAD;        // NSTAGE x 128 x GPAD

    const int tid = threadIdx.x;
    const int wid = tid >> 5, lane = tid & 31;
    const int wm = wid >> 2, wn = wid & 3;
    const int grp = lane >> 2, q2 = (lane & 3) * 2;
    const int rowBase = blockIdx.y * 128;
    const int colBase = blockIdx.x * 128;
    const int lrow = tid >> 1;
    const int lkh = (tid & 1) * 8;

    const int lmRow = lane & 15;
    const int lmK = (lane >> 4) << 3;

    const uint32_t sA_s = (uint32_t)__cvta_generic_to_shared(sA);
    const uint32_t sB_s = (uint32_t)__cvta_generic_to_shared(sB);

    float acc[4][4][4];
#pragma unroll
    for (int i = 0; i < 4; i++)
#pragma unroll
        for (int j = 0; j < 4; j++)
#pragma unroll
            for (int r = 0; r < 4; r++) acc[i][j][r] = 0.f;

    const int nk = K / GK;
#define SAIDX(st, hl, r, k) (((((st) * 2 + (hl)) * 128 + (r)) * GPAD) + (k))
#define SBIDX(st, r, k) ((((st) * 128 + (r)) * GPAD) + (k))

    const __half* pAh = Ah + (size_t)(rowBase + lrow) * K + lkh;
    const __half* pAl = Al + (size_t)(rowBase + lrow) * K + lkh;
    int cn = colBase + lrow;
    int bok = (cn < N) ? 16 : 0;
    int cnc = (cn < N) ? cn : 0;
    const __half* pB = B + (size_t)cnc * K + lkh;

    auto load_stage = [&](int st, int kc) {
        int ko = kc * GK;
        cpasync16(sA_s + SAIDX(st, 0, lrow, lkh) * 2, pAh + ko, 16);
        cpasync16(sA_s + SAIDX(st, 1, lrow, lkh) * 2, pAl + ko, 16);
        cpasync16(sB_s + SBIDX(st, lrow, lkh) * 2, pB + ko, bok);
        CPASYNC_COMMIT();
    };

    load_stage(0, 0);
    if (nk > 1) load_stage(1, 1);

    for (int k = 0; k < nk; k++) {
        int st = k & (NSTAGE - 1);
        if (k + 2 < nk) {
            load_stage((k + 2) & (NSTAGE - 1), k + 2);
            CPASYNC_WAIT(2);
        } else if (k + 1 < nk) {
            CPASYNC_WAIT(1);
        } else {
            CPASYNC_WAIT(0);
        }
        __syncthreads();   // single barrier per k-step (4-stage ring)

        uint32_t bb[4][2];
        {
            uint32_t r0, r1, r2, r3;
            ldsm_x4(r0, r1, r2, r3, sB_s + SBIDX(st, wn * 32 + lmRow, lmK) * 2);
            bb[0][0] = r0; bb[0][1] = r2; bb[1][0] = r1; bb[1][1] = r3;
            ldsm_x4(r0, r1, r2, r3, sB_s + SBIDX(st, wn * 32 + 16 + lmRow, lmK) * 2);
            bb[2][0] = r0; bb[2][1] = r2; bb[3][0] = r1; bb[3][1] = r3;
        }
#pragma unroll
        for (int mt = 0; mt < 4; mt++) {
            int r0row = wm * 64 + mt * 16;
            uint32_t ah[4], al[4];
            ldsm_x4(ah[0], ah[1], ah[2], ah[3], sA_s + SAIDX(st, 0, r0row + lmRow, lmK) * 2);
            ldsm_x4(al[0], al[1], al[2], al[3], sA_s + SAIDX(st, 1, r0row + lmRow, lmK) * 2);
#pragma unroll
            for (int nt = 0; nt < 4; nt++) {
                mma16816h(acc[mt][nt], ah, bb[nt]);
                mma16816h(acc[mt][nt], al, bb[nt]);
            }
        }
    }
#pragma unroll
    for (int mt = 0; mt < 4; mt++) {
#pragma unroll
        for (int nt = 0; nt < 4; nt++) {
            int colTile = colBase + wn * 32 + nt * 8;
            if (colTile >= N) continue;
            int r0 = rowBase + wm * 64 + mt * 16 + grp;
            int c0 = colTile + q2;
            *(float2*)&C[(size_t)r0 * N + c0] = make_float2(acc[mt][nt][0], acc[mt][nt][1]);
            *(float2*)&C[(size_t)(r0 + 8) * N + c0] = make_float2(acc[mt][nt][2], acc[mt][nt][3]);
        }
    }
#undef SAIDX
#undef SBIDX
}

// ---------------- conv1d (causal, depthwise, width 4) + SiLU : 4 t per thread ----------------
__global__ void conv_silu_kernel(const float* __restrict__ zx,
                                 const float* __restrict__ conv_w,
                                 const float* __restrict__ conv_b,
                                 float* __restrict__ xbc) {
    size_t idx = (size_t)blockIdx.x * 256 + threadIdx.x;
    const size_t total = (size_t)(MROWS / 4) * CONVD;
    if (idx >= total) return;
    int cc = (int)(idx % CONVD);
    size_t r4 = idx / CONVD;
    size_t bt0 = r4 * 4;
    int t0 = (int)(bt0 % L_SEQ);

    float w0 = conv_w[cc * 4 + 0], w1 = conv_w[cc * 4 + 1];
    float w2 = conv_w[cc * 4 + 2], w3 = conv_w[cc * 4 + 3];
    float bia = conv_b[cc];

    float v[7];
#pragma unroll
    for (int j = 0; j < 7; j++) {
        int tt = t0 - 3 + j;
        v[j] = (tt >= 0) ? zx[(bt0 - 3 + j) * DIP + 2048 + cc] : 0.f;
    }
#pragma unroll
    for (int i = 0; i < 4; i++) {
        float acc = bia;
        acc = fmaf(v[i + 0], w0, acc);
        acc = fmaf(v[i + 1], w1, acc);
        acc = fmaf(v[i + 2], w2, acc);
        acc = fmaf(v[i + 3], w3, acc);
        xbc[(bt0 + i) * CONVD + cc] = acc * fast_sigmoid(acc);
    }
}

// ---------------- K1: intra-chunk SSM on tensor cores (bf16 x3) ----------------
#define SB_S 136
#define ST_S 66
#define SM_K1_BYTES ((4 * 64 * SB_S + 2 * 128 * ST_S + 6 * 64 * ST_S) * 2 + \
                     (64 * ST_S + 2 * HPB * 64 + 64) * 4)

__global__ __launch_bounds__(256, 1) void ssm_intra_kernel(
    const float* __restrict__ zx, const float* __restrict__ xbc,
    const float* __restrict__ dt_bias, const float* __restrict__ A_log,
    const float* __restrict__ Dvec,
    float* __restrict__ y, float* __restrict__ states, float* __restrict__ cs_out) {
    extern __shared__ char smraw[];
    __nv_bfloat16* sBh = (__nv_bfloat16*)smraw;
    __nv_bfloat16* sBl = sBh + 64 * SB_S;
    __nv_bfloat16* sCh = sBl + 64 * SB_S;
    __nv_bfloat16* sCl = sCh + 64 * SB_S;
    __nv_bfloat16* sBTh = sCl + 64 * SB_S;
    __nv_bfloat16* sBTl = sBTh + 128 * ST_S;
    __nv_bfloat16* sGh = sBTl + 128 * ST_S;
    __nv_bfloat16* sGl = sGh + 64 * ST_S;
    __nv_bfloat16* sXh = sGl + 64 * ST_S;
    __nv_bfloat16* sXl = sXh + 64 * ST_S;
    __nv_bfloat16* sXdh = sXl + 64 * ST_S;
    __nv_bfloat16* sXdl = sXdh + 64 * ST_S;
    float* sG = (float*)(sXdl + 64 * ST_S);
    float* s_dt = sG + 64 * ST_S;
    float* s_cs = s_dt + HPB * 64;
    float* sEd = s_cs + HPB * 64;

    const int c = blockIdx.x, hg = blockIdx.y, b = blockIdx.z;
    const int h0 = hg * HPB;
    const int tid = threadIdx.x;
    const int wid = tid >> 5, lane = tid & 31;
    const int wm = wid >> 2, wn = wid & 3;
    const int grp = lane >> 2, q2 = (lane & 3) * 2;
    const int row0 = b * L_SEQ + c * TCH;
    const float* xrow = xbc + (size_t)row0 * CONVD;

    {
        int h = h0 + wid;
        float Ah = -__expf(A_log[h]);
        float bias = dt_bias[h];
        float d0 = zx[(size_t)(row0 + lane) * DIP + 4352 + h] + bias;
        float d1 = zx[(size_t)(row0 + 32 + lane) * DIP + 4352 + h] + bias;
        float dt0 = (d0 > 20.f) ? d0 : log1pf(__expf(d0));
        float dt1 = (d1 > 20.f) ? d1 : log1pf(__expf(d1));
        s_dt[wid * 64 + lane] = dt0;
        s_dt[wid * 64 + 32 + lane] = dt1;
        float v0 = dt0 * Ah, v1 = dt1 * Ah;
#pragma unroll
        for (int off = 1; off < 32; off <<= 1) {
            float n0 = __shfl_up_sync(0xffffffffu, v0, off);
            float n1 = __shfl_up_sync(0xffffffffu, v1, off);
            if (lane >= off) { v0 += n0; v1 += n1; }
        }
        v1 += __shfl_sync(0xffffffffu, v0, 31);
        s_cs[wid * 64 + lane] = v0;
        s_cs[wid * 64 + 32 + lane] = v1;
        size_t cbase = (((size_t)b * NC64 + c) * NH + h) * TCH;
        cs_out[cbase + lane] = v0;
        cs_out[cbase + 32 + lane] = v1;
    }

    for (int idx = tid; idx < 64 * 128; idx += 256) {
        int s = idx >> 7, n = idx & 127;
        float bv = xrow[(size_t)s * CONVD + 2048 + n];
        float cv = xrow[(size_t)s * CONVD + 2176 + n];
        __nv_bfloat16 bh, bl, ch, cl;
        bfsplit(bv, bh, bl);
        bfsplit(cv, ch, cl);
        sBh[s * SB_S + n] = bh; sBl[s * SB_S + n] = bl;
        sCh[s * SB_S + n] = ch; sCl[s * SB_S + n] = cl;
        sBTh[n * ST_S + s] = bh; sBTl[n * ST_S + s] = bl;
    }
    __syncthreads();

    {
        float g[2][2][4];
#pragma unroll
        for (int i = 0; i < 2; i++)
#pragma unroll
            for (int j = 0; j < 2; j++)
#pragma unroll
                for (int r = 0; r < 4; r++) g[i][j][r] = 0.f;
        for (int kb = 0; kb < 128; kb += 16) {
            uint32_t bh[2][2], bl[2][2];
#pragma unroll
            for (int nt = 0; nt < 2; nt++) {
                int c0 = wn * 16 + nt * 8 + grp;
                bh[nt][0] = *(const uint32_t*)&sBh[c0 * SB_S + kb + q2];
                bh[nt][1] = *(const uint32_t*)&sBh[c0 * SB_S + kb + q2 + 8];
                bl[nt][0] = *(const uint32_t*)&sBl[c0 * SB_S + kb + q2];
                bl[nt][1] = *(const uint32_t*)&sBl[c0 * SB_S + kb + q2 + 8];
            }
#pragma unroll
            for (int mt = 0; mt < 2; mt++) {
                int r0 = wm * 32 + mt * 16 + grp;
                uint32_t ah[4], al[4];
                ah[0] = *(const uint32_t*)&sCh[r0 * SB_S + kb + q2];
                ah[1] = *(const uint32_t*)&sCh[(r0 + 8) * SB_S + kb + q2];
                ah[2] = *(const uint32_t*)&sCh[r0 * SB_S + kb + q2 + 8];
                ah[3] = *(const uint32_t*)&sCh[(r0 + 8) * SB_S + kb + q2 + 8];
                al[0] = *(const uint32_t*)&sCl[r0 * SB_S + kb + q2];
                al[1] = *(const uint32_t*)&sCl[(r0 + 8) * SB_S + kb + q2];
                al[2] = *(const uint32_t*)&sCl[r0 * SB_S + kb + q2 + 8];
                al[3] = *(const uint32_t*)&sCl[(r0 + 8) * SB_S + kb + q2 + 8];
#pragma unroll
                for (int nt = 0; nt < 2; nt++) {
                    mma16816(g[mt][nt], ah, bh[nt]);
                    mma16816(g[mt][nt], ah, bl[nt]);
                    mma16816(g[mt][nt], al, bh[nt]);
                }
            }
        }
#pragma unroll
        for (int mt = 0; mt < 2; mt++)
#pragma unroll
            for (int nt = 0; nt < 2; nt++) {
                int t = wm * 32 + mt * 16 + grp;
                int s = wn * 16 + nt * 8 + q2;
                *(float2*)&sG[t * ST_S + s] = make_float2(g[mt][nt][0], g[mt][nt][1]);
                *(float2*)&sG[(t + 8) * ST_S + s] = make_float2(g[mt][nt][2], g[mt][nt][3]);
            }
    }

    for (int hl = 0; hl < HPB; hl++) {
        int h = h0 + hl;
        __syncthreads();
        const float* csh = s_cs + hl * 64;
        const float* dth = s_dt + hl * 64;
        const float csL = csh[63];
        if (tid < 64) sEd[tid] = __expf(csL - csh[tid]);
        for (int idx = tid; idx < 64 * 64; idx += 256) {
            int t = idx >> 6, s = idx & 63;
            float val = 0.f;
            if (t >= s) val = sG[t * ST_S + s] * __expf(csh[t] - csh[s]);
            __nv_bfloat16 hch, hcl;
            bfsplit(val, hch, hcl);
            sGh[t * ST_S + s] = hch;
            sGl[t * ST_S + s] = hcl;
        }
        __syncthreads();
        for (int idx = tid; idx < 64 * 64; idx += 256) {
            int s = idx >> 6, p = idx & 63;
            float xv = xrow[(size_t)s * CONVD + h * 64 + p];
            float xt = xv * dth[s];
            __nv_bfloat16 xh, xl, xdh, xdl;
            bfsplit(xt, xh, xl);
            bfsplit(xt * sEd[s], xdh, xdl);
            sXh[p * ST_S + s] = xh;  sXl[p * ST_S + s] = xl;
            sXdh[p * ST_S + s] = xdh; sXdl[p * ST_S + s] = xdl;
        }
        __syncthreads();

        {
            float yd[2][2][4];
#pragma unroll
            for (int i = 0; i < 2; i++)
#pragma unroll
                for (int j = 0; j < 2; j++)
#pragma unroll
                    for (int r = 0; r < 4; r++) yd[i][j][r] = 0.f;
            for (int kb = 0; kb < 64; kb += 16) {
                uint32_t bh[2][2], bl[2][2];
#pragma unroll
                for (int nt = 0; nt < 2; nt++) {
                    int c0 = wn * 16 + nt * 8 + grp;
                    bh[nt][0] = *(const uint32_t*)&sXh[c0 * ST_S + kb + q2];
                    bh[nt][1] = *(const uint32_t*)&sXh[c0 * ST_S + kb + q2 + 8];
                    bl[nt][0] = *(const uint32_t*)&sXl[c0 * ST_S + kb + q2];
                    bl[nt][1] = *(const uint32_t*)&sXl[c0 * ST_S + kb + q2 + 8];
                }
#pragma unroll
                for (int mt = 0; mt < 2; mt++) {
                    int r0 = wm * 32 + mt * 16 + grp;
                    uint32_t ah[4], al[4];
                    ah[0] = *(const uint32_t*)&sGh[r0 * ST_S + kb + q2];
                    ah[1] = *(const uint32_t*)&sGh[(r0 + 8) * ST_S + kb + q2];
                    ah[2] = *(const uint32_t*)&sGh[r0 * ST_S + kb + q2 + 8];
                    ah[3] = *(const uint32_t*)&sGh[(r0 + 8) * ST_S + kb + q2 + 8];
                    al[0] = *(const uint32_t*)&sGl[r0 * ST_S + kb + q2];
                    al[1] = *(const uint32_t*)&sGl[(r0 + 8) * ST_S + kb + q2];
                    al[2] = *(const uint32_t*)&sGl[r0 * ST_S + kb + q2 + 8];
                    al[3] = *(const uint32_t*)&sGl[(r0 + 8) * ST_S + kb + q2 + 8];
#pragma unroll
                    for (int nt = 0; nt < 2; nt++) {
                        mma16816(yd[mt][nt], ah, bh[nt]);
                        mma16816(yd[mt][nt], ah, bl[nt]);
                        mma16816(yd[mt][nt], al, bh[nt]);
                    }
                }
            }
            float Dh = Dvec[h];
#pragma unroll
            for (int mt = 0; mt < 2; mt++)
#pragma unroll
                for (int nt = 0; nt < 2; nt++) {
                    int t0 = wm * 32 + mt * 16 + grp;
                    int p0 = wn * 16 + nt * 8 + q2;
#pragma unroll
                    for (int rr = 0; rr < 2; rr++) {
                        int t = t0 + rr * 8;
                        float2 xv = *(const float2*)&xrow[(size_t)t * CONVD + h * 64 + p0];
                        float2 o;
                        o.x = fmaf(Dh, xv.x, yd[mt][nt][rr * 2 + 0]);
                        o.y = fmaf(Dh, xv.y, yd[mt][nt][rr * 2 + 1]);
                        *(float2*)&g_y[(size_t)(row0 + t) * DSSM + h * 64 + p0] = o;
                    }
                }
        }

        {
            float st[2][4][4];
#pragma unroll
            for (int i = 0; i < 2; i++)
#pragma unroll
                for (int j = 0; j < 4; j++)
#pragma unroll
                    for (int r = 0; r < 4; r++) st[i][j][r] = 0.f;
            for (int kb = 0; kb < 64; kb += 16) {
                uint32_t bh[4][2], bl[4][2];
#pragma unroll
                for (int nt = 0; nt < 4; nt++) {
                    int c0 = wn * 32 + nt * 8 + grp;
                    bh[nt][0] = *(const uint32_t*)&sBTh[c0 * ST_S + kb + q2];
                    bh[nt][1] = *(const uint32_t*)&sBTh[c0 * ST_S + kb + q2 + 8];
                    bl[nt][0] = *(const uint32_t*)&sBTl[c0 * ST_S + kb + q2];
                    bl[nt][1] = *(const uint32_t*)&sBTl[c0 * ST_S + kb + q2 + 8];
                }
#pragma unroll
                for (int mt = 0; mt < 2; mt++) {
                    int r0 = wm * 32 + mt * 16 + grp;
                    uint32_t ah[4], al[4];
                    ah[0] = *(const uint32_t*)&sXdh[r0 * ST_S + kb + q2];
                    ah[1] = *(const uint32_t*)&sXdh[(r0 + 8) * ST_S + kb + q2];
                    ah[2] = *(const uint32_t*)&sXdh[r0 * ST_S + kb + q2 + 8];
                    ah[3] = *(const uint32_t*)&sXdh[(r0 + 8) * ST_S + kb + q2 + 8];
                    al[0] = *(const uint32_t*)&sXdl[r0 * ST_S + kb + q2];
                    al[1] = *(const uint32_t*)&sXdl[(r0 + 8) * ST_S + kb + q2];
                    al[2] = *(const uint32_t*)&sXdl[r0 * ST_S + kb + q2 + 8];
                    al[3] = *(const uint32_t*)&sXdl[(r0 + 8) * ST_S + kb + q2 + 8];
#pragma unroll
                    for (int nt = 0; nt < 4; nt++) {
                        mma16816(st[mt][nt], ah, bh[nt]);
                        mma16816(st[mt][nt], ah, bl[nt]);
                        mma16816(st[mt][nt], al, bh[nt]);
                    }
                }
            }
            size_t sbase = (((size_t)b * NC64 + c) * NH + h) * (size_t)(HD * DS);
#pragma unroll
            for (int mt = 0; mt < 2; mt++)
#pragma unroll
                for (int nt = 0; nt < 4; nt++) {
                    int p0 = wm * 32 + mt * 16 + grp;
                    int n0 = wn * 32 + nt * 8 + q2;
                    *(float2*)&states[sbase + (size_t)p0 * DS + n0] =
                        make_float2(st[mt][nt][0], st[mt][nt][1]);
                    *(float2*)&states[sbase + (size_t)(p0 + 8) * DS + n0] =
                        make_float2(st[mt][nt][2], st[mt][nt][3]);
                }
        }
    }
}

// ---------------- K2: inter-chunk recurrence over 64 chunks ----------------
__global__ void chunk_scan64(const float* __restrict__ states,
                             const float* __restrict__ cs,
                             float* __restrict__ prev) {
    const int seg = blockIdx.x, h = blockIdx.y, b = blockIdx.z;
    const int e = seg * 256 + threadIdx.x;
    float P = 0.f;
    for (int c = 0; c < NC64; c++) {
        size_t base = ((size_t)b * NC64 + c) * NH + h;
        float sc = __expf(cs[base * TCH + TCH - 1]);
        size_t off = base * (size_t)(HD * DS) + e;
        prev[off] = P;
        P = fmaf(P, sc, states[off]);
    }
}

// ---------------- K3: Y += diag(exp(cs)) * C * prev^T on tensor cores ----------------
#define SM_K3_BYTES ((4 * 64 * SB_S) * 2 + 64 * 4)
__global__ __launch_bounds__(256, 1) void yoff64_kernel(
    const float* __restrict__ xbc, const float* __restrict__ prev,
    const float* __restrict__ cs, float* __restrict__ y) {
    extern __shared__ char smraw[];
    __nv_bfloat16* sCh = (__nv_bfloat16*)smraw;
    __nv_bfloat16* sCl = sCh + 64 * SB_S;
    __nv_bfloat16* sPh = sCl + 64 * SB_S;
    __nv_bfloat16* sPl = sPh + 64 * SB_S;
    float* sE = (float*)(sPl + 64 * SB_S);

    const int c = blockIdx.x, b = blockIdx.y;
    const int tid = threadIdx.x;
    const int wid = tid >> 5, lane = tid & 31;
    const int wm = wid >> 2, wn = wid & 3;
    const int grp = lane >> 2, q2 = (lane & 3) * 2;
    const int row0 = b * L_SEQ + c * TCH;
    const float* xrow = xbc + (size_t)row0 * CONVD;

    for (int idx = tid; idx < 64 * 128; idx += 256) {
        int t = idx >> 7, n = idx & 127;
        float cv = xrow[(size_t)t * CONVD + 2176 + n];
        __nv_bfloat16 ch, cl;
        bfsplit(cv, ch, cl);
        sCh[t * SB_S + n] = ch;
        sCl[t * SB_S + n] = cl;
    }

    for (int h = 0; h < NH; h++) {
        __syncthreads();
        if (tid < 64)
            sE[tid] = __expf(cs[(((size_t)b * NC64 + c) * NH + h) * TCH + tid]);
        size_t pbase = (((size_t)b * NC64 + c) * NH + h) * (size_t)(HD * DS);
        for (int idx = tid; idx < 64 * 128; idx += 256) {
            int p = idx >> 7, n = idx & 127;
            float pv = prev[pbase + (size_t)p * DS + n];
            __nv_bfloat16 ph, pl;
            bfsplit(pv, ph, pl);
            sPh[p * SB_S + n] = ph;
            sPl[p * SB_S + n] = pl;
        }
        __syncthreads();

        float acc[2][2][4];
#pragma unroll
        for (int i = 0; i < 2; i++)
#pragma unroll
            for (int j = 0; j < 2; j++)
#pragma unroll
                for (int r = 0; r < 4; r++) acc[i][j][r] = 0.f;
        for (int kb = 0; kb < 128; kb += 16) {
            uint32_t bh[2][2], bl[2][2];
#pragma unroll
            for (int nt = 0; nt < 2; nt++) {
                int c0 = wn * 16 + nt * 8 + grp;
                bh[nt][0] = *(const uint32_t*)&sPh[c0 * SB_S + kb + q2];
                bh[nt][1] = *(const uint32_t*)&sPh[c0 * SB_S + kb + q2 + 8];
                bl[nt][0] = *(const uint32_t*)&sPl[c0 * SB_S + kb + q2];
                bl[nt][1] = *(const uint32_t*)&sPl[c0 * SB_S + kb + q2 + 8];
            }
#pragma unroll
            for (int mt = 0; mt < 2; mt++) {
                int r0 = wm * 32 + mt * 16 + grp;
                uint32_t ah[4], al[4];
                ah[0] = *(const uint32_t*)&sCh[r0 * SB_S + kb + q2];
                ah[1] = *(const uint32_t*)&sCh[(r0 + 8) * SB_S + kb + q2];
                ah[2] = *(const uint32_t*)&sCh[r0 * SB_S + kb + q2 + 8];
                ah[3] = *(const uint32_t*)&sCh[(r0 + 8) * SB_S + kb + q2 + 8];
                al[0] = *(const uint32_t*)&sCl[r0 * SB_S + kb + q2];
                al[1] = *(const uint32_t*)&sCl[(r0 + 8) * SB_S + kb + q2];
                al[2] = *(const uint32_t*)&sCl[r0 * SB_S + kb + q2 + 8];
                al[3] = *(const uint32_t*)&sCl[(r0 + 8) * SB_S + kb + q2 + 8];
#pragma unroll
                for (int nt = 0; nt < 2; nt++) {
                    mma16816(acc[mt][nt], ah, bh[nt]);
                    mma16816(acc[mt][nt], ah, bl[nt]);
                    mma16816(acc[mt][nt], al, bh[nt]);
                }
            }
        }
#pragma unroll
        for (int mt = 0; mt < 2; mt++)
#pragma unroll
            for (int nt = 0; nt < 2; nt++) {
                int t0 = wm * 32 + mt * 16 + grp;
                int p0 = wn * 16 + nt * 8 + q2;
#pragma unroll
                for (int rr = 0; rr < 2; rr++) {
                    int t = t0 + rr * 8;
                    float e = sE[t];
                    size_t addr = (size_t)(row0 + t) * DSSM + h * 64 + p0;
                    float2 old = *(float2*)&y[addr];
                    old.x = fmaf(e, acc[mt][nt][rr * 2 + 0], old.x);
                    old.y = fmaf(e, acc[mt][nt][rr * 2 + 1], old.y);
                    *(float2*)&y[addr] = old;
                }
            }
    }
}

// ---------------- gate (y * silu(z)) + RMSNorm, fused fp16 hi/lo split ----------------
__global__ void gate_norm_kernel(const float* __restrict__ zx,
                                 const float* __restrict__ y,
                                 const float* __restrict__ norm_w,
                                 __half* __restrict__ ynh,
                                 __half* __restrict__ ynl) {
    const int row = blockIdx.x;
    const int tid = threadIdx.x;
    const float* yrow = y + (size_t)row * DSSM;
    const float* zrow = zx + (size_t)row * DIP;
    float v[8];
    float ss = 0.f;
#pragma unroll
    for (int k = 0; k < 8; k++) {
        int e = tid + k * 256;
        float z = zrow[e];
        float vv = yrow[e] * (z * fast_sigmoid(z));
        v[k] = vv;
        ss = fmaf(vv, vv, ss);
    }
    __shared__ float red[256];
    red[tid] = ss;
    __syncthreads();
    for (int s = 128; s > 0; s >>= 1) {
        if (tid < s) red[tid] += red[tid + s];
        __syncthreads();
    }
    float r = rsqrtf(red[0] / (float)DSSM + 1e-5f);
#pragma unroll
    for (int k = 0; k < 8; k++) {
        int e = tid + k * 256;
        float o = v[k] * r * norm_w[e];
        __half oh, ol;
        hsplit(o, oh, ol);
        ynh[(size_t)row * DSSM + e] = oh;
        ynl[(size_t)row * DSSM + e] = ol;
    }
}

// ---------------- host launch ----------------
extern "C" void kernel_launch(void* const* d_in, const int* in_sizes, int n_in,
                              void* d_out, int out_size) {
    const float* u       = (const float*)d_in[0];
    const float* W_in    = (const float*)d_in[1];
    const float* conv_w  = (const float*)d_in[2];
    const float* conv_b  = (const float*)d_in[3];
    const float* dt_bias = (const float*)d_in[4];
    const float* A_log   = (const float*)d_in[5];
    const float* Dv      = (const float*)d_in[6];
    const float* norm_w  = (const float*)d_in[7];
    const float* W_out   = (const float*)d_in[8];
    float* out = (float*)d_out;

    void *p_zx, *p_xbc, *p_y, *p_states, *p_prev, *p_cs;
    void *p_uh, *p_ul, *p_wih, *p_ynh, *p_ynl, *p_woh;
    cudaGetSymbolAddress(&p_zx, g_zx);
    cudaGetSymbolAddress(&p_xbc, g_xbc);
    cudaGetSymbolAddress(&p_y, g_y);
    cudaGetSymbolAddress(&p_states, g_states);
    cudaGetSymbolAddress(&p_prev, g_prev);
    cudaGetSymbolAddress(&p_cs, g_cs);
    cudaGetSymbolAddress(&p_uh, g_uh);
    cudaGetSymbolAddress(&p_ul, g_ul);
    cudaGetSymbolAddress(&p_wih, g_wih);
    cudaGetSymbolAddress(&p_ynh, g_ynh);
    cudaGetSymbolAddress(&p_ynl, g_ynl);
    cudaGetSymbolAddress(&p_woh, g_woh);
    float* zx = (float*)p_zx;
    float* xbc = (float*)p_xbc;
    float* y = (float*)p_y;
    float* states = (float*)p_states;
    float* prev = (float*)p_prev;
    float* cs = (float*)p_cs;
    __half* uh = (__half*)p_uh;
    __half* ul = (__half*)p_ul;
    __half* wih = (__half*)p_wih;
    __half* ynh = (__half*)p_ynh;
    __half* ynl = (__half*)p_ynl;
    __half* woh = (__half*)p_woh;

    cudaFuncSetAttribute(gemm_nt_fp16x2, cudaFuncAttributeMaxDynamicSharedMemorySize,
                         GEMM_SMEM);
    cudaFuncSetAttribute(ssm_intra_kernel, cudaFuncAttributeMaxDynamicSharedMemorySize,
                         SM_K1_BYTES);
    cudaFuncSetAttribute(yoff64_kernel, cudaFuncAttributeMaxDynamicSharedMemorySize,
                         SM_K3_BYTES);

    // 0. prepare fp16 inputs
    {
        int n4 = MROWS * D_MODEL / 4;
        split_fp16_kernel<<<(n4 + 255) / 256, 256>>>(u, uh, ul, n4);
        n4 = DIP * D_MODEL / 4;
        conv_fp16_kernel<<<(n4 + 255) / 256, 256>>>(W_in, wih, n4);
        n4 = D_MODEL * DSSM / 4;
        conv_fp16_kernel<<<(n4 + 255) / 256, 256>>>(W_out, woh, n4);
    }

    // 1. in_proj (fp16 2-pass)
    gemm_nt_fp16x2<<<dim3((DIP + 127) / 128, MROWS / 128), 256, GEMM_SMEM>>>(
        uh, ul, wih, zx, MROWS, DIP, D_MODEL);

    // 2. conv1d + silu (4 t per thread)
    {
        size_t total4 = (size_t)(MROWS / 4) * CONVD;
        conv_silu_kernel<<<(unsigned)((total4 + 255) / 256), 256>>>(zx, conv_w, conv_b, xbc);
    }

    // 3. intra-chunk SSM (bf16 x3)
    ssm_intra_kernel<<<dim3(NC64, NH / HPB, BATCH), 256, SM_K1_BYTES>>>(
        zx, xbc, dt_bias, A_log, Dv, y, states, cs);

    // 4. inter-chunk recurrence
    chunk_scan64<<<dim3(32, NH, BATCH), 256>>>(states, cs, prev);

    // 5. Y_off
    yoff64_kernel<<<dim3(NC64, BATCH), 256, SM_K3_BYTES>>>(xbc, prev, cs, y);

    // 6. gate + RMSNorm + fused fp16 split
    gate_norm_kernel<<<MROWS, 256>>>(zx, y, norm_w, ynh, ynl);

    // 7. out_proj (fp16 2-pass)
    gemm_nt_fp16x2<<<dim3(D_MODEL / 128, MROWS / 128), 256, GEMM_SMEM>>>(
        ynh, ynl, woh, out, MROWS, D_MODEL, DSSM);
}

// round 10
// speedup vs baseline: 3.1661x; 1.2508x over previous
#include <cuda_runtime.h>
#include <cuda_bf16.h>
#include <cuda_fp16.h>
#include <math.h>
#include <stdint.h>

#define BATCH 2
#define L_SEQ 4096
#define D_MODEL 1024
#define DIP 4384          // D_IN_PROJ
#define DSSM 2048
#define CONVD 2304        // CONV_DIM
#define NH 32
#define HD 64
#define DS 128
#define NC64 64           // chunks of 64 per batch
#define TCH 64
#define HPB 8             // heads per block in ssm_intra / yoff
#define MROWS (BATCH * L_SEQ)   // 8192

// ---------------- scratch (device globals; no allocation) ----------------
__device__ float g_zx[(size_t)MROWS * DIP];
__device__ float g_xbc[(size_t)MROWS * CONVD];
__device__ float g_y[(size_t)MROWS * DSSM];
__device__ float g_states[(size_t)BATCH * NC64 * NH * HD * DS];
__device__ float g_prev[(size_t)BATCH * NC64 * NH * HD * DS];
__device__ float g_cs[(size_t)BATCH * NC64 * NH * TCH];

// fp16 buffers for projection GEMMs (A hi/lo split, B single)
__device__ __half g_uh[(size_t)MROWS * D_MODEL];
__device__ __half g_ul[(size_t)MROWS * D_MODEL];
__device__ __half g_wih[(size_t)DIP * D_MODEL];
__device__ __half g_ynh[(size_t)MROWS * DSSM];
__device__ __half g_ynl[(size_t)MROWS * DSSM];
__device__ __half g_woh[(size_t)D_MODEL * DSSM];

// ---------------- helpers ----------------
struct alignas(8) half4 { __half a, b, c, d; };

__device__ __forceinline__ float fast_sigmoid(float x) {
    return 1.f / (1.f + __expf(-x));
}

// fp16 mma
__device__ __forceinline__ void mma16816h(float* d, const uint32_t* a, const uint32_t* b) {
    asm volatile(
        "mma.sync.aligned.m16n8k16.row.col.f32.f16.f16.f32 "
        "{%0,%1,%2,%3}, {%4,%5,%6,%7}, {%8,%9}, {%0,%1,%2,%3};"
        : "+f"(d[0]), "+f"(d[1]), "+f"(d[2]), "+f"(d[3])
        : "r"(a[0]), "r"(a[1]), "r"(a[2]), "r"(a[3]), "r"(b[0]), "r"(b[1]));
}

__device__ __forceinline__ void ldsm_x4(uint32_t& r0, uint32_t& r1, uint32_t& r2,
                                        uint32_t& r3, uint32_t addr) {
    asm volatile("ldmatrix.sync.aligned.m8n8.x4.shared.b16 {%0,%1,%2,%3}, [%4];"
                 : "=r"(r0), "=r"(r1), "=r"(r2), "=r"(r3) : "r"(addr));
}

__device__ __forceinline__ void hsplit(float v, __half& h, __half& l) {
    h = __float2half(v);
    l = __float2half(v - __half2float(h));
}

__device__ __forceinline__ void cpasync16(uint32_t dst, const void* src, int szvalid) {
    asm volatile("cp.async.cg.shared.global [%0], [%1], 16, %2;"
                 :: "r"(dst), "l"(src), "r"(szvalid) : "memory");
}
#define CPASYNC_COMMIT() asm volatile("cp.async.commit_group;" ::: "memory")
#define CPASYNC_WAIT(n)  asm volatile("cp.async.wait_group %0;" :: "n"(n) : "memory")

// ---------------- fp32 -> fp16 hi/lo split ----------------
__global__ void split_fp16_kernel(const float* __restrict__ x,
                                  __half* __restrict__ hi,
                                  __half* __restrict__ lo, int n4) {
    int i = blockIdx.x * 256 + threadIdx.x;
    if (i >= n4) return;
    float4 v = ((const float4*)x)[i];
    __half h0, h1, h2, h3, l0, l1, l2, l3;
    hsplit(v.x, h0, l0); hsplit(v.y, h1, l1);
    hsplit(v.z, h2, l2); hsplit(v.w, h3, l3);
    half4 hv = {h0, h1, h2, h3};
    half4 lv = {l0, l1, l2, l3};
    ((half4*)hi)[i] = hv;
    ((half4*)lo)[i] = lv;
}

// ---------------- fp32 -> fp16 single convert ----------------
__global__ void conv_fp16_kernel(const float* __restrict__ x,
                                 __half* __restrict__ o, int n4) {
    int i = blockIdx.x * 256 + threadIdx.x;
    if (i >= n4) return;
    float4 v = ((const float4*)x)[i];
    half4 hv = {__float2half(v.x), __float2half(v.y),
                __float2half(v.z), __float2half(v.w)};
    ((half4*)o)[i] = hv;
}

// ---------------- fp16 2-pass GEMM: C[M,N] = (Ah+Al)[M,K] * B[N,K]^T ----------------
#define GK 16
#define GPAD 24
#define NSTAGE 4
#define GEMM_SMEM (NSTAGE * 3 * 128 * GPAD * 2)   // 73728 bytes

__global__ __launch_bounds__(256, 2) void gemm_nt_fp16x2(
    const __half* __restrict__ Ah, const __half* __restrict__ Al,
    const __half* __restrict__ B,
    float* __restrict__ C, int M, int N, int K) {
    extern __shared__ __half smh[];
    __half* sA = smh;
    __half* sB = smh + NSTAGE * 2 * 128 * GPAD;

    const int tid = threadIdx.x;
    const int wid = tid >> 5, lane = tid & 31;
    const int wm = wid >> 2, wn = wid & 3;
    const int grp = lane >> 2, q2 = (lane & 3) * 2;
    const int rowBase = blockIdx.y * 128;
    const int colBase = blockIdx.x * 128;
    const int lrow = tid >> 1;
    const int lkh = (tid & 1) * 8;

    const int lmRow = lane & 15;
    const int lmK = (lane >> 4) << 3;

    const uint32_t sA_s = (uint32_t)__cvta_generic_to_shared(sA);
    const uint32_t sB_s = (uint32_t)__cvta_generic_to_shared(sB);

    float acc[4][4][4];
#pragma unroll
    for (int i = 0; i < 4; i++)
#pragma unroll
        for (int j = 0; j < 4; j++)
#pragma unroll
            for (int r = 0; r < 4; r++) acc[i][j][r] = 0.f;

    const int nk = K / GK;
#define SAIDX(st, hl, r, k) (((((st) * 2 + (hl)) * 128 + (r)) * GPAD) + (k))
#define SBIDX(st, r, k) ((((st) * 128 + (r)) * GPAD) + (k))

    const __half* pAh = Ah + (size_t)(rowBase + lrow) * K + lkh;
    const __half* pAl = Al + (size_t)(rowBase + lrow) * K + lkh;
    int cn = colBase + lrow;
    int bok = (cn < N) ? 16 : 0;
    int cnc = (cn < N) ? cn : 0;
    const __half* pB = B + (size_t)cnc * K + lkh;

    auto load_stage = [&](int st, int kc) {
        int ko = kc * GK;
        cpasync16(sA_s + SAIDX(st, 0, lrow, lkh) * 2, pAh + ko, 16);
        cpasync16(sA_s + SAIDX(st, 1, lrow, lkh) * 2, pAl + ko, 16);
        cpasync16(sB_s + SBIDX(st, lrow, lkh) * 2, pB + ko, bok);
        CPASYNC_COMMIT();
    };

    load_stage(0, 0);
    if (nk > 1) load_stage(1, 1);

    for (int k = 0; k < nk; k++) {
        int st = k & (NSTAGE - 1);
        if (k + 2 < nk) {
            load_stage((k + 2) & (NSTAGE - 1), k + 2);
            CPASYNC_WAIT(2);
        } else if (k + 1 < nk) {
            CPASYNC_WAIT(1);
        } else {
            CPASYNC_WAIT(0);
        }
        __syncthreads();

        uint32_t bb[4][2];
        {
            uint32_t r0, r1, r2, r3;
            ldsm_x4(r0, r1, r2, r3, sB_s + SBIDX(st, wn * 32 + lmRow, lmK) * 2);
            bb[0][0] = r0; bb[0][1] = r2; bb[1][0] = r1; bb[1][1] = r3;
            ldsm_x4(r0, r1, r2, r3, sB_s + SBIDX(st, wn * 32 + 16 + lmRow, lmK) * 2);
            bb[2][0] = r0; bb[2][1] = r2; bb[3][0] = r1; bb[3][1] = r3;
        }
#pragma unroll
        for (int mt = 0; mt < 4; mt++) {
            int r0row = wm * 64 + mt * 16;
            uint32_t ah[4], al[4];
            ldsm_x4(ah[0], ah[1], ah[2], ah[3], sA_s + SAIDX(st, 0, r0row + lmRow, lmK) * 2);
            ldsm_x4(al[0], al[1], al[2], al[3], sA_s + SAIDX(st, 1, r0row + lmRow, lmK) * 2);
#pragma unroll
            for (int nt = 0; nt < 4; nt++) {
                mma16816h(acc[mt][nt], ah, bb[nt]);
                mma16816h(acc[mt][nt], al, bb[nt]);
            }
        }
    }
#pragma unroll
    for (int mt = 0; mt < 4; mt++) {
#pragma unroll
        for (int nt = 0; nt < 4; nt++) {
            int colTile = colBase + wn * 32 + nt * 8;
            if (colTile >= N) continue;
            int r0 = rowBase + wm * 64 + mt * 16 + grp;
            int c0 = colTile + q2;
            *(float2*)&C[(size_t)r0 * N + c0] = make_float2(acc[mt][nt][0], acc[mt][nt][1]);
            *(float2*)&C[(size_t)(r0 + 8) * N + c0] = make_float2(acc[mt][nt][2], acc[mt][nt][3]);
        }
    }
#undef SAIDX
#undef SBIDX
}

// ---------------- conv1d (causal, depthwise, width 4) + SiLU : 4 t per thread ----------------
__global__ void conv_silu_kernel(const float* __restrict__ zx,
                                 const float* __restrict__ conv_w,
                                 const float* __restrict__ conv_b,
                                 float* __restrict__ xbc) {
    size_t idx = (size_t)blockIdx.x * 256 + threadIdx.x;
    const size_t total = (size_t)(MROWS / 4) * CONVD;
    if (idx >= total) return;
    int cc = (int)(idx % CONVD);
    size_t r4 = idx / CONVD;
    size_t bt0 = r4 * 4;
    int t0 = (int)(bt0 % L_SEQ);

    float w0 = conv_w[cc * 4 + 0], w1 = conv_w[cc * 4 + 1];
    float w2 = conv_w[cc * 4 + 2], w3 = conv_w[cc * 4 + 3];
    float bia = conv_b[cc];

    float v[7];
#pragma unroll
    for (int j = 0; j < 7; j++) {
        int tt = t0 - 3 + j;
        v[j] = (tt >= 0) ? zx[(bt0 - 3 + j) * DIP + 2048 + cc] : 0.f;
    }
#pragma unroll
    for (int i = 0; i < 4; i++) {
        float acc = bia;
        acc = fmaf(v[i + 0], w0, acc);
        acc = fmaf(v[i + 1], w1, acc);
        acc = fmaf(v[i + 2], w2, acc);
        acc = fmaf(v[i + 3], w3, acc);
        xbc[(bt0 + i) * CONVD + cc] = acc * fast_sigmoid(acc);
    }
}

// ---------------- K1: intra-chunk SSM, single-fp16 mma ----------------
// grid (NC64, NH/HPB, BATCH), 256 threads; warp w owns head h0+w's cumsum.
#define SB_S 136
#define ST_S 66
#define SM_K1_BYTES ((2 * 64 * SB_S + 128 * ST_S + 3 * 64 * ST_S) * 2 + \
                     (64 * ST_S + 2 * HPB * 64 + 64) * 4)

__global__ __launch_bounds__(256, 2) void ssm_intra_kernel(
    const float* __restrict__ zx, const float* __restrict__ xbc,
    const float* __restrict__ dt_bias, const float* __restrict__ A_log,
    const float* __restrict__ Dvec,
    float* __restrict__ y, float* __restrict__ states, float* __restrict__ cs_out) {
    extern __shared__ char smraw[];
    __half* sB = (__half*)smraw;                 // 64 x SB_S  (s, n)
    __half* sC = sB + 64 * SB_S;                 // 64 x SB_S  (t, n)
    __half* sBT = sC + 64 * SB_S;                // 128 x ST_S (n, s)
    __half* sGh = sBT + 128 * ST_S;              // 64 x ST_S  (t, s)
    __half* sX = sGh + 64 * ST_S;                // 64 x ST_S  (p, s)  x*dt
    __half* sXd = sX + 64 * ST_S;                // 64 x ST_S  (p, s)  x*dt*decay
    float* sG = (float*)(sXd + 64 * ST_S);       // 64 x ST_S fp32
    float* s_dt = sG + 64 * ST_S;                // HPB x 64
    float* s_cs = s_dt + HPB * 64;               // HPB x 64
    float* sEd = s_cs + HPB * 64;                // 64

    const int c = blockIdx.x, hg = blockIdx.y, b = blockIdx.z;
    const int h0 = hg * HPB;
    const int tid = threadIdx.x;
    const int wid = tid >> 5, lane = tid & 31;
    const int wm = wid >> 2, wn = wid & 3;
    const int grp = lane >> 2, q2 = (lane & 3) * 2;
    const int row0 = b * L_SEQ + c * TCH;
    const float* xrow = xbc + (size_t)row0 * CONVD;

    {
        int h = h0 + wid;
        float Ah = -__expf(A_log[h]);
        float bias = dt_bias[h];
        float d0 = zx[(size_t)(row0 + lane) * DIP + 4352 + h] + bias;
        float d1 = zx[(size_t)(row0 + 32 + lane) * DIP + 4352 + h] + bias;
        float dt0 = (d0 > 20.f) ? d0 : log1pf(__expf(d0));
        float dt1 = (d1 > 20.f) ? d1 : log1pf(__expf(d1));
        s_dt[wid * 64 + lane] = dt0;
        s_dt[wid * 64 + 32 + lane] = dt1;
        float v0 = dt0 * Ah, v1 = dt1 * Ah;
#pragma unroll
        for (int off = 1; off < 32; off <<= 1) {
            float n0 = __shfl_up_sync(0xffffffffu, v0, off);
            float n1 = __shfl_up_sync(0xffffffffu, v1, off);
            if (lane >= off) { v0 += n0; v1 += n1; }
        }
        v1 += __shfl_sync(0xffffffffu, v0, 31);
        s_cs[wid * 64 + lane] = v0;
        s_cs[wid * 64 + 32 + lane] = v1;
        size_t cbase = (((size_t)b * NC64 + c) * NH + h) * TCH;
        cs_out[cbase + lane] = v0;
        cs_out[cbase + 32 + lane] = v1;
    }

    for (int idx = tid; idx < 64 * 128; idx += 256) {
        int s = idx >> 7, n = idx & 127;
        __half bh = __float2half(xrow[(size_t)s * CONVD + 2048 + n]);
        __half ch = __float2half(xrow[(size_t)s * CONVD + 2176 + n]);
        sB[s * SB_S + n] = bh;
        sC[s * SB_S + n] = ch;
        sBT[n * ST_S + s] = bh;
    }
    __syncthreads();

    // G = C * B^T (shared across heads)
    {
        float g[2][2][4];
#pragma unroll
        for (int i = 0; i < 2; i++)
#pragma unroll
            for (int j = 0; j < 2; j++)
#pragma unroll
                for (int r = 0; r < 4; r++) g[i][j][r] = 0.f;
        for (int kb = 0; kb < 128; kb += 16) {
            uint32_t bb[2][2];
#pragma unroll
            for (int nt = 0; nt < 2; nt++) {
                int c0 = wn * 16 + nt * 8 + grp;
                bb[nt][0] = *(const uint32_t*)&sB[c0 * SB_S + kb + q2];
                bb[nt][1] = *(const uint32_t*)&sB[c0 * SB_S + kb + q2 + 8];
            }
#pragma unroll
            for (int mt = 0; mt < 2; mt++) {
                int r0 = wm * 32 + mt * 16 + grp;
                uint32_t aa[4];
                aa[0] = *(const uint32_t*)&sC[r0 * SB_S + kb + q2];
                aa[1] = *(const uint32_t*)&sC[(r0 + 8) * SB_S + kb + q2];
                aa[2] = *(const uint32_t*)&sC[r0 * SB_S + kb + q2 + 8];
                aa[3] = *(const uint32_t*)&sC[(r0 + 8) * SB_S + kb + q2 + 8];
#pragma unroll
                for (int nt = 0; nt < 2; nt++) mma16816h(g[mt][nt], aa, bb[nt]);
            }
        }
#pragma unroll
        for (int mt = 0; mt < 2; mt++)
#pragma unroll
            for (int nt = 0; nt < 2; nt++) {
                int t = wm * 32 + mt * 16 + grp;
                int s = wn * 16 + nt * 8 + q2;
                *(float2*)&sG[t * ST_S + s] = make_float2(g[mt][nt][0], g[mt][nt][1]);
                *(float2*)&sG[(t + 8) * ST_S + s] = make_float2(g[mt][nt][2], g[mt][nt][3]);
            }
    }

    for (int hl = 0; hl < HPB; hl++) {
        int h = h0 + hl;
        __syncthreads();
        const float* csh = s_cs + hl * 64;
        const float* dth = s_dt + hl * 64;
        const float csL = csh[63];
        if (tid < 64) sEd[tid] = __expf(csL - csh[tid]);
        for (int idx = tid; idx < 64 * 64; idx += 256) {
            int t = idx >> 6, s = idx & 63;
            float val = 0.f;
            if (t >= s) val = sG[t * ST_S + s] * __expf(csh[t] - csh[s]);
            sGh[t * ST_S + s] = __float2half(val);
        }
        __syncthreads();
        for (int idx = tid; idx < 64 * 64; idx += 256) {
            int s = idx >> 6, p = idx & 63;
            float xv = xrow[(size_t)s * CONVD + h * 64 + p];
            float xt = xv * dth[s];
            sX[p * ST_S + s] = __float2half(xt);
            sXd[p * ST_S + s] = __float2half(xt * sEd[s]);
        }
        __syncthreads();

        // Y_diag = G~ * x~
        {
            float yd[2][2][4];
#pragma unroll
            for (int i = 0; i < 2; i++)
#pragma unroll
                for (int j = 0; j < 2; j++)
#pragma unroll
                    for (int r = 0; r < 4; r++) yd[i][j][r] = 0.f;
            for (int kb = 0; kb < 64; kb += 16) {
                uint32_t bb[2][2];
#pragma unroll
                for (int nt = 0; nt < 2; nt++) {
                    int c0 = wn * 16 + nt * 8 + grp;
                    bb[nt][0] = *(const uint32_t*)&sX[c0 * ST_S + kb + q2];
                    bb[nt][1] = *(const uint32_t*)&sX[c0 * ST_S + kb + q2 + 8];
                }
#pragma unroll
                for (int mt = 0; mt < 2; mt++) {
                    int r0 = wm * 32 + mt * 16 + grp;
                    uint32_t aa[4];
                    aa[0] = *(const uint32_t*)&sGh[r0 * ST_S + kb + q2];
                    aa[1] = *(const uint32_t*)&sGh[(r0 + 8) * ST_S + kb + q2];
                    aa[2] = *(const uint32_t*)&sGh[r0 * ST_S + kb + q2 + 8];
                    aa[3] = *(const uint32_t*)&sGh[(r0 + 8) * ST_S + kb + q2 + 8];
#pragma unroll
                    for (int nt = 0; nt < 2; nt++) mma16816h(yd[mt][nt], aa, bb[nt]);
                }
            }
            float Dh = Dvec[h];
#pragma unroll
            for (int mt = 0; mt < 2; mt++)
#pragma unroll
                for (int nt = 0; nt < 2; nt++) {
                    int t0 = wm * 32 + mt * 16 + grp;
                    int p0 = wn * 16 + nt * 8 + q2;
#pragma unroll
                    for (int rr = 0; rr < 2; rr++) {
                        int t = t0 + rr * 8;
                        float2 xv = *(const float2*)&xrow[(size_t)t * CONVD + h * 64 + p0];
                        float2 o;
                        o.x = fmaf(Dh, xv.x, yd[mt][nt][rr * 2 + 0]);
                        o.y = fmaf(Dh, xv.y, yd[mt][nt][rr * 2 + 1]);
                        *(float2*)&g_y[(size_t)(row0 + t) * DSSM + h * 64 + p0] = o;
                    }
                }
        }

        // state = x~d^T * B
        {
            float st[2][4][4];
#pragma unroll
            for (int i = 0; i < 2; i++)
#pragma unroll
                for (int j = 0; j < 4; j++)
#pragma unroll
                    for (int r = 0; r < 4; r++) st[i][j][r] = 0.f;
            for (int kb = 0; kb < 64; kb += 16) {
                uint32_t bb[4][2];
#pragma unroll
                for (int nt = 0; nt < 4; nt++) {
                    int c0 = wn * 32 + nt * 8 + grp;
                    bb[nt][0] = *(const uint32_t*)&sBT[c0 * ST_S + kb + q2];
                    bb[nt][1] = *(const uint32_t*)&sBT[c0 * ST_S + kb + q2 + 8];
                }
#pragma unroll
                for (int mt = 0; mt < 2; mt++) {
                    int r0 = wm * 32 + mt * 16 + grp;
                    uint32_t aa[4];
                    aa[0] = *(const uint32_t*)&sXd[r0 * ST_S + kb + q2];
                    aa[1] = *(const uint32_t*)&sXd[(r0 + 8) * ST_S + kb + q2];
                    aa[2] = *(const uint32_t*)&sXd[r0 * ST_S + kb + q2 + 8];
                    aa[3] = *(const uint32_t*)&sXd[(r0 + 8) * ST_S + kb + q2 + 8];
#pragma unroll
                    for (int nt = 0; nt < 4; nt++) mma16816h(st[mt][nt], aa, bb[nt]);
                }
            }
            size_t sbase = (((size_t)b * NC64 + c) * NH + h) * (size_t)(HD * DS);
#pragma unroll
            for (int mt = 0; mt < 2; mt++)
#pragma unroll
                for (int nt = 0; nt < 4; nt++) {
                    int p0 = wm * 32 + mt * 16 + grp;
                    int n0 = wn * 32 + nt * 8 + q2;
                    *(float2*)&states[sbase + (size_t)p0 * DS + n0] =
                        make_float2(st[mt][nt][0], st[mt][nt][1]);
                    *(float2*)&states[sbase + (size_t)(p0 + 8) * DS + n0] =
                        make_float2(st[mt][nt][2], st[mt][nt][3]);
                }
        }
    }
}

// ---------------- K2: inter-chunk recurrence over 64 chunks ----------------
__global__ void chunk_scan64(const float* __restrict__ states,
                             const float* __restrict__ cs,
                             float* __restrict__ prev) {
    const int seg = blockIdx.x, h = blockIdx.y, b = blockIdx.z;
    const int e = seg * 256 + threadIdx.x;
    float P = 0.f;
    for (int c = 0; c < NC64; c++) {
        size_t base = ((size_t)b * NC64 + c) * NH + h;
        float sc = __expf(cs[base * TCH + TCH - 1]);
        size_t off = base * (size_t)(HD * DS) + e;
        prev[off] = P;
        P = fmaf(P, sc, states[off]);
    }
}

// ---------------- K3: Y += diag(exp(cs)) * C * prev^T, single fp16, 8 heads/block ----------------
#define SM_K3_BYTES ((2 * 64 * SB_S) * 2 + 64 * 4)
__global__ __launch_bounds__(256, 2) void yoff64_kernel(
    const float* __restrict__ xbc, const float* __restrict__ prev,
    const float* __restrict__ cs, float* __restrict__ y) {
    extern __shared__ char smraw[];
    __half* sC = (__half*)smraw;                 // 64 x SB_S (t, n)
    __half* sP = sC + 64 * SB_S;                 // 64 x SB_S (p, n)
    float* sE = (float*)(sP + 64 * SB_S);        // 64

    const int c = blockIdx.x, hg = blockIdx.y, b = blockIdx.z;
    const int h0 = hg * HPB;
    const int tid = threadIdx.x;
    const int wid = tid >> 5, lane = tid & 31;
    const int wm = wid >> 2, wn = wid & 3;
    const int grp = lane >> 2, q2 = (lane & 3) * 2;
    const int row0 = b * L_SEQ + c * TCH;
    const float* xrow = xbc + (size_t)row0 * CONVD;

    for (int idx = tid; idx < 64 * 128; idx += 256) {
        int t = idx >> 7, n = idx & 127;
        sC[t * SB_S + n] = __float2half(xrow[(size_t)t * CONVD + 2176 + n]);
    }

    for (int hl = 0; hl < HPB; hl++) {
        int h = h0 + hl;
        __syncthreads();
        if (tid < 64)
            sE[tid] = __expf(cs[(((size_t)b * NC64 + c) * NH + h) * TCH + tid]);
        size_t pbase = (((size_t)b * NC64 + c) * NH + h) * (size_t)(HD * DS);
        for (int idx = tid; idx < 64 * 128; idx += 256) {
            int p = idx >> 7, n = idx & 127;
            sP[p * SB_S + n] = __float2half(prev[pbase + (size_t)p * DS + n]);
        }
        __syncthreads();

        float acc[2][2][4];
#pragma unroll
        for (int i = 0; i < 2; i++)
#pragma unroll
            for (int j = 0; j < 2; j++)
#pragma unroll
                for (int r = 0; r < 4; r++) acc[i][j][r] = 0.f;
        for (int kb = 0; kb < 128; kb += 16) {
            uint32_t bb[2][2];
#pragma unroll
            for (int nt = 0; nt < 2; nt++) {
                int c0 = wn * 16 + nt * 8 + grp;
                bb[nt][0] = *(const uint32_t*)&sP[c0 * SB_S + kb + q2];
                bb[nt][1] = *(const uint32_t*)&sP[c0 * SB_S + kb + q2 + 8];
            }
#pragma unroll
            for (int mt = 0; mt < 2; mt++) {
                int r0 = wm * 32 + mt * 16 + grp;
                uint32_t aa[4];
                aa[0] = *(const uint32_t*)&sC[r0 * SB_S + kb + q2];
                aa[1] = *(const uint32_t*)&sC[(r0 + 8) * SB_S + kb + q2];
                aa[2] = *(const uint32_t*)&sC[r0 * SB_S + kb + q2 + 8];
                aa[3] = *(const uint32_t*)&sC[(r0 + 8) * SB_S + kb + q2 + 8];
#pragma unroll
                for (int nt = 0; nt < 2; nt++) mma16816h(acc[mt][nt], aa, bb[nt]);
            }
        }
#pragma unroll
        for (int mt = 0; mt < 2; mt++)
#pragma unroll
            for (int nt = 0; nt < 2; nt++) {
                int t0 = wm * 32 + mt * 16 + grp;
                int p0 = wn * 16 + nt * 8 + q2;
#pragma unroll
                for (int rr = 0; rr < 2; rr++) {
                    int t = t0 + rr * 8;
                    float e = sE[t];
                    size_t addr = (size_t)(row0 + t) * DSSM + h * 64 + p0;
                    float2 old = *(float2*)&y[addr];
                    old.x = fmaf(e, acc[mt][nt][rr * 2 + 0], old.x);
                    old.y = fmaf(e, acc[mt][nt][rr * 2 + 1], old.y);
                    *(float2*)&y[addr] = old;
                }
            }
    }
}

// ---------------- gate (y * silu(z)) + RMSNorm, fused fp16 hi/lo split ----------------
__global__ void gate_norm_kernel(const float* __restrict__ zx,
                                 const float* __restrict__ y,
                                 const float* __restrict__ norm_w,
                                 __half* __restrict__ ynh,
                                 __half* __restrict__ ynl) {
    const int row = blockIdx.x;
    const int tid = threadIdx.x;
    const float* yrow = y + (size_t)row * DSSM;
    const float* zrow = zx + (size_t)row * DIP;
    float v[8];
    float ss = 0.f;
#pragma unroll
    for (int k = 0; k < 8; k++) {
        int e = tid + k * 256;
        float z = zrow[e];
        float vv = yrow[e] * (z * fast_sigmoid(z));
        v[k] = vv;
        ss = fmaf(vv, vv, ss);
    }
    __shared__ float red[256];
    red[tid] = ss;
    __syncthreads();
    for (int s = 128; s > 0; s >>= 1) {
        if (tid < s) red[tid] += red[tid + s];
        __syncthreads();
    }
    float r = rsqrtf(red[0] / (float)DSSM + 1e-5f);
#pragma unroll
    for (int k = 0; k < 8; k++) {
        int e = tid + k * 256;
        float o = v[k] * r * norm_w[e];
        __half oh, ol;
        hsplit(o, oh, ol);
        ynh[(size_t)row * DSSM + e] = oh;
        ynl[(size_t)row * DSSM + e] = ol;
    }
}

// ---------------- host launch ----------------
extern "C" void kernel_launch(void* const* d_in, const int* in_sizes, int n_in,
                              void* d_out, int out_size) {
    const float* u       = (const float*)d_in[0];
    const float* W_in    = (const float*)d_in[1];
    const float* conv_w  = (const float*)d_in[2];
    const float* conv_b  = (const float*)d_in[3];
    const float* dt_bias = (const float*)d_in[4];
    const float* A_log   = (const float*)d_in[5];
    const float* Dv      = (const float*)d_in[6];
    const float* norm_w  = (const float*)d_in[7];
    const float* W_out   = (const float*)d_in[8];
    float* out = (float*)d_out;

    void *p_zx, *p_xbc, *p_y, *p_states, *p_prev, *p_cs;
    void *p_uh, *p_ul, *p_wih, *p_ynh, *p_ynl, *p_woh;
    cudaGetSymbolAddress(&p_zx, g_zx);
    cudaGetSymbolAddress(&p_xbc, g_xbc);
    cudaGetSymbolAddress(&p_y, g_y);
    cudaGetSymbolAddress(&p_states, g_states);
    cudaGetSymbolAddress(&p_prev, g_prev);
    cudaGetSymbolAddress(&p_cs, g_cs);
    cudaGetSymbolAddress(&p_uh, g_uh);
    cudaGetSymbolAddress(&p_ul, g_ul);
    cudaGetSymbolAddress(&p_wih, g_wih);
    cudaGetSymbolAddress(&p_ynh, g_ynh);
    cudaGetSymbolAddress(&p_ynl, g_ynl);
    cudaGetSymbolAddress(&p_woh, g_woh);
    float* zx = (float*)p_zx;
    float* xbc = (float*)p_xbc;
    float* y = (float*)p_y;
    float* states = (float*)p_states;
    float* prev = (float*)p_prev;
    float* cs = (float*)p_cs;
    __half* uh = (__half*)p_uh;
    __half* ul = (__half*)p_ul;
    __half* wih = (__half*)p_wih;
    __half* ynh = (__half*)p_ynh;
    __half* ynl = (__half*)p_ynl;
    __half* woh = (__half*)p_woh;

    cudaFuncSetAttribute(gemm_nt_fp16x2, cudaFuncAttributeMaxDynamicSharedMemorySize,
                         GEMM_SMEM);
    cudaFuncSetAttribute(ssm_intra_kernel, cudaFuncAttributeMaxDynamicSharedMemorySize,
                         SM_K1_BYTES);
    cudaFuncSetAttribute(yoff64_kernel, cudaFuncAttributeMaxDynamicSharedMemorySize,
                         SM_K3_BYTES);

    // 0. prepare fp16 inputs
    {
        int n4 = MROWS * D_MODEL / 4;
        split_fp16_kernel<<<(n4 + 255) / 256, 256>>>(u, uh, ul, n4);
        n4 = DIP * D_MODEL / 4;
        conv_fp16_kernel<<<(n4 + 255) / 256, 256>>>(W_in, wih, n4);
        n4 = D_MODEL * DSSM / 4;
        conv_fp16_kernel<<<(n4 + 255) / 256, 256>>>(W_out, woh, n4);
    }

    // 1. in_proj (fp16 2-pass)
    gemm_nt_fp16x2<<<dim3((DIP + 127) / 128, MROWS / 128), 256, GEMM_SMEM>>>(
        uh, ul, wih, zx, MROWS, DIP, D_MODEL);

    // 2. conv1d + silu
    {
        size_t total4 = (size_t)(MROWS / 4) * CONVD;
        conv_silu_kernel<<<(unsigned)((total4 + 255) / 256), 256>>>(zx, conv_w, conv_b, xbc);
    }

    // 3. intra-chunk SSM (single fp16 mma)
    ssm_intra_kernel<<<dim3(NC64, NH / HPB, BATCH), 256, SM_K1_BYTES>>>(
        zx, xbc, dt_bias, A_log, Dv, y, states, cs);

    // 4. inter-chunk recurrence
    chunk_scan64<<<dim3(32, NH, BATCH), 256>>>(states, cs, prev);

    // 5. Y_off (single fp16 mma, 8 heads/block)
    yoff64_kernel<<<dim3(NC64, NH / HPB, BATCH), 256, SM_K3_BYTES>>>(xbc, prev, cs, y);

    // 6. gate + RMSNorm + fused fp16 split
    gate_norm_kernel<<<MROWS, 256>>>(zx, y, norm_w, ynh, ynl);

    // 7. out_proj (fp16 2-pass)
    gemm_nt_fp16x2<<<dim3(D_MODEL / 128, MROWS / 128), 256, GEMM_SMEM>>>(
        ynh, ynl, woh, out, MROWS, D_MODEL, DSSM);
}

// round 11
// speedup vs baseline: 4.3806x; 1.3836x over previous
#include <cuda_runtime.h>
#include <cuda_bf16.h>
#include <cuda_fp16.h>
#include <math.h>
#include <stdint.h>

#define BATCH 2
#define L_SEQ 4096
#define D_MODEL 1024
#define DIP 4384          // D_IN_PROJ
#define DSSM 2048
#define CONVD 2304        // CONV_DIM
#define NH 32
#define HD 64
#define DS 128
#define NC64 64           // chunks of 64 per batch
#define TCH 64
#define HPB 8             // heads per block in ssm_intra / yoff
#define MROWS (BATCH * L_SEQ)   // 8192

// ---------------- scratch (device globals; no allocation) ----------------
__device__ float g_zx[(size_t)MROWS * DIP];
__device__ float g_xbc[(size_t)MROWS * CONVD];
__device__ float g_y[(size_t)MROWS * DSSM];
__device__ float g_states[(size_t)BATCH * NC64 * NH * HD * DS];
__device__ float g_prev[(size_t)BATCH * NC64 * NH * HD * DS];
__device__ float g_cs[(size_t)BATCH * NC64 * NH * TCH];

// fp16 buffers for projection GEMMs (single precision pass)
__device__ __half g_uh[(size_t)MROWS * D_MODEL];
__device__ __half g_wih[(size_t)DIP * D_MODEL];
__device__ __half g_ynh[(size_t)MROWS * DSSM];
__device__ __half g_woh[(size_t)D_MODEL * DSSM];

// ---------------- helpers ----------------
struct alignas(8) half4 { __half a, b, c, d; };

__device__ __forceinline__ float fast_sigmoid(float x) {
    return 1.f / (1.f + __expf(-x));
}

__device__ __forceinline__ void mma16816h(float* d, const uint32_t* a, const uint32_t* b) {
    asm volatile(
        "mma.sync.aligned.m16n8k16.row.col.f32.f16.f16.f32 "
        "{%0,%1,%2,%3}, {%4,%5,%6,%7}, {%8,%9}, {%0,%1,%2,%3};"
        : "+f"(d[0]), "+f"(d[1]), "+f"(d[2]), "+f"(d[3])
        : "r"(a[0]), "r"(a[1]), "r"(a[2]), "r"(a[3]), "r"(b[0]), "r"(b[1]));
}

__device__ __forceinline__ void ldsm_x4(uint32_t& r0, uint32_t& r1, uint32_t& r2,
                                        uint32_t& r3, uint32_t addr) {
    asm volatile("ldmatrix.sync.aligned.m8n8.x4.shared.b16 {%0,%1,%2,%3}, [%4];"
                 : "=r"(r0), "=r"(r1), "=r"(r2), "=r"(r3) : "r"(addr));
}

__device__ __forceinline__ void cpasync16(uint32_t dst, const void* src, int szvalid) {
    asm volatile("cp.async.cg.shared.global [%0], [%1], 16, %2;"
                 :: "r"(dst), "l"(src), "r"(szvalid) : "memory");
}
#define CPASYNC_COMMIT() asm volatile("cp.async.commit_group;" ::: "memory")
#define CPASYNC_WAIT(n)  asm volatile("cp.async.wait_group %0;" :: "n"(n) : "memory")

// ---------------- fp32 -> fp16 convert ----------------
__global__ void conv_fp16_kernel(const float* __restrict__ x,
                                 __half* __restrict__ o, int n4) {
    int i = blockIdx.x * 256 + threadIdx.x;
    if (i >= n4) return;
    float4 v = ((const float4*)x)[i];
    half4 hv = {__float2half(v.x), __float2half(v.y),
                __float2half(v.z), __float2half(v.w)};
    ((half4*)o)[i] = hv;
}

// ---------------- fp16 single-pass GEMM: C[M,N] = A[M,K] * B[N,K]^T ----------------
#define GK 16
#define GPAD 24
#define NSTAGE 4
#define GEMM_SMEM (NSTAGE * 2 * 128 * GPAD * 2)   // 49152 bytes

__global__ __launch_bounds__(256, 2) void gemm_nt_fp16(
    const __half* __restrict__ A, const __half* __restrict__ B,
    float* __restrict__ C, int M, int N, int K) {
    extern __shared__ __half smh[];
    __half* sA = smh;                                  // NSTAGE x 128 x GPAD
    __half* sB = smh + NSTAGE * 128 * GPAD;            // NSTAGE x 128 x GPAD

    const int tid = threadIdx.x;
    const int wid = tid >> 5, lane = tid & 31;
    const int wm = wid >> 2, wn = wid & 3;
    const int grp = lane >> 2, q2 = (lane & 3) * 2;
    const int rowBase = blockIdx.y * 128;
    const int colBase = blockIdx.x * 128;
    const int lrow = tid >> 1;
    const int lkh = (tid & 1) * 8;

    const int lmRow = lane & 15;
    const int lmK = (lane >> 4) << 3;

    const uint32_t sA_s = (uint32_t)__cvta_generic_to_shared(sA);
    const uint32_t sB_s = (uint32_t)__cvta_generic_to_shared(sB);

    float acc[4][4][4];
#pragma unroll
    for (int i = 0; i < 4; i++)
#pragma unroll
        for (int j = 0; j < 4; j++)
#pragma unroll
            for (int r = 0; r < 4; r++) acc[i][j][r] = 0.f;

    const int nk = K / GK;
#define SIDX(st, r, k) ((((st) * 128 + (r)) * GPAD) + (k))

    const __half* pA = A + (size_t)(rowBase + lrow) * K + lkh;
    int cn = colBase + lrow;
    int bok = (cn < N) ? 16 : 0;
    int cnc = (cn < N) ? cn : 0;
    const __half* pB = B + (size_t)cnc * K + lkh;

    auto load_stage = [&](int st, int kc) {
        int ko = kc * GK;
        cpasync16(sA_s + SIDX(st, lrow, lkh) * 2, pA + ko, 16);
        cpasync16(sB_s + SIDX(st, lrow, lkh) * 2, pB + ko, bok);
        CPASYNC_COMMIT();
    };

    load_stage(0, 0);
    if (nk > 1) load_stage(1, 1);

    for (int k = 0; k < nk; k++) {
        int st = k & (NSTAGE - 1);
        if (k + 2 < nk) {
            load_stage((k + 2) & (NSTAGE - 1), k + 2);
            CPASYNC_WAIT(2);
        } else if (k + 1 < nk) {
            CPASYNC_WAIT(1);
        } else {
            CPASYNC_WAIT(0);
        }
        __syncthreads();   // single barrier per k-step (4-stage ring)

        uint32_t bb[4][2];
        {
            uint32_t r0, r1, r2, r3;
            ldsm_x4(r0, r1, r2, r3, sB_s + SIDX(st, wn * 32 + lmRow, lmK) * 2);
            bb[0][0] = r0; bb[0][1] = r2; bb[1][0] = r1; bb[1][1] = r3;
            ldsm_x4(r0, r1, r2, r3, sB_s + SIDX(st, wn * 32 + 16 + lmRow, lmK) * 2);
            bb[2][0] = r0; bb[2][1] = r2; bb[3][0] = r1; bb[3][1] = r3;
        }
#pragma unroll
        for (int mt = 0; mt < 4; mt++) {
            int r0row = wm * 64 + mt * 16;
            uint32_t aa[4];
            ldsm_x4(aa[0], aa[1], aa[2], aa[3], sA_s + SIDX(st, r0row + lmRow, lmK) * 2);
#pragma unroll
            for (int nt = 0; nt < 4; nt++) mma16816h(acc[mt][nt], aa, bb[nt]);
        }
    }
#pragma unroll
    for (int mt = 0; mt < 4; mt++) {
#pragma unroll
        for (int nt = 0; nt < 4; nt++) {
            int colTile = colBase + wn * 32 + nt * 8;
            if (colTile >= N) continue;
            int r0 = rowBase + wm * 64 + mt * 16 + grp;
            int c0 = colTile + q2;
            *(float2*)&C[(size_t)r0 * N + c0] = make_float2(acc[mt][nt][0], acc[mt][nt][1]);
            *(float2*)&C[(size_t)(r0 + 8) * N + c0] = make_float2(acc[mt][nt][2], acc[mt][nt][3]);
        }
    }
#undef SIDX
}

// ---------------- conv1d (causal, depthwise, width 4) + SiLU : 4 t per thread ----------------
__global__ void conv_silu_kernel(const float* __restrict__ zx,
                                 const float* __restrict__ conv_w,
                                 const float* __restrict__ conv_b,
                                 float* __restrict__ xbc) {
    size_t idx = (size_t)blockIdx.x * 256 + threadIdx.x;
    const size_t total = (size_t)(MROWS / 4) * CONVD;
    if (idx >= total) return;
    int cc = (int)(idx % CONVD);
    size_t r4 = idx / CONVD;
    size_t bt0 = r4 * 4;
    int t0 = (int)(bt0 % L_SEQ);

    float w0 = conv_w[cc * 4 + 0], w1 = conv_w[cc * 4 + 1];
    float w2 = conv_w[cc * 4 + 2], w3 = conv_w[cc * 4 + 3];
    float bia = conv_b[cc];

    float v[7];
#pragma unroll
    for (int j = 0; j < 7; j++) {
        int tt = t0 - 3 + j;
        v[j] = (tt >= 0) ? zx[(bt0 - 3 + j) * DIP + 2048 + cc] : 0.f;
    }
#pragma unroll
    for (int i = 0; i < 4; i++) {
        float acc = bia;
        acc = fmaf(v[i + 0], w0, acc);
        acc = fmaf(v[i + 1], w1, acc);
        acc = fmaf(v[i + 2], w2, acc);
        acc = fmaf(v[i + 3], w3, acc);
        xbc[(bt0 + i) * CONVD + cc] = acc * fast_sigmoid(acc);
    }
}

// ---------------- K1: intra-chunk SSM, single-fp16 mma ----------------
#define SB_S 136
#define ST_S 66
#define SM_K1_BYTES ((2 * 64 * SB_S + 128 * ST_S + 3 * 64 * ST_S) * 2 + \
                     (64 * ST_S + 2 * HPB * 64 + 64) * 4)

__global__ __launch_bounds__(256, 2) void ssm_intra_kernel(
    const float* __restrict__ zx, const float* __restrict__ xbc,
    const float* __restrict__ dt_bias, const float* __restrict__ A_log,
    const float* __restrict__ Dvec,
    float* __restrict__ y, float* __restrict__ states, float* __restrict__ cs_out) {
    extern __shared__ char smraw[];
    __half* sB = (__half*)smraw;
    __half* sC = sB + 64 * SB_S;
    __half* sBT = sC + 64 * SB_S;
    __half* sGh = sBT + 128 * ST_S;
    __half* sX = sGh + 64 * ST_S;
    __half* sXd = sX + 64 * ST_S;
    float* sG = (float*)(sXd + 64 * ST_S);
    float* s_dt = sG + 64 * ST_S;
    float* s_cs = s_dt + HPB * 64;
    float* sEd = s_cs + HPB * 64;

    const int c = blockIdx.x, hg = blockIdx.y, b = blockIdx.z;
    const int h0 = hg * HPB;
    const int tid = threadIdx.x;
    const int wid = tid >> 5, lane = tid & 31;
    const int wm = wid >> 2, wn = wid & 3;
    const int grp = lane >> 2, q2 = (lane & 3) * 2;
    const int row0 = b * L_SEQ + c * TCH;
    const float* xrow = xbc + (size_t)row0 * CONVD;

    {
        int h = h0 + wid;
        float Ah = -__expf(A_log[h]);
        float bias = dt_bias[h];
        float d0 = zx[(size_t)(row0 + lane) * DIP + 4352 + h] + bias;
        float d1 = zx[(size_t)(row0 + 32 + lane) * DIP + 4352 + h] + bias;
        float dt0 = (d0 > 20.f) ? d0 : log1pf(__expf(d0));
        float dt1 = (d1 > 20.f) ? d1 : log1pf(__expf(d1));
        s_dt[wid * 64 + lane] = dt0;
        s_dt[wid * 64 + 32 + lane] = dt1;
        float v0 = dt0 * Ah, v1 = dt1 * Ah;
#pragma unroll
        for (int off = 1; off < 32; off <<= 1) {
            float n0 = __shfl_up_sync(0xffffffffu, v0, off);
            float n1 = __shfl_up_sync(0xffffffffu, v1, off);
            if (lane >= off) { v0 += n0; v1 += n1; }
        }
        v1 += __shfl_sync(0xffffffffu, v0, 31);
        s_cs[wid * 64 + lane] = v0;
        s_cs[wid * 64 + 32 + lane] = v1;
        size_t cbase = (((size_t)b * NC64 + c) * NH + h) * TCH;
        cs_out[cbase + lane] = v0;
        cs_out[cbase + 32 + lane] = v1;
    }

    for (int idx = tid; idx < 64 * 128; idx += 256) {
        int s = idx >> 7, n = idx & 127;
        __half bh = __float2half(xrow[(size_t)s * CONVD + 2048 + n]);
        __half ch = __float2half(xrow[(size_t)s * CONVD + 2176 + n]);
        sB[s * SB_S + n] = bh;
        sC[s * SB_S + n] = ch;
        sBT[n * ST_S + s] = bh;
    }
    __syncthreads();

    // G = C * B^T (shared across heads)
    {
        float g[2][2][4];
#pragma unroll
        for (int i = 0; i < 2; i++)
#pragma unroll
            for (int j = 0; j < 2; j++)
#pragma unroll
                for (int r = 0; r < 4; r++) g[i][j][r] = 0.f;
        for (int kb = 0; kb < 128; kb += 16) {
            uint32_t bb[2][2];
#pragma unroll
            for (int nt = 0; nt < 2; nt++) {
                int c0 = wn * 16 + nt * 8 + grp;
                bb[nt][0] = *(const uint32_t*)&sB[c0 * SB_S + kb + q2];
                bb[nt][1] = *(const uint32_t*)&sB[c0 * SB_S + kb + q2 + 8];
            }
#pragma unroll
            for (int mt = 0; mt < 2; mt++) {
                int r0 = wm * 32 + mt * 16 + grp;
                uint32_t aa[4];
                aa[0] = *(const uint32_t*)&sC[r0 * SB_S + kb + q2];
                aa[1] = *(const uint32_t*)&sC[(r0 + 8) * SB_S + kb + q2];
                aa[2] = *(const uint32_t*)&sC[r0 * SB_S + kb + q2 + 8];
                aa[3] = *(const uint32_t*)&sC[(r0 + 8) * SB_S + kb + q2 + 8];
#pragma unroll
                for (int nt = 0; nt < 2; nt++) mma16816h(g[mt][nt], aa, bb[nt]);
            }
        }
#pragma unroll
        for (int mt = 0; mt < 2; mt++)
#pragma unroll
            for (int nt = 0; nt < 2; nt++) {
                int t = wm * 32 + mt * 16 + grp;
                int s = wn * 16 + nt * 8 + q2;
                *(float2*)&sG[t * ST_S + s] = make_float2(g[mt][nt][0], g[mt][nt][1]);
                *(float2*)&sG[(t + 8) * ST_S + s] = make_float2(g[mt][nt][2], g[mt][nt][3]);
            }
    }

    for (int hl = 0; hl < HPB; hl++) {
        int h = h0 + hl;
        __syncthreads();
        const float* csh = s_cs + hl * 64;
        const float* dth = s_dt + hl * 64;
        const float csL = csh[63];
        if (tid < 64) sEd[tid] = __expf(csL - csh[tid]);
        for (int idx = tid; idx < 64 * 64; idx += 256) {
            int t = idx >> 6, s = idx & 63;
            float val = 0.f;
            if (t >= s) val = sG[t * ST_S + s] * __expf(csh[t] - csh[s]);
            sGh[t * ST_S + s] = __float2half(val);
        }
        __syncthreads();
        for (int idx = tid; idx < 64 * 64; idx += 256) {
            int s = idx >> 6, p = idx & 63;
            float xv = xrow[(size_t)s * CONVD + h * 64 + p];
            float xt = xv * dth[s];
            sX[p * ST_S + s] = __float2half(xt);
            sXd[p * ST_S + s] = __float2half(xt * sEd[s]);
        }
        __syncthreads();

        // Y_diag = G~ * x~
        {
            float yd[2][2][4];
#pragma unroll
            for (int i = 0; i < 2; i++)
#pragma unroll
                for (int j = 0; j < 2; j++)
#pragma unroll
                    for (int r = 0; r < 4; r++) yd[i][j][r] = 0.f;
            for (int kb = 0; kb < 64; kb += 16) {
                uint32_t bb[2][2];
#pragma unroll
                for (int nt = 0; nt < 2; nt++) {
                    int c0 = wn * 16 + nt * 8 + grp;
                    bb[nt][0] = *(const uint32_t*)&sX[c0 * ST_S + kb + q2];
                    bb[nt][1] = *(const uint32_t*)&sX[c0 * ST_S + kb + q2 + 8];
                }
#pragma unroll
                for (int mt = 0; mt < 2; mt++) {
                    int r0 = wm * 32 + mt * 16 + grp;
                    uint32_t aa[4];
                    aa[0] = *(const uint32_t*)&sGh[r0 * ST_S + kb + q2];
                    aa[1] = *(const uint32_t*)&sGh[(r0 + 8) * ST_S + kb + q2];
                    aa[2] = *(const uint32_t*)&sGh[r0 * ST_S + kb + q2 + 8];
                    aa[3] = *(const uint32_t*)&sGh[(r0 + 8) * ST_S + kb + q2 + 8];
#pragma unroll
                    for (int nt = 0; nt < 2; nt++) mma16816h(yd[mt][nt], aa, bb[nt]);
                }
            }
            float Dh = Dvec[h];
#pragma unroll
            for (int mt = 0; mt < 2; mt++)
#pragma unroll
                for (int nt = 0; nt < 2; nt++) {
                    int t0 = wm * 32 + mt * 16 + grp;
                    int p0 = wn * 16 + nt * 8 + q2;
#pragma unroll
                    for (int rr = 0; rr < 2; rr++) {
                        int t = t0 + rr * 8;
                        float2 xv = *(const float2*)&xrow[(size_t)t * CONVD + h * 64 + p0];
                        float2 o;
                        o.x = fmaf(Dh, xv.x, yd[mt][nt][rr * 2 + 0]);
                        o.y = fmaf(Dh, xv.y, yd[mt][nt][rr * 2 + 1]);
                        *(float2*)&g_y[(size_t)(row0 + t) * DSSM + h * 64 + p0] = o;
                    }
                }
        }

        // state = x~d^T * B
        {
            float st[2][4][4];
#pragma unroll
            for (int i = 0; i < 2; i++)
#pragma unroll
                for (int j = 0; j < 4; j++)
#pragma unroll
                    for (int r = 0; r < 4; r++) st[i][j][r] = 0.f;
            for (int kb = 0; kb < 64; kb += 16) {
                uint32_t bb[4][2];
#pragma unroll
                for (int nt = 0; nt < 4; nt++) {
                    int c0 = wn * 32 + nt * 8 + grp;
                    bb[nt][0] = *(const uint32_t*)&sBT[c0 * ST_S + kb + q2];
                    bb[nt][1] = *(const uint32_t*)&sBT[c0 * ST_S + kb + q2 + 8];
                }
#pragma unroll
                for (int mt = 0; mt < 2; mt++) {
                    int r0 = wm * 32 + mt * 16 + grp;
                    uint32_t aa[4];
                    aa[0] = *(const uint32_t*)&sXd[r0 * ST_S + kb + q2];
                    aa[1] = *(const uint32_t*)&sXd[(r0 + 8) * ST_S + kb + q2];
                    aa[2] = *(const uint32_t*)&sXd[r0 * ST_S + kb + q2 + 8];
                    aa[3] = *(const uint32_t*)&sXd[(r0 + 8) * ST_S + kb + q2 + 8];
#pragma unroll
                    for (int nt = 0; nt < 4; nt++) mma16816h(st[mt][nt], aa, bb[nt]);
                }
            }
            size_t sbase = (((size_t)b * NC64 + c) * NH + h) * (size_t)(HD * DS);
#pragma unroll
            for (int mt = 0; mt < 2; mt++)
#pragma unroll
                for (int nt = 0; nt < 4; nt++) {
                    int p0 = wm * 32 + mt * 16 + grp;
                    int n0 = wn * 32 + nt * 8 + q2;
                    *(float2*)&states[sbase + (size_t)p0 * DS + n0] =
                        make_float2(st[mt][nt][0], st[mt][nt][1]);
                    *(float2*)&states[sbase + (size_t)(p0 + 8) * DS + n0] =
                        make_float2(st[mt][nt][2], st[mt][nt][3]);
                }
        }
    }
}

// ---------------- K2: inter-chunk recurrence over 64 chunks ----------------
__global__ void chunk_scan64(const float* __restrict__ states,
                             const float* __restrict__ cs,
                             float* __restrict__ prev) {
    const int seg = blockIdx.x, h = blockIdx.y, b = blockIdx.z;
    const int e = seg * 256 + threadIdx.x;
    float P = 0.f;
    for (int c = 0; c < NC64; c++) {
        size_t base = ((size_t)b * NC64 + c) * NH + h;
        float sc = __expf(cs[base * TCH + TCH - 1]);
        size_t off = base * (size_t)(HD * DS) + e;
        prev[off] = P;
        P = fmaf(P, sc, states[off]);
    }
}

// ---------------- K3: Y += diag(exp(cs)) * C * prev^T, single fp16, 8 heads/block ----------------
#define SM_K3_BYTES ((2 * 64 * SB_S) * 2 + 64 * 4)
__global__ __launch_bounds__(256, 2) void yoff64_kernel(
    const float* __restrict__ xbc, const float* __restrict__ prev,
    const float* __restrict__ cs, float* __restrict__ y) {
    extern __shared__ char smraw[];
    __half* sC = (__half*)smraw;
    __half* sP = sC + 64 * SB_S;
    float* sE = (float*)(sP + 64 * SB_S);

    const int c = blockIdx.x, hg = blockIdx.y, b = blockIdx.z;
    const int h0 = hg * HPB;
    const int tid = threadIdx.x;
    const int wid = tid >> 5, lane = tid & 31;
    const int wm = wid >> 2, wn = wid & 3;
    const int grp = lane >> 2, q2 = (lane & 3) * 2;
    const int row0 = b * L_SEQ + c * TCH;
    const float* xrow = xbc + (size_t)row0 * CONVD;

    for (int idx = tid; idx < 64 * 128; idx += 256) {
        int t = idx >> 7, n = idx & 127;
        sC[t * SB_S + n] = __float2half(xrow[(size_t)t * CONVD + 2176 + n]);
    }

    for (int hl = 0; hl < HPB; hl++) {
        int h = h0 + hl;
        __syncthreads();
        if (tid < 64)
            sE[tid] = __expf(cs[(((size_t)b * NC64 + c) * NH + h) * TCH + tid]);
        size_t pbase = (((size_t)b * NC64 + c) * NH + h) * (size_t)(HD * DS);
        for (int idx = tid; idx < 64 * 128; idx += 256) {
            int p = idx >> 7, n = idx & 127;
            sP[p * SB_S + n] = __float2half(prev[pbase + (size_t)p * DS + n]);
        }
        __syncthreads();

        float acc[2][2][4];
#pragma unroll
        for (int i = 0; i < 2; i++)
#pragma unroll
            for (int j = 0; j < 2; j++)
#pragma unroll
                for (int r = 0; r < 4; r++) acc[i][j][r] = 0.f;
        for (int kb = 0; kb < 128; kb += 16) {
            uint32_t bb[2][2];
#pragma unroll
            for (int nt = 0; nt < 2; nt++) {
                int c0 = wn * 16 + nt * 8 + grp;
                bb[nt][0] = *(const uint32_t*)&sP[c0 * SB_S + kb + q2];
                bb[nt][1] = *(const uint32_t*)&sP[c0 * SB_S + kb + q2 + 8];
            }
#pragma unroll
            for (int mt = 0; mt < 2; mt++) {
                int r0 = wm * 32 + mt * 16 + grp;
                uint32_t aa[4];
                aa[0] = *(const uint32_t*)&sC[r0 * SB_S + kb + q2];
                aa[1] = *(const uint32_t*)&sC[(r0 + 8) * SB_S + kb + q2];
                aa[2] = *(const uint32_t*)&sC[r0 * SB_S + kb + q2 + 8];
                aa[3] = *(const uint32_t*)&sC[(r0 + 8) * SB_S + kb + q2 + 8];
#pragma unroll
                for (int nt = 0; nt < 2; nt++) mma16816h(acc[mt][nt], aa, bb[nt]);
            }
        }
#pragma unroll
        for (int mt = 0; mt < 2; mt++)
#pragma unroll
            for (int nt = 0; nt < 2; nt++) {
                int t0 = wm * 32 + mt * 16 + grp;
                int p0 = wn * 16 + nt * 8 + q2;
#pragma unroll
                for (int rr = 0; rr < 2; rr++) {
                    int t = t0 + rr * 8;
                    float e = sE[t];
                    size_t addr = (size_t)(row0 + t) * DSSM + h * 64 + p0;
                    float2 old = *(float2*)&y[addr];
                    old.x = fmaf(e, acc[mt][nt][rr * 2 + 0], old.x);
                    old.y = fmaf(e, acc[mt][nt][rr * 2 + 1], old.y);
                    *(float2*)&y[addr] = old;
                }
            }
    }
}

// ---------------- gate (y * silu(z)) + RMSNorm -> fp16 ----------------
__global__ void gate_norm_kernel(const float* __restrict__ zx,
                                 const float* __restrict__ y,
                                 const float* __restrict__ norm_w,
                                 __half* __restrict__ ynh) {
    const int row = blockIdx.x;
    const int tid = threadIdx.x;
    const float* yrow = y + (size_t)row * DSSM;
    const float* zrow = zx + (size_t)row * DIP;
    float v[8];
    float ss = 0.f;
#pragma unroll
    for (int k = 0; k < 8; k++) {
        int e = tid + k * 256;
        float z = zrow[e];
        float vv = yrow[e] * (z * fast_sigmoid(z));
        v[k] = vv;
        ss = fmaf(vv, vv, ss);
    }
    __shared__ float red[256];
    red[tid] = ss;
    __syncthreads();
    for (int s = 128; s > 0; s >>= 1) {
        if (tid < s) red[tid] += red[tid + s];
        __syncthreads();
    }
    float r = rsqrtf(red[0] / (float)DSSM + 1e-5f);
#pragma unroll
    for (int k = 0; k < 8; k++) {
        int e = tid + k * 256;
        ynh[(size_t)row * DSSM + e] = __float2half(v[k] * r * norm_w[e]);
    }
}

// ---------------- host launch ----------------
extern "C" void kernel_launch(void* const* d_in, const int* in_sizes, int n_in,
                              void* d_out, int out_size) {
    const float* u       = (const float*)d_in[0];
    const float* W_in    = (const float*)d_in[1];
    const float* conv_w  = (const float*)d_in[2];
    const float* conv_b  = (const float*)d_in[3];
    const float* dt_bias = (const float*)d_in[4];
    const float* A_log   = (const float*)d_in[5];
    const float* Dv      = (const float*)d_in[6];
    const float* norm_w  = (const float*)d_in[7];
    const float* W_out   = (const float*)d_in[8];
    float* out = (float*)d_out;

    void *p_zx, *p_xbc, *p_y, *p_states, *p_prev, *p_cs;
    void *p_uh, *p_wih, *p_ynh, *p_woh;
    cudaGetSymbolAddress(&p_zx, g_zx);
    cudaGetSymbolAddress(&p_xbc, g_xbc);
    cudaGetSymbolAddress(&p_y, g_y);
    cudaGetSymbolAddress(&p_states, g_states);
    cudaGetSymbolAddress(&p_prev, g_prev);
    cudaGetSymbolAddress(&p_cs, g_cs);
    cudaGetSymbolAddress(&p_uh, g_uh);
    cudaGetSymbolAddress(&p_wih, g_wih);
    cudaGetSymbolAddress(&p_ynh, g_ynh);
    cudaGetSymbolAddress(&p_woh, g_woh);
    float* zx = (float*)p_zx;
    float* xbc = (float*)p_xbc;
    float* y = (float*)p_y;
    float* states = (float*)p_states;
    float* prev = (float*)p_prev;
    float* cs = (float*)p_cs;
    __half* uh = (__half*)p_uh;
    __half* wih = (__half*)p_wih;
    __half* ynh = (__half*)p_ynh;
    __half* woh = (__half*)p_woh;

    cudaFuncSetAttribute(gemm_nt_fp16, cudaFuncAttributeMaxDynamicSharedMemorySize,
                         GEMM_SMEM);
    cudaFuncSetAttribute(ssm_intra_kernel, cudaFuncAttributeMaxDynamicSharedMemorySize,
                         SM_K1_BYTES);
    cudaFuncSetAttribute(yoff64_kernel, cudaFuncAttributeMaxDynamicSharedMemorySize,
                         SM_K3_BYTES);

    // 0. fp16 conversions
    {
        int n4 = MROWS * D_MODEL / 4;
        conv_fp16_kernel<<<(n4 + 255) / 256, 256>>>(u, uh, n4);
        n4 = DIP * D_MODEL / 4;
        conv_fp16_kernel<<<(n4 + 255) / 256, 256>>>(W_in, wih, n4);
        n4 = D_MODEL * DSSM / 4;
        conv_fp16_kernel<<<(n4 + 255) / 256, 256>>>(W_out, woh, n4);
    }

    // 1. in_proj (fp16 single-pass)
    gemm_nt_fp16<<<dim3((DIP + 127) / 128, MROWS / 128), 256, GEMM_SMEM>>>(
        uh, wih, zx, MROWS, DIP, D_MODEL);

    // 2. conv1d + silu
    {
        size_t total4 = (size_t)(MROWS / 4) * CONVD;
        conv_silu_kernel<<<(unsigned)((total4 + 255) / 256), 256>>>(zx, conv_w, conv_b, xbc);
    }

    // 3. intra-chunk SSM (single fp16 mma)
    ssm_intra_kernel<<<dim3(NC64, NH / HPB, BATCH), 256, SM_K1_BYTES>>>(
        zx, xbc, dt_bias, A_log, Dv, y, states, cs);

    // 4. inter-chunk recurrence
    chunk_scan64<<<dim3(32, NH, BATCH), 256>>>(states, cs, prev);

    // 5. Y_off (single fp16 mma, 8 heads/block)
    yoff64_kernel<<<dim3(NC64, NH / HPB, BATCH), 256, SM_K3_BYTES>>>(xbc, prev, cs, y);

    // 6. gate + RMSNorm -> fp16
    gate_norm_kernel<<<MROWS, 256>>>(zx, y, norm_w, ynh);

    // 7. out_proj (fp16 single-pass)
    gemm_nt_fp16<<<dim3(D_MODEL / 128, MROWS / 128), 256, GEMM_SMEM>>>(
        ynh, woh, out, MROWS, D_MODEL, DSSM);
}

// round 12
// speedup vs baseline: 4.5803x; 1.0456x over previous
#include <cuda_runtime.h>
#include <cuda_bf16.h>
#include <cuda_fp16.h>
#include <math.h>
#include <stdint.h>

#define BATCH 2
#define L_SEQ 4096
#define D_MODEL 1024
#define DIP 4384          // D_IN_PROJ
#define DSSM 2048
#define CONVD 2304        // CONV_DIM
#define NH 32
#define HD 64
#define DS 128
#define NC64 64           // chunks of 64 per batch
#define TCH 64
#define HPB 8             // heads per block in ssm_intra / yoff
#define MROWS (BATCH * L_SEQ)   // 8192

// ---------------- scratch (device globals; no allocation) ----------------
__device__ float g_zx[(size_t)MROWS * DIP];
__device__ __half g_xbc[(size_t)MROWS * CONVD];
__device__ float g_y[(size_t)MROWS * DSSM];
__device__ __half g_states[(size_t)BATCH * NC64 * NH * HD * DS];
__device__ __half g_prev[(size_t)BATCH * NC64 * NH * HD * DS];
__device__ float g_cs[(size_t)BATCH * NC64 * NH * TCH];

// fp16 buffers for projection GEMMs
__device__ __half g_uh[(size_t)MROWS * D_MODEL];
__device__ __half g_wih[(size_t)DIP * D_MODEL];
__device__ __half g_ynh[(size_t)MROWS * DSSM];
__device__ __half g_woh[(size_t)D_MODEL * DSSM];

// ---------------- helpers ----------------
struct alignas(8) half4 { __half a, b, c, d; };

__device__ __forceinline__ float fast_sigmoid(float x) {
    return 1.f / (1.f + __expf(-x));
}

__device__ __forceinline__ void mma16816h(float* d, const uint32_t* a, const uint32_t* b) {
    asm volatile(
        "mma.sync.aligned.m16n8k16.row.col.f32.f16.f16.f32 "
        "{%0,%1,%2,%3}, {%4,%5,%6,%7}, {%8,%9}, {%0,%1,%2,%3};"
        : "+f"(d[0]), "+f"(d[1]), "+f"(d[2]), "+f"(d[3])
        : "r"(a[0]), "r"(a[1]), "r"(a[2]), "r"(a[3]), "r"(b[0]), "r"(b[1]));
}

__device__ __forceinline__ void ldsm_x4(uint32_t& r0, uint32_t& r1, uint32_t& r2,
                                        uint32_t& r3, uint32_t addr) {
    asm volatile("ldmatrix.sync.aligned.m8n8.x4.shared.b16 {%0,%1,%2,%3}, [%4];"
                 : "=r"(r0), "=r"(r1), "=r"(r2), "=r"(r3) : "r"(addr));
}

__device__ __forceinline__ void cpasync16(uint32_t dst, const void* src, int szvalid) {
    asm volatile("cp.async.cg.shared.global [%0], [%1], 16, %2;"
                 :: "r"(dst), "l"(src), "r"(szvalid) : "memory");
}
#define CPASYNC_COMMIT() asm volatile("cp.async.commit_group;" ::: "memory")
#define CPASYNC_WAIT(n)  asm volatile("cp.async.wait_group %0;" :: "n"(n) : "memory")

// ---------------- fp32 -> fp16 convert ----------------
__global__ void conv_fp16_kernel(const float* __restrict__ x,
                                 __half* __restrict__ o, int n4) {
    int i = blockIdx.x * 256 + threadIdx.x;
    if (i >= n4) return;
    float4 v = ((const float4*)x)[i];
    half4 hv = {__float2half(v.x), __float2half(v.y),
                __float2half(v.z), __float2half(v.w)};
    ((half4*)o)[i] = hv;
}

// ---------------- fp16 single-pass GEMM: C[M,N] = A[M,K] * B[N,K]^T ----------------
#define GK 16
#define GPAD 24
#define NSTAGE 4
#define GEMM_SMEM (NSTAGE * 2 * 128 * GPAD * 2)   // 49152 bytes

__global__ __launch_bounds__(256, 2) void gemm_nt_fp16(
    const __half* __restrict__ A, const __half* __restrict__ B,
    float* __restrict__ C, int M, int N, int K) {
    extern __shared__ __half smh[];
    __half* sA = smh;
    __half* sB = smh + NSTAGE * 128 * GPAD;

    const int tid = threadIdx.x;
    const int wid = tid >> 5, lane = tid & 31;
    const int wm = wid >> 2, wn = wid & 3;
    const int grp = lane >> 2, q2 = (lane & 3) * 2;
    const int rowBase = blockIdx.y * 128;
    const int colBase = blockIdx.x * 128;
    const int lrow = tid >> 1;
    const int lkh = (tid & 1) * 8;

    const int lmRow = lane & 15;
    const int lmK = (lane >> 4) << 3;

    const uint32_t sA_s = (uint32_t)__cvta_generic_to_shared(sA);
    const uint32_t sB_s = (uint32_t)__cvta_generic_to_shared(sB);

    float acc[4][4][4];
#pragma unroll
    for (int i = 0; i < 4; i++)
#pragma unroll
        for (int j = 0; j < 4; j++)
#pragma unroll
            for (int r = 0; r < 4; r++) acc[i][j][r] = 0.f;

    const int nk = K / GK;
#define SIDX(st, r, k) ((((st) * 128 + (r)) * GPAD) + (k))

    const __half* pA = A + (size_t)(rowBase + lrow) * K + lkh;
    int cn = colBase + lrow;
    int bok = (cn < N) ? 16 : 0;
    int cnc = (cn < N) ? cn : 0;
    const __half* pB = B + (size_t)cnc * K + lkh;

    auto load_stage = [&](int st, int kc) {
        int ko = kc * GK;
        cpasync16(sA_s + SIDX(st, lrow, lkh) * 2, pA + ko, 16);
        cpasync16(sB_s + SIDX(st, lrow, lkh) * 2, pB + ko, bok);
        CPASYNC_COMMIT();
    };

    load_stage(0, 0);
    if (nk > 1) load_stage(1, 1);

    for (int k = 0; k < nk; k++) {
        int st = k & (NSTAGE - 1);
        if (k + 2 < nk) {
            load_stage((k + 2) & (NSTAGE - 1), k + 2);
            CPASYNC_WAIT(2);
        } else if (k + 1 < nk) {
            CPASYNC_WAIT(1);
        } else {
            CPASYNC_WAIT(0);
        }
        __syncthreads();

        uint32_t bb[4][2];
        {
            uint32_t r0, r1, r2, r3;
            ldsm_x4(r0, r1, r2, r3, sB_s + SIDX(st, wn * 32 + lmRow, lmK) * 2);
            bb[0][0] = r0; bb[0][1] = r2; bb[1][0] = r1; bb[1][1] = r3;
            ldsm_x4(r0, r1, r2, r3, sB_s + SIDX(st, wn * 32 + 16 + lmRow, lmK) * 2);
            bb[2][0] = r0; bb[2][1] = r2; bb[3][0] = r1; bb[3][1] = r3;
        }
#pragma unroll
        for (int mt = 0; mt < 4; mt++) {
            int r0row = wm * 64 + mt * 16;
            uint32_t aa[4];
            ldsm_x4(aa[0], aa[1], aa[2], aa[3], sA_s + SIDX(st, r0row + lmRow, lmK) * 2);
#pragma unroll
            for (int nt = 0; nt < 4; nt++) mma16816h(acc[mt][nt], aa, bb[nt]);
        }
    }
#pragma unroll
    for (int mt = 0; mt < 4; mt++) {
#pragma unroll
        for (int nt = 0; nt < 4; nt++) {
            int colTile = colBase + wn * 32 + nt * 8;
            if (colTile >= N) continue;
            int r0 = rowBase + wm * 64 + mt * 16 + grp;
            int c0 = colTile + q2;
            *(float2*)&C[(size_t)r0 * N + c0] = make_float2(acc[mt][nt][0], acc[mt][nt][1]);
            *(float2*)&C[(size_t)(r0 + 8) * N + c0] = make_float2(acc[mt][nt][2], acc[mt][nt][3]);
        }
    }
#undef SIDX
}

// ---------------- conv1d + SiLU : 4 t per thread, fp16 output ----------------
__global__ void conv_silu_kernel(const float* __restrict__ zx,
                                 const float* __restrict__ conv_w,
                                 const float* __restrict__ conv_b,
                                 __half* __restrict__ xbc) {
    size_t idx = (size_t)blockIdx.x * 256 + threadIdx.x;
    const size_t total = (size_t)(MROWS / 4) * CONVD;
    if (idx >= total) return;
    int cc = (int)(idx % CONVD);
    size_t r4 = idx / CONVD;
    size_t bt0 = r4 * 4;
    int t0 = (int)(bt0 % L_SEQ);

    float w0 = conv_w[cc * 4 + 0], w1 = conv_w[cc * 4 + 1];
    float w2 = conv_w[cc * 4 + 2], w3 = conv_w[cc * 4 + 3];
    float bia = conv_b[cc];

    float v[7];
#pragma unroll
    for (int j = 0; j < 7; j++) {
        int tt = t0 - 3 + j;
        v[j] = (tt >= 0) ? zx[(bt0 - 3 + j) * DIP + 2048 + cc] : 0.f;
    }
#pragma unroll
    for (int i = 0; i < 4; i++) {
        float acc = bia;
        acc = fmaf(v[i + 0], w0, acc);
        acc = fmaf(v[i + 1], w1, acc);
        acc = fmaf(v[i + 2], w2, acc);
        acc = fmaf(v[i + 3], w3, acc);
        xbc[(bt0 + i) * CONVD + cc] = __float2half(acc * fast_sigmoid(acc));
    }
}

// ---------------- K1: intra-chunk SSM, single-fp16 mma, fp16 inputs ----------------
#define SB_S 136
#define ST_S 66
#define SM_K1_BYTES ((2 * 64 * SB_S + 128 * ST_S + 3 * 64 * ST_S) * 2 + \
                     (64 * ST_S + 2 * HPB * 64 + 64) * 4)

__global__ __launch_bounds__(256, 2) void ssm_intra_kernel(
    const float* __restrict__ zx, const __half* __restrict__ xbc,
    const float* __restrict__ dt_bias, const float* __restrict__ A_log,
    const float* __restrict__ Dvec,
    float* __restrict__ y, __half* __restrict__ states, float* __restrict__ cs_out) {
    extern __shared__ char smraw[];
    __half* sB = (__half*)smraw;
    __half* sC = sB + 64 * SB_S;
    __half* sBT = sC + 64 * SB_S;
    __half* sGh = sBT + 128 * ST_S;
    __half* sX = sGh + 64 * ST_S;
    __half* sXd = sX + 64 * ST_S;
    float* sG = (float*)(sXd + 64 * ST_S);
    float* s_dt = sG + 64 * ST_S;
    float* s_cs = s_dt + HPB * 64;
    float* sEd = s_cs + HPB * 64;

    const int c = blockIdx.x, hg = blockIdx.y, b = blockIdx.z;
    const int h0 = hg * HPB;
    const int tid = threadIdx.x;
    const int wid = tid >> 5, lane = tid & 31;
    const int wm = wid >> 2, wn = wid & 3;
    const int grp = lane >> 2, q2 = (lane & 3) * 2;
    const int row0 = b * L_SEQ + c * TCH;
    const __half* xrow = xbc + (size_t)row0 * CONVD;

    {
        int h = h0 + wid;
        float Ah = -__expf(A_log[h]);
        float bias = dt_bias[h];
        float d0 = zx[(size_t)(row0 + lane) * DIP + 4352 + h] + bias;
        float d1 = zx[(size_t)(row0 + 32 + lane) * DIP + 4352 + h] + bias;
        float dt0 = (d0 > 20.f) ? d0 : log1pf(__expf(d0));
        float dt1 = (d1 > 20.f) ? d1 : log1pf(__expf(d1));
        s_dt[wid * 64 + lane] = dt0;
        s_dt[wid * 64 + 32 + lane] = dt1;
        float v0 = dt0 * Ah, v1 = dt1 * Ah;
#pragma unroll
        for (int off = 1; off < 32; off <<= 1) {
            float n0 = __shfl_up_sync(0xffffffffu, v0, off);
            float n1 = __shfl_up_sync(0xffffffffu, v1, off);
            if (lane >= off) { v0 += n0; v1 += n1; }
        }
        v1 += __shfl_sync(0xffffffffu, v0, 31);
        s_cs[wid * 64 + lane] = v0;
        s_cs[wid * 64 + 32 + lane] = v1;
        size_t cbase = (((size_t)b * NC64 + c) * NH + h) * TCH;
        cs_out[cbase + lane] = v0;
        cs_out[cbase + 32 + lane] = v1;
    }

    for (int idx = tid; idx < 64 * 128; idx += 256) {
        int s = idx >> 7, n = idx & 127;
        __half bh = xrow[(size_t)s * CONVD + 2048 + n];
        __half ch = xrow[(size_t)s * CONVD + 2176 + n];
        sB[s * SB_S + n] = bh;
        sC[s * SB_S + n] = ch;
        sBT[n * ST_S + s] = bh;
    }
    __syncthreads();

    // G = C * B^T (shared across heads)
    {
        float g[2][2][4];
#pragma unroll
        for (int i = 0; i < 2; i++)
#pragma unroll
            for (int j = 0; j < 2; j++)
#pragma unroll
                for (int r = 0; r < 4; r++) g[i][j][r] = 0.f;
        for (int kb = 0; kb < 128; kb += 16) {
            uint32_t bb[2][2];
#pragma unroll
            for (int nt = 0; nt < 2; nt++) {
                int c0 = wn * 16 + nt * 8 + grp;
                bb[nt][0] = *(const uint32_t*)&sB[c0 * SB_S + kb + q2];
                bb[nt][1] = *(const uint32_t*)&sB[c0 * SB_S + kb + q2 + 8];
            }
#pragma unroll
            for (int mt = 0; mt < 2; mt++) {
                int r0 = wm * 32 + mt * 16 + grp;
                uint32_t aa[4];
                aa[0] = *(const uint32_t*)&sC[r0 * SB_S + kb + q2];
                aa[1] = *(const uint32_t*)&sC[(r0 + 8) * SB_S + kb + q2];
                aa[2] = *(const uint32_t*)&sC[r0 * SB_S + kb + q2 + 8];
                aa[3] = *(const uint32_t*)&sC[(r0 + 8) * SB_S + kb + q2 + 8];
#pragma unroll
                for (int nt = 0; nt < 2; nt++) mma16816h(g[mt][nt], aa, bb[nt]);
            }
        }
#pragma unroll
        for (int mt = 0; mt < 2; mt++)
#pragma unroll
            for (int nt = 0; nt < 2; nt++) {
                int t = wm * 32 + mt * 16 + grp;
                int s = wn * 16 + nt * 8 + q2;
                *(float2*)&sG[t * ST_S + s] = make_float2(g[mt][nt][0], g[mt][nt][1]);
                *(float2*)&sG[(t + 8) * ST_S + s] = make_float2(g[mt][nt][2], g[mt][nt][3]);
            }
    }

    for (int hl = 0; hl < HPB; hl++) {
        int h = h0 + hl;
        __syncthreads();
        const float* csh = s_cs + hl * 64;
        const float* dth = s_dt + hl * 64;
        const float csL = csh[63];
        if (tid < 64) sEd[tid] = __expf(csL - csh[tid]);
        for (int idx = tid; idx < 64 * 64; idx += 256) {
            int t = idx >> 6, s = idx & 63;
            float val = 0.f;
            if (t >= s) val = sG[t * ST_S + s] * __expf(csh[t] - csh[s]);
            sGh[t * ST_S + s] = __float2half(val);
        }
        __syncthreads();
        for (int idx = tid; idx < 64 * 64; idx += 256) {
            int s = idx >> 6, p = idx & 63;
            float xv = __half2float(xrow[(size_t)s * CONVD + h * 64 + p]);
            float xt = xv * dth[s];
            sX[p * ST_S + s] = __float2half(xt);
            sXd[p * ST_S + s] = __float2half(xt * sEd[s]);
        }
        __syncthreads();

        // Y_diag = G~ * x~
        {
            float yd[2][2][4];
#pragma unroll
            for (int i = 0; i < 2; i++)
#pragma unroll
                for (int j = 0; j < 2; j++)
#pragma unroll
                    for (int r = 0; r < 4; r++) yd[i][j][r] = 0.f;
            for (int kb = 0; kb < 64; kb += 16) {
                uint32_t bb[2][2];
#pragma unroll
                for (int nt = 0; nt < 2; nt++) {
                    int c0 = wn * 16 + nt * 8 + grp;
                    bb[nt][0] = *(const uint32_t*)&sX[c0 * ST_S + kb + q2];
                    bb[nt][1] = *(const uint32_t*)&sX[c0 * ST_S + kb + q2 + 8];
                }
#pragma unroll
                for (int mt = 0; mt < 2; mt++) {
                    int r0 = wm * 32 + mt * 16 + grp;
                    uint32_t aa[4];
                    aa[0] = *(const uint32_t*)&sGh[r0 * ST_S + kb + q2];
                    aa[1] = *(const uint32_t*)&sGh[(r0 + 8) * ST_S + kb + q2];
                    aa[2] = *(const uint32_t*)&sGh[r0 * ST_S + kb + q2 + 8];
                    aa[3] = *(const uint32_t*)&sGh[(r0 + 8) * ST_S + kb + q2 + 8];
#pragma unroll
                    for (int nt = 0; nt < 2; nt++) mma16816h(yd[mt][nt], aa, bb[nt]);
                }
            }
            float Dh = Dvec[h];
#pragma unroll
            for (int mt = 0; mt < 2; mt++)
#pragma unroll
                for (int nt = 0; nt < 2; nt++) {
                    int t0 = wm * 32 + mt * 16 + grp;
                    int p0 = wn * 16 + nt * 8 + q2;
#pragma unroll
                    for (int rr = 0; rr < 2; rr++) {
                        int t = t0 + rr * 8;
                        __half2 xv2 = *(const __half2*)&xrow[(size_t)t * CONVD + h * 64 + p0];
                        float2 xv = __half22float2(xv2);
                        float2 o;
                        o.x = fmaf(Dh, xv.x, yd[mt][nt][rr * 2 + 0]);
                        o.y = fmaf(Dh, xv.y, yd[mt][nt][rr * 2 + 1]);
                        *(float2*)&g_y[(size_t)(row0 + t) * DSSM + h * 64 + p0] = o;
                    }
                }
        }

        // state = x~d^T * B  -> fp16 storage
        {
            float st[2][4][4];
#pragma unroll
            for (int i = 0; i < 2; i++)
#pragma unroll
                for (int j = 0; j < 4; j++)
#pragma unroll
                    for (int r = 0; r < 4; r++) st[i][j][r] = 0.f;
            for (int kb = 0; kb < 64; kb += 16) {
                uint32_t bb[4][2];
#pragma unroll
                for (int nt = 0; nt < 4; nt++) {
                    int c0 = wn * 32 + nt * 8 + grp;
                    bb[nt][0] = *(const uint32_t*)&sBT[c0 * ST_S + kb + q2];
                    bb[nt][1] = *(const uint32_t*)&sBT[c0 * ST_S + kb + q2 + 8];
                }
#pragma unroll
                for (int mt = 0; mt < 2; mt++) {
                    int r0 = wm * 32 + mt * 16 + grp;
                    uint32_t aa[4];
                    aa[0] = *(const uint32_t*)&sXd[r0 * ST_S + kb + q2];
                    aa[1] = *(const uint32_t*)&sXd[(r0 + 8) * ST_S + kb + q2];
                    aa[2] = *(const uint32_t*)&sXd[r0 * ST_S + kb + q2 + 8];
                    aa[3] = *(const uint32_t*)&sXd[(r0 + 8) * ST_S + kb + q2 + 8];
#pragma unroll
                    for (int nt = 0; nt < 4; nt++) mma16816h(st[mt][nt], aa, bb[nt]);
                }
            }
            size_t sbase = (((size_t)b * NC64 + c) * NH + h) * (size_t)(HD * DS);
#pragma unroll
            for (int mt = 0; mt < 2; mt++)
#pragma unroll
                for (int nt = 0; nt < 4; nt++) {
                    int p0 = wm * 32 + mt * 16 + grp;
                    int n0 = wn * 32 + nt * 8 + q2;
                    *(__half2*)&states[sbase + (size_t)p0 * DS + n0] =
                        __floats2half2_rn(st[mt][nt][0], st[mt][nt][1]);
                    *(__half2*)&states[sbase + (size_t)(p0 + 8) * DS + n0] =
                        __floats2half2_rn(st[mt][nt][2], st[mt][nt][3]);
                }
        }
    }
}

// ---------------- K2: inter-chunk recurrence (half2 vectorized) ----------------
__global__ void chunk_scan64(const __half* __restrict__ states,
                             const float* __restrict__ cs,
                             __half* __restrict__ prev) {
    const int seg = blockIdx.x, h = blockIdx.y, b = blockIdx.z;
    const int e2 = seg * 256 + threadIdx.x;   // half2 index, 0..4095
    float2 P = make_float2(0.f, 0.f);
    for (int c = 0; c < NC64; c++) {
        size_t base = ((size_t)b * NC64 + c) * NH + h;
        float sc = __expf(cs[base * TCH + TCH - 1]);
        size_t off = base * (size_t)(HD * DS / 2) + e2;
        ((__half2*)prev)[off] = __floats2half2_rn(P.x, P.y);
        float2 sv = __half22float2(((const __half2*)states)[off]);
        P.x = fmaf(P.x, sc, sv.x);
        P.y = fmaf(P.y, sc, sv.y);
    }
}

// ---------------- K3: Y += diag(exp(cs)) * C * prev^T, fp16 inputs ----------------
#define SM_K3_BYTES ((2 * 64 * SB_S) * 2 + 64 * 4)
__global__ __launch_bounds__(256, 2) void yoff64_kernel(
    const __half* __restrict__ xbc, const __half* __restrict__ prev,
    const float* __restrict__ cs, float* __restrict__ y) {
    extern __shared__ char smraw[];
    __half* sC = (__half*)smraw;
    __half* sP = sC + 64 * SB_S;
    float* sE = (float*)(sP + 64 * SB_S);

    const int c = blockIdx.x, hg = blockIdx.y, b = blockIdx.z;
    const int h0 = hg * HPB;
    const int tid = threadIdx.x;
    const int wid = tid >> 5, lane = tid & 31;
    const int wm = wid >> 2, wn = wid & 3;
    const int grp = lane >> 2, q2 = (lane & 3) * 2;
    const int row0 = b * L_SEQ + c * TCH;
    const __half* xrow = xbc + (size_t)row0 * CONVD;

    for (int idx = tid; idx < 64 * 128; idx += 256) {
        int t = idx >> 7, n = idx & 127;
        sC[t * SB_S + n] = xrow[(size_t)t * CONVD + 2176 + n];
    }

    for (int hl = 0; hl < HPB; hl++) {
        int h = h0 + hl;
        __syncthreads();
        if (tid < 64)
            sE[tid] = __expf(cs[(((size_t)b * NC64 + c) * NH + h) * TCH + tid]);
        size_t pbase = (((size_t)b * NC64 + c) * NH + h) * (size_t)(HD * DS);
        for (int idx = tid; idx < 64 * 128; idx += 256) {
            int p = idx >> 7, n = idx & 127;
            sP[p * SB_S + n] = prev[pbase + (size_t)p * DS + n];
        }
        __syncthreads();

        float acc[2][2][4];
#pragma unroll
        for (int i = 0; i < 2; i++)
#pragma unroll
            for (int j = 0; j < 2; j++)
#pragma unroll
                for (int r = 0; r < 4; r++) acc[i][j][r] = 0.f;
        for (int kb = 0; kb < 128; kb += 16) {
            uint32_t bb[2][2];
#pragma unroll
            for (int nt = 0; nt < 2; nt++) {
                int c0 = wn * 16 + nt * 8 + grp;
                bb[nt][0] = *(const uint32_t*)&sP[c0 * SB_S + kb + q2];
                bb[nt][1] = *(const uint32_t*)&sP[c0 * SB_S + kb + q2 + 8];
            }
#pragma unroll
            for (int mt = 0; mt < 2; mt++) {
                int r0 = wm * 32 + mt * 16 + grp;
                uint32_t aa[4];
                aa[0] = *(const uint32_t*)&sC[r0 * SB_S + kb + q2];
                aa[1] = *(const uint32_t*)&sC[(r0 + 8) * SB_S + kb + q2];
                aa[2] = *(const uint32_t*)&sC[r0 * SB_S + kb + q2 + 8];
                aa[3] = *(const uint32_t*)&sC[(r0 + 8) * SB_S + kb + q2 + 8];
#pragma unroll
                for (int nt = 0; nt < 2; nt++) mma16816h(acc[mt][nt], aa, bb[nt]);
            }
        }
#pragma unroll
        for (int mt = 0; mt < 2; mt++)
#pragma unroll
            for (int nt = 0; nt < 2; nt++) {
                int t0 = wm * 32 + mt * 16 + grp;
                int p0 = wn * 16 + nt * 8 + q2;
#pragma unroll
                for (int rr = 0; rr < 2; rr++) {
                    int t = t0 + rr * 8;
                    float e = sE[t];
                    size_t addr = (size_t)(row0 + t) * DSSM + h * 64 + p0;
                    float2 old = *(float2*)&y[addr];
                    old.x = fmaf(e, acc[mt][nt][rr * 2 + 0], old.x);
                    old.y = fmaf(e, acc[mt][nt][rr * 2 + 1], old.y);
                    *(float2*)&y[addr] = old;
                }
            }
    }
}

// ---------------- gate (y * silu(z)) + RMSNorm -> fp16 ----------------
__global__ void gate_norm_kernel(const float* __restrict__ zx,
                                 const float* __restrict__ y,
                                 const float* __restrict__ norm_w,
                                 __half* __restrict__ ynh) {
    const int row = blockIdx.x;
    const int tid = threadIdx.x;
    const float* yrow = y + (size_t)row * DSSM;
    const float* zrow = zx + (size_t)row * DIP;
    float v[8];
    float ss = 0.f;
#pragma unroll
    for (int k = 0; k < 8; k++) {
        int e = tid + k * 256;
        float z = zrow[e];
        float vv = yrow[e] * (z * fast_sigmoid(z));
        v[k] = vv;
        ss = fmaf(vv, vv, ss);
    }
    __shared__ float red[256];
    red[tid] = ss;
    __syncthreads();
    for (int s = 128; s > 0; s >>= 1) {
        if (tid < s) red[tid] += red[tid + s];
        __syncthreads();
    }
    float r = rsqrtf(red[0] / (float)DSSM + 1e-5f);
#pragma unroll
    for (int k = 0; k < 8; k++) {
        int e = tid + k * 256;
        ynh[(size_t)row * DSSM + e] = __float2half(v[k] * r * norm_w[e]);
    }
}

// ---------------- host launch ----------------
extern "C" void kernel_launch(void* const* d_in, const int* in_sizes, int n_in,
                              void* d_out, int out_size) {
    const float* u       = (const float*)d_in[0];
    const float* W_in    = (const float*)d_in[1];
    const float* conv_w  = (const float*)d_in[2];
    const float* conv_b  = (const float*)d_in[3];
    const float* dt_bias = (const float*)d_in[4];
    const float* A_log   = (const float*)d_in[5];
    const float* Dv      = (const float*)d_in[6];
    const float* norm_w  = (const float*)d_in[7];
    const float* W_out   = (const float*)d_in[8];
    float* out = (float*)d_out;

    void *p_zx, *p_xbc, *p_y, *p_states, *p_prev, *p_cs;
    void *p_uh, *p_wih, *p_ynh, *p_woh;
    cudaGetSymbolAddress(&p_zx, g_zx);
    cudaGetSymbolAddress(&p_xbc, g_xbc);
    cudaGetSymbolAddress(&p_y, g_y);
    cudaGetSymbolAddress(&p_states, g_states);
    cudaGetSymbolAddress(&p_prev, g_prev);
    cudaGetSymbolAddress(&p_cs, g_cs);
    cudaGetSymbolAddress(&p_uh, g_uh);
    cudaGetSymbolAddress(&p_wih, g_wih);
    cudaGetSymbolAddress(&p_ynh, g_ynh);
    cudaGetSymbolAddress(&p_woh, g_woh);
    float* zx = (float*)p_zx;
    __half* xbc = (__half*)p_xbc;
    float* y = (float*)p_y;
    __half* states = (__half*)p_states;
    __half* prev = (__half*)p_prev;
    float* cs = (float*)p_cs;
    __half* uh = (__half*)p_uh;
    __half* wih = (__half*)p_wih;
    __half* ynh = (__half*)p_ynh;
    __half* woh = (__half*)p_woh;

    cudaFuncSetAttribute(gemm_nt_fp16, cudaFuncAttributeMaxDynamicSharedMemorySize,
                         GEMM_SMEM);
    cudaFuncSetAttribute(ssm_intra_kernel, cudaFuncAttributeMaxDynamicSharedMemorySize,
                         SM_K1_BYTES);
    cudaFuncSetAttribute(yoff64_kernel, cudaFuncAttributeMaxDynamicSharedMemorySize,
                         SM_K3_BYTES);

    // 0. fp16 conversions
    {
        int n4 = MROWS * D_MODEL / 4;
        conv_fp16_kernel<<<(n4 + 255) / 256, 256>>>(u, uh, n4);
        n4 = DIP * D_MODEL / 4;
        conv_fp16_kernel<<<(n4 + 255) / 256, 256>>>(W_in, wih, n4);
        n4 = D_MODEL * DSSM / 4;
        conv_fp16_kernel<<<(n4 + 255) / 256, 256>>>(W_out, woh, n4);
    }

    // 1. in_proj (fp16 single-pass)
    gemm_nt_fp16<<<dim3((DIP + 127) / 128, MROWS / 128), 256, GEMM_SMEM>>>(
        uh, wih, zx, MROWS, DIP, D_MODEL);

    // 2. conv1d + silu -> fp16
    {
        size_t total4 = (size_t)(MROWS / 4) * CONVD;
        conv_silu_kernel<<<(unsigned)((total4 + 255) / 256), 256>>>(zx, conv_w, conv_b, xbc);
    }

    // 3. intra-chunk SSM (single fp16 mma, fp16 states out)
    ssm_intra_kernel<<<dim3(NC64, NH / HPB, BATCH), 256, SM_K1_BYTES>>>(
        zx, xbc, dt_bias, A_log, Dv, y, states, cs);

    // 4. inter-chunk recurrence (half2)
    chunk_scan64<<<dim3(16, NH, BATCH), 256>>>(states, cs, prev);

    // 5. Y_off (fp16 inputs, 8 heads/block)
    yoff64_kernel<<<dim3(NC64, NH / HPB, BATCH), 256, SM_K3_BYTES>>>(xbc, prev, cs, y);

    // 6. gate + RMSNorm -> fp16
    gate_norm_kernel<<<MROWS, 256>>>(zx, y, norm_w, ynh);

    // 7. out_proj (fp16 single-pass)
    gemm_nt_fp16<<<dim3(D_MODEL / 128, MROWS / 128), 256, GEMM_SMEM>>>(
        ynh, woh, out, MROWS, D_MODEL, DSSM);
}

// round 13
// speedup vs baseline: 4.7834x; 1.0443x over previous
#include <cuda_runtime.h>
#include <cuda_bf16.h>
#include <cuda_fp16.h>
#include <math.h>
#include <stdint.h>

#define BATCH 2
#define L_SEQ 4096
#define D_MODEL 1024
#define DIP 4384          // D_IN_PROJ
#define DSSM 2048
#define CONVD 2304        // CONV_DIM
#define NH 32
#define HD 64
#define DS 128
#define NC64 64           // chunks of 64 per batch
#define TCH 64
#define HPB 8             // heads per block
#define MROWS (BATCH * L_SEQ)   // 8192

// ---------------- scratch (device globals; no allocation) ----------------
__device__ __half g_zxh[(size_t)MROWS * DIP];
__device__ __half g_xbc[(size_t)MROWS * CONVD];
__device__ float g_y[(size_t)MROWS * DSSM];
__device__ __half g_states[(size_t)BATCH * NC64 * NH * HD * DS];
__device__ __half g_prev[(size_t)BATCH * NC64 * NH * HD * DS];
__device__ float g_cs[(size_t)BATCH * NC64 * NH * TCH];
__device__ float g_dt[(size_t)BATCH * NC64 * NH * TCH];

__device__ __half g_uh[(size_t)MROWS * D_MODEL];
__device__ __half g_wih[(size_t)DIP * D_MODEL];
__device__ __half g_ynh[(size_t)MROWS * DSSM];
__device__ __half g_woh[(size_t)D_MODEL * DSSM];

// ---------------- helpers ----------------
struct alignas(8) half4 { __half a, b, c, d; };

__device__ __forceinline__ float fast_sigmoid(float x) {
    return 1.f / (1.f + __expf(-x));
}

__device__ __forceinline__ void mma16816h(float* d, const uint32_t* a, const uint32_t* b) {
    asm volatile(
        "mma.sync.aligned.m16n8k16.row.col.f32.f16.f16.f32 "
        "{%0,%1,%2,%3}, {%4,%5,%6,%7}, {%8,%9}, {%0,%1,%2,%3};"
        : "+f"(d[0]), "+f"(d[1]), "+f"(d[2]), "+f"(d[3])
        : "r"(a[0]), "r"(a[1]), "r"(a[2]), "r"(a[3]), "r"(b[0]), "r"(b[1]));
}

__device__ __forceinline__ void ldsm_x4(uint32_t& r0, uint32_t& r1, uint32_t& r2,
                                        uint32_t& r3, uint32_t addr) {
    asm volatile("ldmatrix.sync.aligned.m8n8.x4.shared.b16 {%0,%1,%2,%3}, [%4];"
                 : "=r"(r0), "=r"(r1), "=r"(r2), "=r"(r3) : "r"(addr));
}

__device__ __forceinline__ void cpasync16(uint32_t dst, const void* src, int szvalid) {
    asm volatile("cp.async.cg.shared.global [%0], [%1], 16, %2;"
                 :: "r"(dst), "l"(src), "r"(szvalid) : "memory");
}
#define CPASYNC_COMMIT() asm volatile("cp.async.commit_group;" ::: "memory")
#define CPASYNC_WAIT(n)  asm volatile("cp.async.wait_group %0;" :: "n"(n) : "memory")

// ---------------- fp32 -> fp16 convert ----------------
__global__ void conv_fp16_kernel(const float* __restrict__ x,
                                 __half* __restrict__ o, int n4) {
    int i = blockIdx.x * 256 + threadIdx.x;
    if (i >= n4) return;
    float4 v = ((const float4*)x)[i];
    half4 hv = {__float2half(v.x), __float2half(v.y),
                __float2half(v.z), __float2half(v.w)};
    ((half4*)o)[i] = hv;
}

// ---------------- fp16 single-pass GEMM, templated output ----------------
#define GK 16
#define GPAD 24
#define NSTAGE 4
#define GEMM_SMEM (NSTAGE * 2 * 128 * GPAD * 2)   // 49152 bytes

template <typename OutT>
__global__ __launch_bounds__(256, 2) void gemm_nt_fp16(
    const __half* __restrict__ A, const __half* __restrict__ B,
    OutT* __restrict__ C, int M, int N, int K) {
    extern __shared__ __half smh[];
    __half* sA = smh;
    __half* sB = smh + NSTAGE * 128 * GPAD;

    const int tid = threadIdx.x;
    const int wid = tid >> 5, lane = tid & 31;
    const int wm = wid >> 2, wn = wid & 3;
    const int grp = lane >> 2, q2 = (lane & 3) * 2;
    const int rowBase = blockIdx.y * 128;
    const int colBase = blockIdx.x * 128;
    const int lrow = tid >> 1;
    const int lkh = (tid & 1) * 8;

    const int lmRow = lane & 15;
    const int lmK = (lane >> 4) << 3;

    const uint32_t sA_s = (uint32_t)__cvta_generic_to_shared(sA);
    const uint32_t sB_s = (uint32_t)__cvta_generic_to_shared(sB);

    float acc[4][4][4];
#pragma unroll
    for (int i = 0; i < 4; i++)
#pragma unroll
        for (int j = 0; j < 4; j++)
#pragma unroll
            for (int r = 0; r < 4; r++) acc[i][j][r] = 0.f;

    const int nk = K / GK;
#define SIDX(st, r, k) ((((st) * 128 + (r)) * GPAD) + (k))

    const __half* pA = A + (size_t)(rowBase + lrow) * K + lkh;
    int cn = colBase + lrow;
    int bok = (cn < N) ? 16 : 0;
    int cnc = (cn < N) ? cn : 0;
    const __half* pB = B + (size_t)cnc * K + lkh;

    auto load_stage = [&](int st, int kc) {
        int ko = kc * GK;
        cpasync16(sA_s + SIDX(st, lrow, lkh) * 2, pA + ko, 16);
        cpasync16(sB_s + SIDX(st, lrow, lkh) * 2, pB + ko, bok);
        CPASYNC_COMMIT();
    };

    load_stage(0, 0);
    if (nk > 1) load_stage(1, 1);

    for (int k = 0; k < nk; k++) {
        int st = k & (NSTAGE - 1);
        if (k + 2 < nk) {
            load_stage((k + 2) & (NSTAGE - 1), k + 2);
            CPASYNC_WAIT(2);
        } else if (k + 1 < nk) {
            CPASYNC_WAIT(1);
        } else {
            CPASYNC_WAIT(0);
        }
        __syncthreads();

        uint32_t bb[4][2];
        {
            uint32_t r0, r1, r2, r3;
            ldsm_x4(r0, r1, r2, r3, sB_s + SIDX(st, wn * 32 + lmRow, lmK) * 2);
            bb[0][0] = r0; bb[0][1] = r2; bb[1][0] = r1; bb[1][1] = r3;
            ldsm_x4(r0, r1, r2, r3, sB_s + SIDX(st, wn * 32 + 16 + lmRow, lmK) * 2);
            bb[2][0] = r0; bb[2][1] = r2; bb[3][0] = r1; bb[3][1] = r3;
        }
#pragma unroll
        for (int mt = 0; mt < 4; mt++) {
            int r0row = wm * 64 + mt * 16;
            uint32_t aa[4];
            ldsm_x4(aa[0], aa[1], aa[2], aa[3], sA_s + SIDX(st, r0row + lmRow, lmK) * 2);
#pragma unroll
            for (int nt = 0; nt < 4; nt++) mma16816h(acc[mt][nt], aa, bb[nt]);
        }
    }
#pragma unroll
    for (int mt = 0; mt < 4; mt++) {
#pragma unroll
        for (int nt = 0; nt < 4; nt++) {
            int colTile = colBase + wn * 32 + nt * 8;
            if (colTile >= N) continue;
            int r0 = rowBase + wm * 64 + mt * 16 + grp;
            int c0 = colTile + q2;
            if constexpr (sizeof(OutT) == 2) {
                *(__half2*)&C[(size_t)r0 * N + c0] =
                    __floats2half2_rn(acc[mt][nt][0], acc[mt][nt][1]);
                *(__half2*)&C[(size_t)(r0 + 8) * N + c0] =
                    __floats2half2_rn(acc[mt][nt][2], acc[mt][nt][3]);
            } else {
                *(float2*)&C[(size_t)r0 * N + c0] = make_float2(acc[mt][nt][0], acc[mt][nt][1]);
                *(float2*)&C[(size_t)(r0 + 8) * N + c0] = make_float2(acc[mt][nt][2], acc[mt][nt][3]);
            }
        }
    }
#undef SIDX
}

// ---------------- conv1d + SiLU : 4 t per thread, fp16 in/out ----------------
__global__ void conv_silu_kernel(const __half* __restrict__ zxh,
                                 const float* __restrict__ conv_w,
                                 const float* __restrict__ conv_b,
                                 __half* __restrict__ xbc) {
    size_t idx = (size_t)blockIdx.x * 256 + threadIdx.x;
    const size_t total = (size_t)(MROWS / 4) * CONVD;
    if (idx >= total) return;
    int cc = (int)(idx % CONVD);
    size_t r4 = idx / CONVD;
    size_t bt0 = r4 * 4;
    int t0 = (int)(bt0 % L_SEQ);

    float w0 = conv_w[cc * 4 + 0], w1 = conv_w[cc * 4 + 1];
    float w2 = conv_w[cc * 4 + 2], w3 = conv_w[cc * 4 + 3];
    float bia = conv_b[cc];

    float v[7];
#pragma unroll
    for (int j = 0; j < 7; j++) {
        int tt = t0 - 3 + j;
        v[j] = (tt >= 0) ? __half2float(zxh[(bt0 - 3 + j) * DIP + 2048 + cc]) : 0.f;
    }
#pragma unroll
    for (int i = 0; i < 4; i++) {
        float acc = bia;
        acc = fmaf(v[i + 0], w0, acc);
        acc = fmaf(v[i + 1], w1, acc);
        acc = fmaf(v[i + 2], w2, acc);
        acc = fmaf(v[i + 3], w3, acc);
        xbc[(bt0 + i) * CONVD + cc] = __float2half(acc * fast_sigmoid(acc));
    }
}

// ---------------- K1a: dt/cs + per-chunk states only ----------------
#define SB_S 136
#define ST_S 66
#define SM_K1A_BYTES ((128 * ST_S + 64 * ST_S) * 2 + (2 * HPB * 64 + 64) * 4)

__global__ __launch_bounds__(256, 2) void ssm_states_kernel(
    const __half* __restrict__ zxh, const __half* __restrict__ xbc,
    const float* __restrict__ dt_bias, const float* __restrict__ A_log,
    __half* __restrict__ states, float* __restrict__ cs_out, float* __restrict__ dt_out) {
    extern __shared__ char smraw[];
    __half* sBT = (__half*)smraw;                 // 128 x ST_S (n, s)
    __half* sXd = sBT + 128 * ST_S;               // 64 x ST_S  (p, s)
    float* s_dt = (float*)(sXd + 64 * ST_S);      // HPB x 64
    float* s_cs = s_dt + HPB * 64;                // HPB x 64
    float* sEd = s_cs + HPB * 64;                 // 64

    const int c = blockIdx.x, hg = blockIdx.y, b = blockIdx.z;
    const int h0 = hg * HPB;
    const int tid = threadIdx.x;
    const int wid = tid >> 5, lane = tid & 31;
    const int wm = wid >> 2, wn = wid & 3;
    const int grp = lane >> 2, q2 = (lane & 3) * 2;
    const int row0 = b * L_SEQ + c * TCH;
    const __half* xrow = xbc + (size_t)row0 * CONVD;

    {
        int h = h0 + wid;
        float Ah = -__expf(A_log[h]);
        float bias = dt_bias[h];
        float d0 = __half2float(zxh[(size_t)(row0 + lane) * DIP + 4352 + h]) + bias;
        float d1 = __half2float(zxh[(size_t)(row0 + 32 + lane) * DIP + 4352 + h]) + bias;
        float dt0 = (d0 > 20.f) ? d0 : log1pf(__expf(d0));
        float dt1 = (d1 > 20.f) ? d1 : log1pf(__expf(d1));
        s_dt[wid * 64 + lane] = dt0;
        s_dt[wid * 64 + 32 + lane] = dt1;
        float v0 = dt0 * Ah, v1 = dt1 * Ah;
#pragma unroll
        for (int off = 1; off < 32; off <<= 1) {
            float n0 = __shfl_up_sync(0xffffffffu, v0, off);
            float n1 = __shfl_up_sync(0xffffffffu, v1, off);
            if (lane >= off) { v0 += n0; v1 += n1; }
        }
        v1 += __shfl_sync(0xffffffffu, v0, 31);
        s_cs[wid * 64 + lane] = v0;
        s_cs[wid * 64 + 32 + lane] = v1;
        size_t cbase = (((size_t)b * NC64 + c) * NH + h) * TCH;
        cs_out[cbase + lane] = v0;
        cs_out[cbase + 32 + lane] = v1;
        dt_out[cbase + lane] = dt0;
        dt_out[cbase + 32 + lane] = dt1;
    }

    for (int idx = tid; idx < 64 * 128; idx += 256) {
        int s = idx >> 7, n = idx & 127;
        sBT[n * ST_S + s] = xrow[(size_t)s * CONVD + 2048 + n];
    }
    __syncthreads();

    for (int hl = 0; hl < HPB; hl++) {
        int h = h0 + hl;
        const float* csh = s_cs + hl * 64;
        const float* dth = s_dt + hl * 64;
        const float csL = csh[63];
        if (tid < 64) sEd[tid] = __expf(csL - csh[tid]);
        __syncthreads();
        for (int idx = tid; idx < 64 * 64; idx += 256) {
            int s = idx >> 6, p = idx & 63;
            float xv = __half2float(xrow[(size_t)s * CONVD + h * 64 + p]);
            sXd[p * ST_S + s] = __float2half(xv * dth[s] * sEd[s]);
        }
        __syncthreads();

        float st[2][4][4];
#pragma unroll
        for (int i = 0; i < 2; i++)
#pragma unroll
            for (int j = 0; j < 4; j++)
#pragma unroll
                for (int r = 0; r < 4; r++) st[i][j][r] = 0.f;
        for (int kb = 0; kb < 64; kb += 16) {
            uint32_t bb[4][2];
#pragma unroll
            for (int nt = 0; nt < 4; nt++) {
                int c0 = wn * 32 + nt * 8 + grp;
                bb[nt][0] = *(const uint32_t*)&sBT[c0 * ST_S + kb + q2];
                bb[nt][1] = *(const uint32_t*)&sBT[c0 * ST_S + kb + q2 + 8];
            }
#pragma unroll
            for (int mt = 0; mt < 2; mt++) {
                int r0 = wm * 32 + mt * 16 + grp;
                uint32_t aa[4];
                aa[0] = *(const uint32_t*)&sXd[r0 * ST_S + kb + q2];
                aa[1] = *(const uint32_t*)&sXd[(r0 + 8) * ST_S + kb + q2];
                aa[2] = *(const uint32_t*)&sXd[r0 * ST_S + kb + q2 + 8];
                aa[3] = *(const uint32_t*)&sXd[(r0 + 8) * ST_S + kb + q2 + 8];
#pragma unroll
                for (int nt = 0; nt < 4; nt++) mma16816h(st[mt][nt], aa, bb[nt]);
            }
        }
        size_t sbase = (((size_t)b * NC64 + c) * NH + h) * (size_t)(HD * DS);
#pragma unroll
        for (int mt = 0; mt < 2; mt++)
#pragma unroll
            for (int nt = 0; nt < 4; nt++) {
                int p0 = wm * 32 + mt * 16 + grp;
                int n0 = wn * 32 + nt * 8 + q2;
                *(__half2*)&states[sbase + (size_t)p0 * DS + n0] =
                    __floats2half2_rn(st[mt][nt][0], st[mt][nt][1]);
                *(__half2*)&states[sbase + (size_t)(p0 + 8) * DS + n0] =
                    __floats2half2_rn(st[mt][nt][2], st[mt][nt][3]);
            }
        __syncthreads();   // protect sXd before next head's fill
    }
}

// ---------------- K2: inter-chunk recurrence (half2 vectorized) ----------------
__global__ void chunk_scan64(const __half* __restrict__ states,
                             const float* __restrict__ cs,
                             __half* __restrict__ prev) {
    const int seg = blockIdx.x, h = blockIdx.y, b = blockIdx.z;
    const int e2 = seg * 256 + threadIdx.x;
    float2 P = make_float2(0.f, 0.f);
    for (int c = 0; c < NC64; c++) {
        size_t base = ((size_t)b * NC64 + c) * NH + h;
        float sc = __expf(cs[base * TCH + TCH - 1]);
        size_t off = base * (size_t)(HD * DS / 2) + e2;
        ((__half2*)prev)[off] = __floats2half2_rn(P.x, P.y);
        float2 sv = __half22float2(((const __half2*)states)[off]);
        P.x = fmaf(P.x, sc, sv.x);
        P.y = fmaf(P.y, sc, sv.y);
    }
}

// ---------------- K1b: fused Y = Y_diag + Y_off + D*x, write y once ----------------
#define SM_K1B_BYTES ((3 * 64 * SB_S + 2 * 64 * ST_S) * 2 + (64 * ST_S + 2 * 64) * 4)

__global__ __launch_bounds__(256, 2) void ssm_y_kernel(
    const __half* __restrict__ xbc, const __half* __restrict__ prev,
    const float* __restrict__ cs, const float* __restrict__ dt,
    const float* __restrict__ Dvec, float* __restrict__ y) {
    extern __shared__ char smraw[];
    __half* sB = (__half*)smraw;                 // 64 x SB_S (s, n)
    __half* sC = sB + 64 * SB_S;                 // 64 x SB_S (t, n)
    __half* sP = sC + 64 * SB_S;                 // 64 x SB_S (p, n)
    __half* sGh = sP + 64 * SB_S;                // 64 x ST_S (t, s)
    __half* sX = sGh + 64 * ST_S;                // 64 x ST_S (p, s)
    float* sG = (float*)(sX + 64 * ST_S);        // 64 x ST_S
    float* s_cs = sG + 64 * ST_S;                // 64
    float* s_dt = s_cs + 64;                     // 64

    const int c = blockIdx.x, hg = blockIdx.y, b = blockIdx.z;
    const int h0 = hg * HPB;
    const int tid = threadIdx.x;
    const int wid = tid >> 5, lane = tid & 31;
    const int wm = wid >> 2, wn = wid & 3;
    const int grp = lane >> 2, q2 = (lane & 3) * 2;
    const int row0 = b * L_SEQ + c * TCH;
    const __half* xrow = xbc + (size_t)row0 * CONVD;

    for (int idx = tid; idx < 64 * 128; idx += 256) {
        int s = idx >> 7, n = idx & 127;
        sB[s * SB_S + n] = xrow[(size_t)s * CONVD + 2048 + n];
        sC[s * SB_S + n] = xrow[(size_t)s * CONVD + 2176 + n];
    }
    __syncthreads();

    // G = C * B^T (head-independent)
    {
        float g[2][2][4];
#pragma unroll
        for (int i = 0; i < 2; i++)
#pragma unroll
            for (int j = 0; j < 2; j++)
#pragma unroll
                for (int r = 0; r < 4; r++) g[i][j][r] = 0.f;
        for (int kb = 0; kb < 128; kb += 16) {
            uint32_t bb[2][2];
#pragma unroll
            for (int nt = 0; nt < 2; nt++) {
                int c0 = wn * 16 + nt * 8 + grp;
                bb[nt][0] = *(const uint32_t*)&sB[c0 * SB_S + kb + q2];
                bb[nt][1] = *(const uint32_t*)&sB[c0 * SB_S + kb + q2 + 8];
            }
#pragma unroll
            for (int mt = 0; mt < 2; mt++) {
                int r0 = wm * 32 + mt * 16 + grp;
                uint32_t aa[4];
                aa[0] = *(const uint32_t*)&sC[r0 * SB_S + kb + q2];
                aa[1] = *(const uint32_t*)&sC[(r0 + 8) * SB_S + kb + q2];
                aa[2] = *(const uint32_t*)&sC[r0 * SB_S + kb + q2 + 8];
                aa[3] = *(const uint32_t*)&sC[(r0 + 8) * SB_S + kb + q2 + 8];
#pragma unroll
                for (int nt = 0; nt < 2; nt++) mma16816h(g[mt][nt], aa, bb[nt]);
            }
        }
#pragma unroll
        for (int mt = 0; mt < 2; mt++)
#pragma unroll
            for (int nt = 0; nt < 2; nt++) {
                int t = wm * 32 + mt * 16 + grp;
                int s = wn * 16 + nt * 8 + q2;
                *(float2*)&sG[t * ST_S + s] = make_float2(g[mt][nt][0], g[mt][nt][1]);
                *(float2*)&sG[(t + 8) * ST_S + s] = make_float2(g[mt][nt][2], g[mt][nt][3]);
            }
    }

    for (int hl = 0; hl < HPB; hl++) {
        int h = h0 + hl;
        __syncthreads();   // sG ready (first iter) / prev head reads done
        size_t cbase = (((size_t)b * NC64 + c) * NH + h) * TCH;
        if (tid < 64) {
            s_cs[tid] = cs[cbase + tid];
            s_dt[tid] = dt[cbase + tid];
        }
        size_t pbase = (((size_t)b * NC64 + c) * NH + h) * (size_t)(HD * DS);
        for (int idx = tid; idx < 64 * 128; idx += 256) {
            int p = idx >> 7, n = idx & 127;
            sP[p * SB_S + n] = prev[pbase + (size_t)p * DS + n];
        }
        __syncthreads();
        for (int idx = tid; idx < 64 * 64; idx += 256) {
            int t = idx >> 6, s = idx & 63;
            float val = 0.f;
            if (t >= s) val = sG[t * ST_S + s] * __expf(s_cs[t] - s_cs[s]);
            sGh[t * ST_S + s] = __float2half(val);
            // reuse same loop to fill sX with transposed indexing
            int ss = idx >> 6, p = idx & 63;
            float xv = __half2float(xrow[(size_t)ss * CONVD + h * 64 + p]);
            sX[p * ST_S + ss] = __float2half(xv * s_dt[ss]);
        }
        __syncthreads();

        // Y_diag (k=64 over s) and Y_off (k=128 over n)
        float yd[2][2][4], yo[2][2][4];
#pragma unroll
        for (int i = 0; i < 2; i++)
#pragma unroll
            for (int j = 0; j < 2; j++)
#pragma unroll
                for (int r = 0; r < 4; r++) { yd[i][j][r] = 0.f; yo[i][j][r] = 0.f; }
        for (int kb = 0; kb < 64; kb += 16) {
            uint32_t bb[2][2];
#pragma unroll
            for (int nt = 0; nt < 2; nt++) {
                int c0 = wn * 16 + nt * 8 + grp;
                bb[nt][0] = *(const uint32_t*)&sX[c0 * ST_S + kb + q2];
                bb[nt][1] = *(const uint32_t*)&sX[c0 * ST_S + kb + q2 + 8];
            }
#pragma unroll
            for (int mt = 0; mt < 2; mt++) {
                int r0 = wm * 32 + mt * 16 + grp;
                uint32_t aa[4];
                aa[0] = *(const uint32_t*)&sGh[r0 * ST_S + kb + q2];
                aa[1] = *(const uint32_t*)&sGh[(r0 + 8) * ST_S + kb + q2];
                aa[2] = *(const uint32_t*)&sGh[r0 * ST_S + kb + q2 + 8];
                aa[3] = *(const uint32_t*)&sGh[(r0 + 8) * ST_S + kb + q2 + 8];
#pragma unroll
                for (int nt = 0; nt < 2; nt++) mma16816h(yd[mt][nt], aa, bb[nt]);
            }
        }
        for (int kb = 0; kb < 128; kb += 16) {
            uint32_t bb[2][2];
#pragma unroll
            for (int nt = 0; nt < 2; nt++) {
                int c0 = wn * 16 + nt * 8 + grp;
                bb[nt][0] = *(const uint32_t*)&sP[c0 * SB_S + kb + q2];
                bb[nt][1] = *(const uint32_t*)&sP[c0 * SB_S + kb + q2 + 8];
            }
#pragma unroll
            for (int mt = 0; mt < 2; mt++) {
                int r0 = wm * 32 + mt * 16 + grp;
                uint32_t aa[4];
                aa[0] = *(const uint32_t*)&sC[r0 * SB_S + kb + q2];
                aa[1] = *(const uint32_t*)&sC[(r0 + 8) * SB_S + kb + q2];
                aa[2] = *(const uint32_t*)&sC[r0 * SB_S + kb + q2 + 8];
                aa[3] = *(const uint32_t*)&sC[(r0 + 8) * SB_S + kb + q2 + 8];
#pragma unroll
                for (int nt = 0; nt < 2; nt++) mma16816h(yo[mt][nt], aa, bb[nt]);
            }
        }

        float Dh = Dvec[h];
#pragma unroll
        for (int mt = 0; mt < 2; mt++)
#pragma unroll
            for (int nt = 0; nt < 2; nt++) {
                int t0 = wm * 32 + mt * 16 + grp;
                int p0 = wn * 16 + nt * 8 + q2;
#pragma unroll
                for (int rr = 0; rr < 2; rr++) {
                    int t = t0 + rr * 8;
                    float e = __expf(s_cs[t]);
                    __half2 xv2 = *(const __half2*)&xrow[(size_t)t * CONVD + h * 64 + p0];
                    float2 xv = __half22float2(xv2);
                    float2 o;
                    o.x = fmaf(e, yo[mt][nt][rr * 2 + 0], fmaf(Dh, xv.x, yd[mt][nt][rr * 2 + 0]));
                    o.y = fmaf(e, yo[mt][nt][rr * 2 + 1], fmaf(Dh, xv.y, yd[mt][nt][rr * 2 + 1]));
                    *(float2*)&y[(size_t)(row0 + t) * DSSM + h * 64 + p0] = o;
                }
            }
    }
}

// ---------------- gate (y * silu(z)) + RMSNorm -> fp16 ----------------
__global__ void gate_norm_kernel(const __half* __restrict__ zxh,
                                 const float* __restrict__ y,
                                 const float* __restrict__ norm_w,
                                 __half* __restrict__ ynh) {
    const int row = blockIdx.x;
    const int tid = threadIdx.x;
    const float* yrow = y + (size_t)row * DSSM;
    const __half* zrow = zxh + (size_t)row * DIP;
    float v[8];
    float ss = 0.f;
#pragma unroll
    for (int k = 0; k < 8; k++) {
        int e = tid + k * 256;
        float z = __half2float(zrow[e]);
        float vv = yrow[e] * (z * fast_sigmoid(z));
        v[k] = vv;
        ss = fmaf(vv, vv, ss);
    }
    __shared__ float red[256];
    red[tid] = ss;
    __syncthreads();
    for (int s = 128; s > 0; s >>= 1) {
        if (tid < s) red[tid] += red[tid + s];
        __syncthreads();
    }
    float r = rsqrtf(red[0] / (float)DSSM + 1e-5f);
#pragma unroll
    for (int k = 0; k < 8; k++) {
        int e = tid + k * 256;
        ynh[(size_t)row * DSSM + e] = __float2half(v[k] * r * norm_w[e]);
    }
}

// ---------------- host launch ----------------
extern "C" void kernel_launch(void* const* d_in, const int* in_sizes, int n_in,
                              void* d_out, int out_size) {
    const float* u       = (const float*)d_in[0];
    const float* W_in    = (const float*)d_in[1];
    const float* conv_w  = (const float*)d_in[2];
    const float* conv_b  = (const float*)d_in[3];
    const float* dt_bias = (const float*)d_in[4];
    const float* A_log   = (const float*)d_in[5];
    const float* Dv      = (const float*)d_in[6];
    const float* norm_w  = (const float*)d_in[7];
    const float* W_out   = (const float*)d_in[8];
    float* out = (float*)d_out;

    void *p_zxh, *p_xbc, *p_y, *p_states, *p_prev, *p_cs, *p_dt;
    void *p_uh, *p_wih, *p_ynh, *p_woh;
    cudaGetSymbolAddress(&p_zxh, g_zxh);
    cudaGetSymbolAddress(&p_xbc, g_xbc);
    cudaGetSymbolAddress(&p_y, g_y);
    cudaGetSymbolAddress(&p_states, g_states);
    cudaGetSymbolAddress(&p_prev, g_prev);
    cudaGetSymbolAddress(&p_cs, g_cs);
    cudaGetSymbolAddress(&p_dt, g_dt);
    cudaGetSymbolAddress(&p_uh, g_uh);
    cudaGetSymbolAddress(&p_wih, g_wih);
    cudaGetSymbolAddress(&p_ynh, g_ynh);
    cudaGetSymbolAddress(&p_woh, g_woh);
    __half* zxh = (__half*)p_zxh;
    __half* xbc = (__half*)p_xbc;
    float* y = (float*)p_y;
    __half* states = (__half*)p_states;
    __half* prev = (__half*)p_prev;
    float* cs = (float*)p_cs;
    float* dtb = (float*)p_dt;
    __half* uh = (__half*)p_uh;
    __half* wih = (__half*)p_wih;
    __half* ynh = (__half*)p_ynh;
    __half* woh = (__half*)p_woh;

    cudaFuncSetAttribute(gemm_nt_fp16<__half>, cudaFuncAttributeMaxDynamicSharedMemorySize,
                         GEMM_SMEM);
    cudaFuncSetAttribute(gemm_nt_fp16<float>, cudaFuncAttributeMaxDynamicSharedMemorySize,
                         GEMM_SMEM);
    cudaFuncSetAttribute(ssm_states_kernel, cudaFuncAttributeMaxDynamicSharedMemorySize,
                         SM_K1A_BYTES);
    cudaFuncSetAttribute(ssm_y_kernel, cudaFuncAttributeMaxDynamicSharedMemorySize,
                         SM_K1B_BYTES);

    // 0. fp16 conversions
    {
        int n4 = MROWS * D_MODEL / 4;
        conv_fp16_kernel<<<(n4 + 255) / 256, 256>>>(u, uh, n4);
        n4 = DIP * D_MODEL / 4;
        conv_fp16_kernel<<<(n4 + 255) / 256, 256>>>(W_in, wih, n4);
        n4 = D_MODEL * DSSM / 4;
        conv_fp16_kernel<<<(n4 + 255) / 256, 256>>>(W_out, woh, n4);
    }

    // 1. in_proj (fp16, fp16 output)
    gemm_nt_fp16<__half><<<dim3((DIP + 127) / 128, MROWS / 128), 256, GEMM_SMEM>>>(
        uh, wih, zxh, MROWS, DIP, D_MODEL);

    // 2. conv1d + silu -> fp16
    {
        size_t total4 = (size_t)(MROWS / 4) * CONVD;
        conv_silu_kernel<<<(unsigned)((total4 + 255) / 256), 256>>>(zxh, conv_w, conv_b, xbc);
    }

    // 3a. states + dt/cs
    ssm_states_kernel<<<dim3(NC64, NH / HPB, BATCH), 256, SM_K1A_BYTES>>>(
        zxh, xbc, dt_bias, A_log, states, cs, dtb);

    // 3b. inter-chunk recurrence
    chunk_scan64<<<dim3(16, NH, BATCH), 256>>>(states, cs, prev);

    // 3c. fused Y (Y_diag + Y_off + D*x), single write
    ssm_y_kernel<<<dim3(NC64, NH / HPB, BATCH), 256, SM_K1B_BYTES>>>(
        xbc, prev, cs, dtb, Dv, y);

    // 4. gate + RMSNorm -> fp16
    gate_norm_kernel<<<MROWS, 256>>>(zxh, y, norm_w, ynh);

    // 5. out_proj (fp16, fp32 output)
    gemm_nt_fp16<float><<<dim3(D_MODEL / 128, MROWS / 128), 256, GEMM_SMEM>>>(
        ynh, woh, out, MROWS, D_MODEL, DSSM);
}

// round 14
// speedup vs baseline: 4.9251x; 1.0296x over previous
#include <cuda_runtime.h>
#include <cuda_bf16.h>
#include <cuda_fp16.h>
#include <math.h>
#include <stdint.h>

#define BATCH 2
#define L_SEQ 4096
#define D_MODEL 1024
#define DIP 4384          // D_IN_PROJ
#define DSSM 2048
#define CONVD 2304        // CONV_DIM
#define NH 32
#define HD 64
#define DS 128
#define NC64 64           // chunks of 64 per batch
#define TCH 64
#define HPB 8             // heads per block
#define MROWS (BATCH * L_SEQ)   // 8192

// ---------------- scratch (device globals; no allocation) ----------------
__device__ __half g_zxh[(size_t)MROWS * DIP];
__device__ __half g_xbc[(size_t)MROWS * CONVD];
__device__ __half g_y[(size_t)MROWS * DSSM];
__device__ __half g_states[(size_t)BATCH * NC64 * NH * HD * DS];
__device__ __half g_prev[(size_t)BATCH * NC64 * NH * HD * DS];
__device__ float g_cs[(size_t)BATCH * NC64 * NH * TCH];
__device__ float g_dt[(size_t)BATCH * NC64 * NH * TCH];

__device__ __half g_uh[(size_t)MROWS * D_MODEL];
__device__ __half g_wih[(size_t)DIP * D_MODEL];
__device__ __half g_ynh[(size_t)MROWS * DSSM];
__device__ __half g_woh[(size_t)D_MODEL * DSSM];

// ---------------- helpers ----------------
struct alignas(8) half4 { __half a, b, c, d; };

// silu via single-MUFU tanh: x*sigmoid(x) = 0.5*x*(1+tanh(x/2))
__device__ __forceinline__ float fast_silu(float x) {
    float t;
    asm("tanh.approx.f32 %0, %1;" : "=f"(t) : "f"(x * 0.5f));
    return 0.5f * x * (1.f + t);
}

__device__ __forceinline__ void mma16816h(float* d, const uint32_t* a, const uint32_t* b) {
    asm volatile(
        "mma.sync.aligned.m16n8k16.row.col.f32.f16.f16.f32 "
        "{%0,%1,%2,%3}, {%4,%5,%6,%7}, {%8,%9}, {%0,%1,%2,%3};"
        : "+f"(d[0]), "+f"(d[1]), "+f"(d[2]), "+f"(d[3])
        : "r"(a[0]), "r"(a[1]), "r"(a[2]), "r"(a[3]), "r"(b[0]), "r"(b[1]));
}

__device__ __forceinline__ void ldsm_x4(uint32_t& r0, uint32_t& r1, uint32_t& r2,
                                        uint32_t& r3, uint32_t addr) {
    asm volatile("ldmatrix.sync.aligned.m8n8.x4.shared.b16 {%0,%1,%2,%3}, [%4];"
                 : "=r"(r0), "=r"(r1), "=r"(r2), "=r"(r3) : "r"(addr));
}

__device__ __forceinline__ void cpasync16(uint32_t dst, const void* src, int szvalid) {
    asm volatile("cp.async.cg.shared.global [%0], [%1], 16, %2;"
                 :: "r"(dst), "l"(src), "r"(szvalid) : "memory");
}
#define CPASYNC_COMMIT() asm volatile("cp.async.commit_group;" ::: "memory")
#define CPASYNC_WAIT(n)  asm volatile("cp.async.wait_group %0;" :: "n"(n) : "memory")

// ---------------- fp32 -> fp16 convert ----------------
__global__ void conv_fp16_kernel(const float* __restrict__ x,
                                 __half* __restrict__ o, int n4) {
    int i = blockIdx.x * 256 + threadIdx.x;
    if (i >= n4) return;
    float4 v = ((const float4*)x)[i];
    half4 hv = {__float2half(v.x), __float2half(v.y),
                __float2half(v.z), __float2half(v.w)};
    ((half4*)o)[i] = hv;
}

// ---------------- fp16 single-pass GEMM, templated output ----------------
#define GK 16
#define GPAD 24
#define NSTAGE 4
#define GEMM_SMEM (NSTAGE * 2 * 128 * GPAD * 2)   // 49152 bytes

template <typename OutT>
__global__ __launch_bounds__(256, 2) void gemm_nt_fp16(
    const __half* __restrict__ A, const __half* __restrict__ B,
    OutT* __restrict__ C, int M, int N, int K) {
    extern __shared__ __half smh[];
    __half* sA = smh;
    __half* sB = smh + NSTAGE * 128 * GPAD;

    const int tid = threadIdx.x;
    const int wid = tid >> 5, lane = tid & 31;
    const int wm = wid >> 2, wn = wid & 3;
    const int grp = lane >> 2, q2 = (lane & 3) * 2;
    const int rowBase = blockIdx.y * 128;
    const int colBase = blockIdx.x * 128;
    const int lrow = tid >> 1;
    const int lkh = (tid & 1) * 8;

    const int lmRow = lane & 15;
    const int lmK = (lane >> 4) << 3;

    const uint32_t sA_s = (uint32_t)__cvta_generic_to_shared(sA);
    const uint32_t sB_s = (uint32_t)__cvta_generic_to_shared(sB);

    float acc[4][4][4];
#pragma unroll
    for (int i = 0; i < 4; i++)
#pragma unroll
        for (int j = 0; j < 4; j++)
#pragma unroll
            for (int r = 0; r < 4; r++) acc[i][j][r] = 0.f;

    const int nk = K / GK;
#define SIDX(st, r, k) ((((st) * 128 + (r)) * GPAD) + (k))

    const __half* pA = A + (size_t)(rowBase + lrow) * K + lkh;
    int cn = colBase + lrow;
    int bok = (cn < N) ? 16 : 0;
    int cnc = (cn < N) ? cn : 0;
    const __half* pB = B + (size_t)cnc * K + lkh;

    auto load_stage = [&](int st, int kc) {
        int ko = kc * GK;
        cpasync16(sA_s + SIDX(st, lrow, lkh) * 2, pA + ko, 16);
        cpasync16(sB_s + SIDX(st, lrow, lkh) * 2, pB + ko, bok);
        CPASYNC_COMMIT();
    };

    load_stage(0, 0);
    if (nk > 1) load_stage(1, 1);

    for (int k = 0; k < nk; k++) {
        int st = k & (NSTAGE - 1);
        if (k + 2 < nk) {
            load_stage((k + 2) & (NSTAGE - 1), k + 2);
            CPASYNC_WAIT(2);
        } else if (k + 1 < nk) {
            CPASYNC_WAIT(1);
        } else {
            CPASYNC_WAIT(0);
        }
        __syncthreads();

        uint32_t bb[4][2];
        {
            uint32_t r0, r1, r2, r3;
            ldsm_x4(r0, r1, r2, r3, sB_s + SIDX(st, wn * 32 + lmRow, lmK) * 2);
            bb[0][0] = r0; bb[0][1] = r2; bb[1][0] = r1; bb[1][1] = r3;
            ldsm_x4(r0, r1, r2, r3, sB_s + SIDX(st, wn * 32 + 16 + lmRow, lmK) * 2);
            bb[2][0] = r0; bb[2][1] = r2; bb[3][0] = r1; bb[3][1] = r3;
        }
#pragma unroll
        for (int mt = 0; mt < 4; mt++) {
            int r0row = wm * 64 + mt * 16;
            uint32_t aa[4];
            ldsm_x4(aa[0], aa[1], aa[2], aa[3], sA_s + SIDX(st, r0row + lmRow, lmK) * 2);
#pragma unroll
            for (int nt = 0; nt < 4; nt++) mma16816h(acc[mt][nt], aa, bb[nt]);
        }
    }
#pragma unroll
    for (int mt = 0; mt < 4; mt++) {
#pragma unroll
        for (int nt = 0; nt < 4; nt++) {
            int colTile = colBase + wn * 32 + nt * 8;
            if (colTile >= N) continue;
            int r0 = rowBase + wm * 64 + mt * 16 + grp;
            int c0 = colTile + q2;
            if constexpr (sizeof(OutT) == 2) {
                *(__half2*)&C[(size_t)r0 * N + c0] =
                    __floats2half2_rn(acc[mt][nt][0], acc[mt][nt][1]);
                *(__half2*)&C[(size_t)(r0 + 8) * N + c0] =
                    __floats2half2_rn(acc[mt][nt][2], acc[mt][nt][3]);
            } else {
                *(float2*)&C[(size_t)r0 * N + c0] = make_float2(acc[mt][nt][0], acc[mt][nt][1]);
                *(float2*)&C[(size_t)(r0 + 8) * N + c0] = make_float2(acc[mt][nt][2], acc[mt][nt][3]);
            }
        }
    }
#undef SIDX
}

// ---------------- conv1d + SiLU : 4 t per thread, fp16 in/out, tanh silu ----------------
__global__ void conv_silu_kernel(const __half* __restrict__ zxh,
                                 const float* __restrict__ conv_w,
                                 const float* __restrict__ conv_b,
                                 __half* __restrict__ xbc) {
    size_t idx = (size_t)blockIdx.x * 256 + threadIdx.x;
    const size_t total = (size_t)(MROWS / 4) * CONVD;
    if (idx >= total) return;
    int cc = (int)(idx % CONVD);
    size_t r4 = idx / CONVD;
    size_t bt0 = r4 * 4;
    int t0 = (int)(bt0 % L_SEQ);

    float w0 = conv_w[cc * 4 + 0], w1 = conv_w[cc * 4 + 1];
    float w2 = conv_w[cc * 4 + 2], w3 = conv_w[cc * 4 + 3];
    float bia = conv_b[cc];

    float v[7];
#pragma unroll
    for (int j = 0; j < 7; j++) {
        int tt = t0 - 3 + j;
        v[j] = (tt >= 0) ? __half2float(zxh[(bt0 - 3 + j) * DIP + 2048 + cc]) : 0.f;
    }
#pragma unroll
    for (int i = 0; i < 4; i++) {
        float acc = bia;
        acc = fmaf(v[i + 0], w0, acc);
        acc = fmaf(v[i + 1], w1, acc);
        acc = fmaf(v[i + 2], w2, acc);
        acc = fmaf(v[i + 3], w3, acc);
        xbc[(bt0 + i) * CONVD + cc] = __float2half(fast_silu(acc));
    }
}

// ---------------- K1a: dt/cs + per-chunk states only ----------------
#define SB_S 136
#define ST_S 66
#define SM_K1A_BYTES ((128 * ST_S + 64 * ST_S) * 2 + (2 * HPB * 64 + 64) * 4)

__global__ __launch_bounds__(256, 2) void ssm_states_kernel(
    const __half* __restrict__ zxh, const __half* __restrict__ xbc,
    const float* __restrict__ dt_bias, const float* __restrict__ A_log,
    __half* __restrict__ states, float* __restrict__ cs_out, float* __restrict__ dt_out) {
    extern __shared__ char smraw[];
    __half* sBT = (__half*)smraw;
    __half* sXd = sBT + 128 * ST_S;
    float* s_dt = (float*)(sXd + 64 * ST_S);
    float* s_cs = s_dt + HPB * 64;
    float* sEd = s_cs + HPB * 64;

    const int c = blockIdx.x, hg = blockIdx.y, b = blockIdx.z;
    const int h0 = hg * HPB;
    const int tid = threadIdx.x;
    const int wid = tid >> 5, lane = tid & 31;
    const int wm = wid >> 2, wn = wid & 3;
    const int grp = lane >> 2, q2 = (lane & 3) * 2;
    const int row0 = b * L_SEQ + c * TCH;
    const __half* xrow = xbc + (size_t)row0 * CONVD;

    {
        int h = h0 + wid;
        float Ah = -__expf(A_log[h]);
        float bias = dt_bias[h];
        float d0 = __half2float(zxh[(size_t)(row0 + lane) * DIP + 4352 + h]) + bias;
        float d1 = __half2float(zxh[(size_t)(row0 + 32 + lane) * DIP + 4352 + h]) + bias;
        float dt0 = (d0 > 20.f) ? d0 : log1pf(__expf(d0));
        float dt1 = (d1 > 20.f) ? d1 : log1pf(__expf(d1));
        s_dt[wid * 64 + lane] = dt0;
        s_dt[wid * 64 + 32 + lane] = dt1;
        float v0 = dt0 * Ah, v1 = dt1 * Ah;
#pragma unroll
        for (int off = 1; off < 32; off <<= 1) {
            float n0 = __shfl_up_sync(0xffffffffu, v0, off);
            float n1 = __shfl_up_sync(0xffffffffu, v1, off);
            if (lane >= off) { v0 += n0; v1 += n1; }
        }
        v1 += __shfl_sync(0xffffffffu, v0, 31);
        s_cs[wid * 64 + lane] = v0;
        s_cs[wid * 64 + 32 + lane] = v1;
        size_t cbase = (((size_t)b * NC64 + c) * NH + h) * TCH;
        cs_out[cbase + lane] = v0;
        cs_out[cbase + 32 + lane] = v1;
        dt_out[cbase + lane] = dt0;
        dt_out[cbase + 32 + lane] = dt1;
    }

    for (int idx = tid; idx < 64 * 128; idx += 256) {
        int s = idx >> 7, n = idx & 127;
        sBT[n * ST_S + s] = xrow[(size_t)s * CONVD + 2048 + n];
    }
    __syncthreads();

    for (int hl = 0; hl < HPB; hl++) {
        int h = h0 + hl;
        const float* csh = s_cs + hl * 64;
        const float* dth = s_dt + hl * 64;
        const float csL = csh[63];
        if (tid < 64) sEd[tid] = __expf(csL - csh[tid]);
        __syncthreads();
        for (int idx = tid; idx < 64 * 64; idx += 256) {
            int s = idx >> 6, p = idx & 63;
            float xv = __half2float(xrow[(size_t)s * CONVD + h * 64 + p]);
            sXd[p * ST_S + s] = __float2half(xv * dth[s] * sEd[s]);
        }
        __syncthreads();

        float st[2][4][4];
#pragma unroll
        for (int i = 0; i < 2; i++)
#pragma unroll
            for (int j = 0; j < 4; j++)
#pragma unroll
                for (int r = 0; r < 4; r++) st[i][j][r] = 0.f;
        for (int kb = 0; kb < 64; kb += 16) {
            uint32_t bb[4][2];
#pragma unroll
            for (int nt = 0; nt < 4; nt++) {
                int c0 = wn * 32 + nt * 8 + grp;
                bb[nt][0] = *(const uint32_t*)&sBT[c0 * ST_S + kb + q2];
                bb[nt][1] = *(const uint32_t*)&sBT[c0 * ST_S + kb + q2 + 8];
            }
#pragma unroll
            for (int mt = 0; mt < 2; mt++) {
                int r0 = wm * 32 + mt * 16 + grp;
                uint32_t aa[4];
                aa[0] = *(const uint32_t*)&sXd[r0 * ST_S + kb + q2];
                aa[1] = *(const uint32_t*)&sXd[(r0 + 8) * ST_S + kb + q2];
                aa[2] = *(const uint32_t*)&sXd[r0 * ST_S + kb + q2 + 8];
                aa[3] = *(const uint32_t*)&sXd[(r0 + 8) * ST_S + kb + q2 + 8];
#pragma unroll
                for (int nt = 0; nt < 4; nt++) mma16816h(st[mt][nt], aa, bb[nt]);
            }
        }
        size_t sbase = (((size_t)b * NC64 + c) * NH + h) * (size_t)(HD * DS);
#pragma unroll
        for (int mt = 0; mt < 2; mt++)
#pragma unroll
            for (int nt = 0; nt < 4; nt++) {
                int p0 = wm * 32 + mt * 16 + grp;
                int n0 = wn * 32 + nt * 8 + q2;
                *(__half2*)&states[sbase + (size_t)p0 * DS + n0] =
                    __floats2half2_rn(st[mt][nt][0], st[mt][nt][1]);
                *(__half2*)&states[sbase + (size_t)(p0 + 8) * DS + n0] =
                    __floats2half2_rn(st[mt][nt][2], st[mt][nt][3]);
            }
        __syncthreads();
    }
}

// ---------------- K2: inter-chunk recurrence (half2 vectorized) ----------------
__global__ void chunk_scan64(const __half* __restrict__ states,
                             const float* __restrict__ cs,
                             __half* __restrict__ prev) {
    const int seg = blockIdx.x, h = blockIdx.y, b = blockIdx.z;
    const int e2 = seg * 256 + threadIdx.x;
    float2 P = make_float2(0.f, 0.f);
    for (int c = 0; c < NC64; c++) {
        size_t base = ((size_t)b * NC64 + c) * NH + h;
        float sc = __expf(cs[base * TCH + TCH - 1]);
        size_t off = base * (size_t)(HD * DS / 2) + e2;
        ((__half2*)prev)[off] = __floats2half2_rn(P.x, P.y);
        float2 sv = __half22float2(((const __half2*)states)[off]);
        P.x = fmaf(P.x, sc, sv.x);
        P.y = fmaf(P.y, sc, sv.y);
    }
}

// ---------------- K1b: fused Y = Y_diag + Y_off + D*x, fp16 y write ----------------
#define SM_K1B_BYTES ((3 * 64 * SB_S + 2 * 64 * ST_S) * 2 + (64 * ST_S + 2 * 64) * 4)

__global__ __launch_bounds__(256, 2) void ssm_y_kernel(
    const __half* __restrict__ xbc, const __half* __restrict__ prev,
    const float* __restrict__ cs, const float* __restrict__ dt,
    const float* __restrict__ Dvec, __half* __restrict__ y) {
    extern __shared__ char smraw[];
    __half* sB = (__half*)smraw;
    __half* sC = sB + 64 * SB_S;
    __half* sP = sC + 64 * SB_S;
    __half* sGh = sP + 64 * SB_S;
    __half* sX = sGh + 64 * ST_S;
    float* sG = (float*)(sX + 64 * ST_S);
    float* s_cs = sG + 64 * ST_S;
    float* s_dt = s_cs + 64;

    const int c = blockIdx.x, hg = blockIdx.y, b = blockIdx.z;
    const int h0 = hg * HPB;
    const int tid = threadIdx.x;
    const int wid = tid >> 5, lane = tid & 31;
    const int wm = wid >> 2, wn = wid & 3;
    const int grp = lane >> 2, q2 = (lane & 3) * 2;
    const int row0 = b * L_SEQ + c * TCH;
    const __half* xrow = xbc + (size_t)row0 * CONVD;

    for (int idx = tid; idx < 64 * 128; idx += 256) {
        int s = idx >> 7, n = idx & 127;
        sB[s * SB_S + n] = xrow[(size_t)s * CONVD + 2048 + n];
        sC[s * SB_S + n] = xrow[(size_t)s * CONVD + 2176 + n];
    }
    __syncthreads();

    // G = C * B^T (head-independent)
    {
        float g[2][2][4];
#pragma unroll
        for (int i = 0; i < 2; i++)
#pragma unroll
            for (int j = 0; j < 2; j++)
#pragma unroll
                for (int r = 0; r < 4; r++) g[i][j][r] = 0.f;
        for (int kb = 0; kb < 128; kb += 16) {
            uint32_t bb[2][2];
#pragma unroll
            for (int nt = 0; nt < 2; nt++) {
                int c0 = wn * 16 + nt * 8 + grp;
                bb[nt][0] = *(const uint32_t*)&sB[c0 * SB_S + kb + q2];
                bb[nt][1] = *(const uint32_t*)&sB[c0 * SB_S + kb + q2 + 8];
            }
#pragma unroll
            for (int mt = 0; mt < 2; mt++) {
                int r0 = wm * 32 + mt * 16 + grp;
                uint32_t aa[4];
                aa[0] = *(const uint32_t*)&sC[r0 * SB_S + kb + q2];
                aa[1] = *(const uint32_t*)&sC[(r0 + 8) * SB_S + kb + q2];
                aa[2] = *(const uint32_t*)&sC[r0 * SB_S + kb + q2 + 8];
                aa[3] = *(const uint32_t*)&sC[(r0 + 8) * SB_S + kb + q2 + 8];
#pragma unroll
                for (int nt = 0; nt < 2; nt++) mma16816h(g[mt][nt], aa, bb[nt]);
            }
        }
#pragma unroll
        for (int mt = 0; mt < 2; mt++)
#pragma unroll
            for (int nt = 0; nt < 2; nt++) {
                int t = wm * 32 + mt * 16 + grp;
                int s = wn * 16 + nt * 8 + q2;
                *(float2*)&sG[t * ST_S + s] = make_float2(g[mt][nt][0], g[mt][nt][1]);
                *(float2*)&sG[(t + 8) * ST_S + s] = make_float2(g[mt][nt][2], g[mt][nt][3]);
            }
    }

    // zero the upper triangle of sGh once (it is never overwritten)
    __syncthreads();
    for (int idx = tid; idx < 64 * 64; idx += 256) {
        int t = idx >> 6, s = idx & 63;
        if (t < s) sGh[t * ST_S + s] = __ushort_as_half(0);
    }

    for (int hl = 0; hl < HPB; hl++) {
        int h = h0 + hl;
        __syncthreads();
        size_t cbase = (((size_t)b * NC64 + c) * NH + h) * TCH;
        if (tid < 64) {
            s_cs[tid] = cs[cbase + tid];
            s_dt[tid] = dt[cbase + tid];
        }
        size_t pbase = (((size_t)b * NC64 + c) * NH + h) * (size_t)(HD * DS);
        for (int idx = tid; idx < 64 * 128; idx += 256) {
            int p = idx >> 7, n = idx & 127;
            sP[p * SB_S + n] = prev[pbase + (size_t)p * DS + n];
        }
        __syncthreads();
        // decay fill: lower triangle only (real branch; upper stays zero)
        for (int idx = tid; idx < 64 * 64; idx += 256) {
            int t = idx >> 6, s = idx & 63;
            if (t >= s) {
                sGh[t * ST_S + s] =
                    __float2half(sG[t * ST_S + s] * __expf(s_cs[t] - s_cs[s]));
            }
            int p = idx & 63, ss = idx >> 6;
            float xv = __half2float(xrow[(size_t)ss * CONVD + h * 64 + p]);
            sX[p * ST_S + ss] = __float2half(xv * s_dt[ss]);
        }
        __syncthreads();

        float yd[2][2][4], yo[2][2][4];
#pragma unroll
        for (int i = 0; i < 2; i++)
#pragma unroll
            for (int j = 0; j < 2; j++)
#pragma unroll
                for (int r = 0; r < 4; r++) { yd[i][j][r] = 0.f; yo[i][j][r] = 0.f; }
        for (int kb = 0; kb < 64; kb += 16) {
            uint32_t bb[2][2];
#pragma unroll
            for (int nt = 0; nt < 2; nt++) {
                int c0 = wn * 16 + nt * 8 + grp;
                bb[nt][0] = *(const uint32_t*)&sX[c0 * ST_S + kb + q2];
                bb[nt][1] = *(const uint32_t*)&sX[c0 * ST_S + kb + q2 + 8];
            }
#pragma unroll
            for (int mt = 0; mt < 2; mt++) {
                int r0 = wm * 32 + mt * 16 + grp;
                uint32_t aa[4];
                aa[0] = *(const uint32_t*)&sGh[r0 * ST_S + kb + q2];
                aa[1] = *(const uint32_t*)&sGh[(r0 + 8) * ST_S + kb + q2];
                aa[2] = *(const uint32_t*)&sGh[r0 * ST_S + kb + q2 + 8];
                aa[3] = *(const uint32_t*)&sGh[(r0 + 8) * ST_S + kb + q2 + 8];
#pragma unroll
                for (int nt = 0; nt < 2; nt++) mma16816h(yd[mt][nt], aa, bb[nt]);
            }
        }
        for (int kb = 0; kb < 128; kb += 16) {
            uint32_t bb[2][2];
#pragma unroll
            for (int nt = 0; nt < 2; nt++) {
                int c0 = wn * 16 + nt * 8 + grp;
                bb[nt][0] = *(const uint32_t*)&sP[c0 * SB_S + kb + q2];
                bb[nt][1] = *(const uint32_t*)&sP[c0 * SB_S + kb + q2 + 8];
            }
#pragma unroll
            for (int mt = 0; mt < 2; mt++) {
                int r0 = wm * 32 + mt * 16 + grp;
                uint32_t aa[4];
                aa[0] = *(const uint32_t*)&sC[r0 * SB_S + kb + q2];
                aa[1] = *(const uint32_t*)&sC[(r0 + 8) * SB_S + kb + q2];
                aa[2] = *(const uint32_t*)&sC[r0 * SB_S + kb + q2 + 8];
                aa[3] = *(const uint32_t*)&sC[(r0 + 8) * SB_S + kb + q2 + 8];
#pragma unroll
                for (int nt = 0; nt < 2; nt++) mma16816h(yo[mt][nt], aa, bb[nt]);
            }
        }

        float Dh = Dvec[h];
#pragma unroll
        for (int mt = 0; mt < 2; mt++)
#pragma unroll
            for (int nt = 0; nt < 2; nt++) {
                int t0 = wm * 32 + mt * 16 + grp;
                int p0 = wn * 16 + nt * 8 + q2;
#pragma unroll
                for (int rr = 0; rr < 2; rr++) {
                    int t = t0 + rr * 8;
                    float e = __expf(s_cs[t]);
                    __half2 xv2 = *(const __half2*)&xrow[(size_t)t * CONVD + h * 64 + p0];
                    float2 xv = __half22float2(xv2);
                    float ox = fmaf(e, yo[mt][nt][rr * 2 + 0], fmaf(Dh, xv.x, yd[mt][nt][rr * 2 + 0]));
                    float oy = fmaf(e, yo[mt][nt][rr * 2 + 1], fmaf(Dh, xv.y, yd[mt][nt][rr * 2 + 1]));
                    *(__half2*)&y[(size_t)(row0 + t) * DSSM + h * 64 + p0] =
                        __floats2half2_rn(ox, oy);
                }
            }
    }
}

// ---------------- gate (y * silu(z)) + RMSNorm -> fp16, tanh silu ----------------
__global__ void gate_norm_kernel(const __half* __restrict__ zxh,
                                 const __half* __restrict__ y,
                                 const float* __restrict__ norm_w,
                                 __half* __restrict__ ynh) {
    const int row = blockIdx.x;
    const int tid = threadIdx.x;
    const __half* yrow = y + (size_t)row * DSSM;
    const __half* zrow = zxh + (size_t)row * DIP;
    float v[8];
    float ss = 0.f;
#pragma unroll
    for (int k = 0; k < 8; k++) {
        int e = tid + k * 256;
        float z = __half2float(zrow[e]);
        float vv = __half2float(yrow[e]) * fast_silu(z);
        v[k] = vv;
        ss = fmaf(vv, vv, ss);
    }
    __shared__ float red[256];
    red[tid] = ss;
    __syncthreads();
    for (int s = 128; s > 0; s >>= 1) {
        if (tid < s) red[tid] += red[tid + s];
        __syncthreads();
    }
    float r = rsqrtf(red[0] / (float)DSSM + 1e-5f);
#pragma unroll
    for (int k = 0; k < 8; k++) {
        int e = tid + k * 256;
        ynh[(size_t)row * DSSM + e] = __float2half(v[k] * r * norm_w[e]);
    }
}

// ---------------- host launch ----------------
extern "C" void kernel_launch(void* const* d_in, const int* in_sizes, int n_in,
                              void* d_out, int out_size) {
    const float* u       = (const float*)d_in[0];
    const float* W_in    = (const float*)d_in[1];
    const float* conv_w  = (const float*)d_in[2];
    const float* conv_b  = (const float*)d_in[3];
    const float* dt_bias = (const float*)d_in[4];
    const float* A_log   = (const float*)d_in[5];
    const float* Dv      = (const float*)d_in[6];
    const float* norm_w  = (const float*)d_in[7];
    const float* W_out   = (const float*)d_in[8];
    float* out = (float*)d_out;

    void *p_zxh, *p_xbc, *p_y, *p_states, *p_prev, *p_cs, *p_dt;
    void *p_uh, *p_wih, *p_ynh, *p_woh;
    cudaGetSymbolAddress(&p_zxh, g_zxh);
    cudaGetSymbolAddress(&p_xbc, g_xbc);
    cudaGetSymbolAddress(&p_y, g_y);
    cudaGetSymbolAddress(&p_states, g_states);
    cudaGetSymbolAddress(&p_prev, g_prev);
    cudaGetSymbolAddress(&p_cs, g_cs);
    cudaGetSymbolAddress(&p_dt, g_dt);
    cudaGetSymbolAddress(&p_uh, g_uh);
    cudaGetSymbolAddress(&p_wih, g_wih);
    cudaGetSymbolAddress(&p_ynh, g_ynh);
    cudaGetSymbolAddress(&p_woh, g_woh);
    __half* zxh = (__half*)p_zxh;
    __half* xbc = (__half*)p_xbc;
    __half* y = (__half*)p_y;
    __half* states = (__half*)p_states;
    __half* prev = (__half*)p_prev;
    float* cs = (float*)p_cs;
    float* dtb = (float*)p_dt;
    __half* uh = (__half*)p_uh;
    __half* wih = (__half*)p_wih;
    __half* ynh = (__half*)p_ynh;
    __half* woh = (__half*)p_woh;

    cudaFuncSetAttribute(gemm_nt_fp16<__half>, cudaFuncAttributeMaxDynamicSharedMemorySize,
                         GEMM_SMEM);
    cudaFuncSetAttribute(gemm_nt_fp16<float>, cudaFuncAttributeMaxDynamicSharedMemorySize,
                         GEMM_SMEM);
    cudaFuncSetAttribute(ssm_states_kernel, cudaFuncAttributeMaxDynamicSharedMemorySize,
                         SM_K1A_BYTES);
    cudaFuncSetAttribute(ssm_y_kernel, cudaFuncAttributeMaxDynamicSharedMemorySize,
                         SM_K1B_BYTES);

    // 0. fp16 conversions
    {
        int n4 = MROWS * D_MODEL / 4;
        conv_fp16_kernel<<<(n4 + 255) / 256, 256>>>(u, uh, n4);
        n4 = DIP * D_MODEL / 4;
        conv_fp16_kernel<<<(n4 + 255) / 256, 256>>>(W_in, wih, n4);
        n4 = D_MODEL * DSSM / 4;
        conv_fp16_kernel<<<(n4 + 255) / 256, 256>>>(W_out, woh, n4);
    }

    // 1. in_proj (fp16, fp16 output)
    gemm_nt_fp16<__half><<<dim3((DIP + 127) / 128, MROWS / 128), 256, GEMM_SMEM>>>(
        uh, wih, zxh, MROWS, DIP, D_MODEL);

    // 2. conv1d + silu -> fp16
    {
        size_t total4 = (size_t)(MROWS / 4) * CONVD;
        conv_silu_kernel<<<(unsigned)((total4 + 255) / 256), 256>>>(zxh, conv_w, conv_b, xbc);
    }

    // 3a. states + dt/cs
    ssm_states_kernel<<<dim3(NC64, NH / HPB, BATCH), 256, SM_K1A_BYTES>>>(
        zxh, xbc, dt_bias, A_log, states, cs, dtb);

    // 3b. inter-chunk recurrence
    chunk_scan64<<<dim3(16, NH, BATCH), 256>>>(states, cs, prev);

    // 3c. fused Y (Y_diag + Y_off + D*x), fp16 write
    ssm_y_kernel<<<dim3(NC64, NH / HPB, BATCH), 256, SM_K1B_BYTES>>>(
        xbc, prev, cs, dtb, Dv, y);

    // 4. gate + RMSNorm -> fp16
    gate_norm_kernel<<<MROWS, 256>>>(zxh, y, norm_w, ynh);

    // 5. out_proj (fp16, fp32 output)
    gemm_nt_fp16<float><<<dim3(D_MODEL / 128, MROWS / 128), 256, GEMM_SMEM>>>(
        ynh, woh, out, MROWS, D_MODEL, DSSM);
}